// round 2
// baseline (speedup 1.0000x reference)
#include <cuda_runtime.h>
#include <cuda_bf16.h>
#include <math.h>

// Problem constants
#define BATCH 4
#define LSEQ  8192
#define CC    256
#define BL    32768            // BATCH*LSEQ
#define HID   2048
#define NSPLIT 16              // n-splits for context GEMM

// ---------------- scratch (device globals; no allocations allowed) -----------
__device__ float g_q   [BL * CC];
__device__ float g_k   [BL * CC];
__device__ float g_v   [BL * CC];
__device__ float g_attn[BL * CC];
__device__ float g_lin [BL * CC];
__device__ float g_ln1 [BL * CC];
__device__ float g_f2  [BL * CC];
__device__ float g_hid [(long long)BL * HID];          // 256 MB
__device__ float g_ctx [BATCH * CC * CC];
__device__ float g_cpart[NSPLIT * BATCH * CC * CC];    // split-N partials
__device__ float g_cm  [BATCH * CC];
__device__ float g_cs  [BATCH * CC];

// ---------------- generic 128x128x8 fp32 SGEMM -------------------------------
// EPI: 0 = none, 1 = +bias, 2 = +bias then exact GELU
// DUAL: A is virtual concat [A (cols 0..255) | A2 (cols 256..511)], lda=256
template<int EPI, bool DUAL>
__global__ __launch_bounds__(256, 2)
void sgemm_k(const float* __restrict__ A, const float* __restrict__ A2, int lda,
             const float* __restrict__ B, const float* __restrict__ bias,
             float* __restrict__ C,
             int M, int N, int K,
             long long sA, long long sB, long long sC)
{
    A += blockIdx.z * sA;
    B += blockIdx.z * sB;
    C += blockIdx.z * sC;

    const int m0 = blockIdx.y * 128;
    const int n0 = blockIdx.x * 128;

    __shared__ float As[8][128];
    __shared__ float Bs[8][128];

    const int t  = threadIdx.x;
    const int tx = t & 15;        // 16 col-groups
    const int ty = t >> 4;        // 16 row-groups

    // global-load mapping
    const int am = t >> 1;              // 0..127
    const int ak = (t & 1) << 2;        // 0 or 4
    const int bk = t >> 5;              // 0..7
    const int bn = (t & 31) << 2;       // 0..124

    float acc[8][8];
#pragma unroll
    for (int i = 0; i < 8; i++)
#pragma unroll
        for (int j = 0; j < 8; j++) acc[i][j] = 0.f;

    for (int k0 = 0; k0 < K; k0 += 8) {
        const float* Aeff;
        int kk0;
        if (DUAL) {
            if (k0 < 256) { Aeff = A;  kk0 = k0; }
            else          { Aeff = A2; kk0 = k0 - 256; }
        } else { Aeff = A; kk0 = k0; }

        float4 av = *(const float4*)&Aeff[(long long)(m0 + am) * lda + kk0 + ak];
        float4 bv = *(const float4*)&B[(long long)(k0 + bk) * N + n0 + bn];

        As[ak + 0][am] = av.x;
        As[ak + 1][am] = av.y;
        As[ak + 2][am] = av.z;
        As[ak + 3][am] = av.w;
        *(float4*)&Bs[bk][bn] = bv;
        __syncthreads();

#pragma unroll
        for (int kk = 0; kk < 8; kk++) {
            float a[8], bb[8];
#pragma unroll
            for (int i = 0; i < 4; i++) {
                a[i]     = As[kk][ty * 4 + i];
                a[i + 4] = As[kk][64 + ty * 4 + i];
            }
#pragma unroll
            for (int j = 0; j < 4; j++) {
                bb[j]     = Bs[kk][tx * 4 + j];
                bb[j + 4] = Bs[kk][64 + tx * 4 + j];
            }
#pragma unroll
            for (int i = 0; i < 8; i++)
#pragma unroll
                for (int j = 0; j < 8; j++)
                    acc[i][j] += a[i] * bb[j];
        }
        __syncthreads();
    }

    // epilogue
#pragma unroll
    for (int i = 0; i < 8; i++) {
        int r = m0 + ((i < 4) ? (ty * 4 + i) : (64 + ty * 4 + (i - 4)));
#pragma unroll
        for (int j = 0; j < 8; j++) {
            int c = n0 + ((j < 4) ? (tx * 4 + j) : (64 + tx * 4 + (j - 4)));
            float v = acc[i][j];
            if (EPI >= 1) v += bias[c];
            if (EPI == 2) v = 0.5f * v * (1.0f + erff(v * 0.70710678118654752f));
            C[(long long)r * N + c] = v;
        }
    }
}

// ---------------- column softmax over L (axis=1) ------------------------------
// pass1: per-(b, channel) online max + sum(exp(x - max))
__global__ void softmax_p1(const float* __restrict__ Kin,
                           float* __restrict__ cm, float* __restrict__ cs)
{
    const int b  = blockIdx.y;
    const int c0 = blockIdx.x * 32;
    const int tx = threadIdx.x;   // 0..31 channel
    const int ty = threadIdx.y;   // 0..15 L partition

    const float* kb = Kin + (long long)b * LSEQ * CC + c0 + tx;
    float m = -1e30f, s = 0.f;
    for (int l = ty; l < LSEQ; l += 16) {
        float v = kb[(long long)l * CC];
        if (v > m) { s = s * expf(m - v) + 1.0f; m = v; }
        else       { s += expf(v - m); }
    }

    __shared__ float Ms[16][32], Ss[16][32];
    Ms[ty][tx] = m; Ss[ty][tx] = s;
    __syncthreads();
    for (int st = 8; st > 0; st >>= 1) {
        if (ty < st) {
            float m2 = Ms[ty + st][tx], s2 = Ss[ty + st][tx];
            float mm = fmaxf(m, m2);
            s = s * expf(m - mm) + s2 * expf(m2 - mm);
            m = mm;
            Ms[ty][tx] = m; Ss[ty][tx] = s;
        }
        __syncthreads();
    }
    if (ty == 0) { cm[b * CC + c0 + tx] = m; cs[b * CC + c0 + tx] = s; }
}

// pass2: in-place normalize
__global__ void softmax_p2(float* __restrict__ Kio,
                           const float* __restrict__ cm, const float* __restrict__ cs)
{
    int idx = blockIdx.x * 256 + threadIdx.x;   // BL*CC = 2^23 elements
    int c = idx & 255;
    int b = idx >> 21;                           // LSEQ*CC = 2^21
    float v = Kio[idx];
    Kio[idx] = expf(v - cm[b * CC + c]) / cs[b * CC + c];
}

// ---------------- context^T: ctxT[b][e][d] = sum_n k[n,e] q[n,d] --------------
// split-N partials (deterministic), 64x64 tile per block
__global__ __launch_bounds__(256)
void ata64(const float* __restrict__ Km, const float* __restrict__ Qm,
           float* __restrict__ part)
{
    const int b     = blockIdx.z;
    const int tile  = blockIdx.x;           // 0..15
    const int split = blockIdx.y;           // 0..NSPLIT-1
    const int e0 = (tile >> 2) * 64;
    const int d0 = (tile & 3)  * 64;

    const float* kb = Km + (long long)b * LSEQ * CC;
    const float* qb = Qm + (long long)b * LSEQ * CC;

    __shared__ float Ks[8][64], Qs[8][64];
    const int t  = threadIdx.x;
    const int tx = t & 15, ty = t >> 4;

    float acc[4][4];
#pragma unroll
    for (int i = 0; i < 4; i++)
#pragma unroll
        for (int j = 0; j < 4; j++) acc[i][j] = 0.f;

    const int nbeg = split * (LSEQ / NSPLIT);
    const int nend = nbeg + (LSEQ / NSPLIT);
    for (int n0 = nbeg; n0 < nend; n0 += 8) {
#pragma unroll
        for (int i = 0; i < 2; i++) {
            int lin = t + i * 256;
            int r = lin >> 6, c = lin & 63;
            Ks[r][c] = kb[(long long)(n0 + r) * CC + e0 + c];
            Qs[r][c] = qb[(long long)(n0 + r) * CC + d0 + c];
        }
        __syncthreads();
#pragma unroll
        for (int r = 0; r < 8; r++) {
            float a[4], bb[4];
#pragma unroll
            for (int i = 0; i < 4; i++) a[i]  = Ks[r][ty * 4 + i];
#pragma unroll
            for (int j = 0; j < 4; j++) bb[j] = Qs[r][tx * 4 + j];
#pragma unroll
            for (int i = 0; i < 4; i++)
#pragma unroll
                for (int j = 0; j < 4; j++) acc[i][j] += a[i] * bb[j];
        }
        __syncthreads();
    }

    float* cp = part + ((long long)(split * BATCH + b) << 16);
#pragma unroll
    for (int i = 0; i < 4; i++)
#pragma unroll
        for (int j = 0; j < 4; j++)
            cp[(e0 + ty * 4 + i) * CC + d0 + tx * 4 + j] = acc[i][j];
}

__global__ void reduce_ctx(const float* __restrict__ part, float* __restrict__ ctx)
{
    int i = blockIdx.x * 256 + threadIdx.x;   // BATCH*CC*CC = 262144
    int b = i >> 16;
    int w = i & 65535;
    float s = 0.f;
#pragma unroll
    for (int sp = 0; sp < NSPLIT; sp++)
        s += part[((long long)(sp * BATCH + b) << 16) + w];
    ctx[i] = s;
}

// ---------------- layernorm over C=256 (optionally + residual) ---------------
template<bool RES>
__global__ void layernorm_k(const float* __restrict__ X,
                            const float* __restrict__ gamma,
                            const float* __restrict__ beta,
                            const float* __restrict__ src,
                            float* __restrict__ O)
{
    const int row = blockIdx.x;
    const int t   = threadIdx.x;   // 256
    const long long base = (long long)row * CC;

    float x = X[base + t];
    __shared__ float red[8];

    float s = x;
#pragma unroll
    for (int o = 16; o; o >>= 1) s += __shfl_xor_sync(0xffffffffu, s, o);
    if ((t & 31) == 0) red[t >> 5] = s;
    __syncthreads();
    float mu = 0.f;
#pragma unroll
    for (int i = 0; i < 8; i++) mu += red[i];
    mu *= (1.0f / 256.0f);
    __syncthreads();

    float d = x - mu;
    float q = d * d;
#pragma unroll
    for (int o = 16; o; o >>= 1) q += __shfl_xor_sync(0xffffffffu, q, o);
    if ((t & 31) == 0) red[t >> 5] = q;
    __syncthreads();
    float var = 0.f;
#pragma unroll
    for (int i = 0; i < 8; i++) var += red[i];
    var *= (1.0f / 256.0f);

    float y = d * rsqrtf(var + 1e-5f) * gamma[t] + beta[t];
    O[base + t] = RES ? (src[base + t] + y) : y;
}

// ---------------- launch ------------------------------------------------------
extern "C" void kernel_launch(void* const* d_in, const int* in_sizes, int n_in,
                              void* d_out, int out_size)
{
    const float* src    = (const float*)d_in[0];
    const float* tgt    = (const float*)d_in[1];
    const float* Wq     = (const float*)d_in[2];
    const float* Wk     = (const float*)d_in[3];
    const float* Wv     = (const float*)d_in[4];
    const float* Wl     = (const float*)d_in[5];
    const float* gamma1 = (const float*)d_in[6];
    const float* beta1  = (const float*)d_in[7];
    const float* W1     = (const float*)d_in[8];
    const float* b1     = (const float*)d_in[9];
    const float* W2     = (const float*)d_in[10];
    const float* b2     = (const float*)d_in[11];
    const float* gamma2 = (const float*)d_in[12];
    const float* beta2  = (const float*)d_in[13];
    float* out = (float*)d_out;

    float *q, *k, *v, *attn, *lin, *ln1, *f2, *hid, *ctx, *cpart, *cm, *cs;
    cudaGetSymbolAddress((void**)&q,     g_q);
    cudaGetSymbolAddress((void**)&k,     g_k);
    cudaGetSymbolAddress((void**)&v,     g_v);
    cudaGetSymbolAddress((void**)&attn,  g_attn);
    cudaGetSymbolAddress((void**)&lin,   g_lin);
    cudaGetSymbolAddress((void**)&ln1,   g_ln1);
    cudaGetSymbolAddress((void**)&f2,    g_f2);
    cudaGetSymbolAddress((void**)&hid,   g_hid);
    cudaGetSymbolAddress((void**)&ctx,   g_ctx);
    cudaGetSymbolAddress((void**)&cpart, g_cpart);
    cudaGetSymbolAddress((void**)&cm,    g_cm);
    cudaGetSymbolAddress((void**)&cs,    g_cs);

    dim3 blk(256);

    // q = source @ Wq ; k = target @ Wk ; v = target @ Wv
    sgemm_k<0, false><<<dim3(2, 256, 1), blk>>>(src, nullptr, CC, Wq, nullptr, q,  BL, CC, CC, 0, 0, 0);
    sgemm_k<0, false><<<dim3(2, 256, 1), blk>>>(tgt, nullptr, CC, Wk, nullptr, k,  BL, CC, CC, 0, 0, 0);
    sgemm_k<0, false><<<dim3(2, 256, 1), blk>>>(tgt, nullptr, CC, Wv, nullptr, v,  BL, CC, CC, 0, 0, 0);

    // softmax over token dim (axis=1), in place on k
    softmax_p1<<<dim3(8, 4), dim3(32, 16)>>>(k, cm, cs);
    softmax_p2<<<32768, 256>>>(k, cm, cs);

    // ctxT[b] = k_soft[b]^T @ q[b]  (split-N partials + deterministic reduce)
    ata64<<<dim3(16, NSPLIT, BATCH), 256>>>(k, q, cpart);
    reduce_ctx<<<1024, 256>>>(cpart, ctx);

    // attn[b] = v[b] @ ctxT[b]   (batched)
    sgemm_k<0, false><<<dim3(2, 64, BATCH), blk>>>(v, nullptr, CC, ctx, nullptr, attn,
                                                   LSEQ, CC, CC,
                                                   (long long)LSEQ * CC, (long long)CC * CC,
                                                   (long long)LSEQ * CC);

    // message = LN(attn @ Wl)
    sgemm_k<0, false><<<dim3(2, 256, 1), blk>>>(attn, nullptr, CC, Wl, nullptr, lin, BL, CC, CC, 0, 0, 0);
    layernorm_k<false><<<32768, 256>>>(lin, gamma1, beta1, nullptr, ln1);

    // hidden = gelu([source | message] @ W1 + b1)   (virtual concat, dual-A)
    sgemm_k<2, true><<<dim3(16, 256, 1), blk>>>(src, ln1, CC, W1, b1, hid, BL, HID, 512, 0, 0, 0);

    // out = source + LN(hidden @ W2 + b2)
    sgemm_k<1, false><<<dim3(2, 256, 1), blk>>>(hid, nullptr, HID, W2, b2, f2, BL, CC, HID, 0, 0, 0);
    layernorm_k<true><<<32768, 256>>>(f2, gamma2, beta2, src, out);
}

// round 4
// speedup vs baseline: 2.2921x; 2.2921x over previous
#include <cuda_runtime.h>
#include <cuda_bf16.h>
#include <cstdint>
#include <math.h>

#define BATCH 4
#define LSEQ  8192
#define CC    256
#define BL    32768
#define HID   2048
#define NSPK  16

// ---------------- PTX helpers -----------------------------------------------
__device__ __forceinline__ uint32_t s2u(const void* p) {
    uint32_t a;
    asm("{ .reg .u64 t; cvta.to.shared.u64 t, %1; cvt.u32.u64 %0, t; }" : "=r"(a) : "l"(p));
    return a;
}
__device__ __forceinline__ void cpasync16(uint32_t s, const void* g) {
    asm volatile("cp.async.cg.shared.global [%0], [%1], 16;" :: "r"(s), "l"(g));
}
#define CP_COMMIT() asm volatile("cp.async.commit_group;" ::: "memory")
#define CP_WAIT1()  asm volatile("cp.async.wait_group 1;" ::: "memory")
__device__ __forceinline__ void ldsm4(uint32_t* r, uint32_t a) {
    asm volatile("ldmatrix.sync.aligned.m8n8.x4.shared.b16 {%0,%1,%2,%3}, [%4];"
        : "=r"(r[0]), "=r"(r[1]), "=r"(r[2]), "=r"(r[3]) : "r"(a));
}
__device__ __forceinline__ void ldsm2(uint32_t* r, uint32_t a) {
    asm volatile("ldmatrix.sync.aligned.m8n8.x2.shared.b16 {%0,%1}, [%2];"
        : "=r"(r[0]), "=r"(r[1]) : "r"(a));
}
__device__ __forceinline__ void mma16816(float* d, const uint32_t* a, const uint32_t* b) {
    asm volatile(
        "mma.sync.aligned.m16n8k16.row.col.f32.bf16.bf16.f32 "
        "{%0,%1,%2,%3}, {%4,%5,%6,%7}, {%8,%9}, {%0,%1,%2,%3};"
        : "+f"(d[0]), "+f"(d[1]), "+f"(d[2]), "+f"(d[3])
        : "r"(a[0]), "r"(a[1]), "r"(a[2]), "r"(a[3]), "r"(b[0]), "r"(b[1]));
}

// ---------------- scratch ----------------------------------------------------
__device__ __nv_bfloat16 g_srcH[BL*CC], g_srcL[BL*CC], g_tgtH[BL*CC], g_tgtL[BL*CC];
__device__ float         g_q[BL*CC], g_k[BL*CC], g_lin[BL*CC], g_f2[BL*CC];
__device__ __nv_bfloat16 g_qTh[BL*CC], g_qTl[BL*CC], g_kTh[BL*CC], g_kTl[BL*CC];
__device__ __nv_bfloat16 g_vH[BL*CC], g_vL[BL*CC], g_atH[BL*CC], g_atL[BL*CC];
__device__ __nv_bfloat16 g_l1H[BL*CC], g_l1L[BL*CC];
__device__ __nv_bfloat16 g_hidH[(long long)BL*HID], g_hidL[(long long)BL*HID];
__device__ __nv_bfloat16 g_cxH[BATCH*CC*CC], g_cxL[BATCH*CC*CC];
__device__ float         g_cpart[BATCH*NSPK*CC*CC];
__device__ __nv_bfloat16 g_WqH[CC*CC], g_WqL[CC*CC], g_WkH[CC*CC], g_WkL[CC*CC];
__device__ __nv_bfloat16 g_WvH[CC*CC], g_WvL[CC*CC], g_WlH[CC*CC], g_WlL[CC*CC];
__device__ __nv_bfloat16 g_W1H[HID*2*CC], g_W1L[HID*2*CC], g_W2H[CC*HID], g_W2L[CC*HID];
__device__ float g_pm[16*BATCH*CC], g_ps[16*BATCH*CC], g_cm[BATCH*CC], g_cs[BATCH*CC];

// ---------------- small utils -------------------------------------------------
__device__ __forceinline__ void bsplit(float x, unsigned short& h, unsigned short& l) {
    __nv_bfloat16 bh = __float2bfloat16_rn(x);
    __nv_bfloat16 bl = __float2bfloat16_rn(x - __bfloat162float(bh));
    h = __bfloat16_as_ushort(bh); l = __bfloat16_as_ushort(bl);
}
__device__ __forceinline__ void bsplit2(float a, float b, uint32_t& h, uint32_t& l) {
    unsigned short h0, l0, h1, l1;
    bsplit(a, h0, l0); bsplit(b, h1, l1);
    h = (uint32_t)h0 | ((uint32_t)h1 << 16);
    l = (uint32_t)l0 | ((uint32_t)l1 << 16);
}
__device__ __forceinline__ float gelu_f(float x) {
    return 0.5f * x * (1.0f + erff(x * 0.70710678118654752f));
}

// ---------------- mma.sync GEMM ----------------------------------------------
// Tile M=128 N=128 Kchunk=32, 2-stage cp.async, 8 warps (2m x 4n), bf16x3.
// EP: 0 = f32 out, 1 = hi/lo out, 2 = bias+gelu hi/lo out
static constexpr int STAGE = 40960;            // Ah|Al|Bh|Bl, each 128*80B
static constexpr int GSMEM = 2 * STAGE;

template<int EP, bool DUAL, bool SPLITK>
__global__ __launch_bounds__(256)
void gemm_mma(const __nv_bfloat16* __restrict__ Ah, const __nv_bfloat16* __restrict__ Al,
              const __nv_bfloat16* __restrict__ A2h, const __nv_bfloat16* __restrict__ A2l, int lda,
              const __nv_bfloat16* __restrict__ Bh, const __nv_bfloat16* __restrict__ Bl, int ldb,
              const float* __restrict__ bias,
              float* __restrict__ of, __nv_bfloat16* __restrict__ oh, __nv_bfloat16* __restrict__ ol,
              int ldo, int Ktot, long long sA, long long sB, long long sO, int kslen)
{
    extern __shared__ char smem[];
    const uint32_t sb = s2u(smem);
    const int tid = threadIdx.x, lane = tid & 31, wid = tid >> 5;
    const int wm = wid >> 2, wn = wid & 3;
    const int m0 = blockIdx.y * 128, n0 = blockIdx.x * 128, z = blockIdx.z;

    int kbase = 0, K = Ktot;
    long long ooff;
    if (SPLITK) {
        int b = z / NSPK, sp = z - b * NSPK;
        Ah += (long long)b * sA; Al += (long long)b * sA;
        Bh += (long long)b * sB; Bl += (long long)b * sB;
        kbase = sp * kslen; K = kslen;
        ooff = (long long)z * sO;
    } else {
        Ah += (long long)z * sA; Al += (long long)z * sA;
        Bh += (long long)z * sB; Bl += (long long)z * sB;
        ooff = (long long)z * sO;
    }
    if (of) of += ooff;
    if (oh) { oh += ooff; ol += ooff; }

    float c[4][4][4];
#pragma unroll
    for (int i = 0; i < 4; ++i)
#pragma unroll
        for (int j = 0; j < 4; ++j)
#pragma unroll
            for (int q = 0; q < 4; ++q) c[i][j][q] = 0.f;

    auto LOADST = [&](int s, int kc) {
        uint32_t stb = sb + s * STAGE;
#pragma unroll
        for (int i = 0; i < 8; ++i) {
            int g = tid + i * 256;
            int tile = g >> 9, idx = g & 511;
            int row = idx >> 2, ch = idx & 3;
            uint32_t sa = stb + tile * 10240 + row * 80 + ch * 16;
            const __nv_bfloat16* gp;
            if (tile < 2) {
                const __nv_bfloat16* pa; int ka = kc;
                if (DUAL && kc >= 256) { pa = (tile == 0 ? A2h : A2l); ka = kc - 256; }
                else                   { pa = (tile == 0 ? Ah  : Al ); }
                gp = pa + (long long)(m0 + row) * lda + ka + ch * 8;
            } else {
                gp = (tile == 2 ? Bh : Bl) + (long long)(n0 + row) * ldb + kc + ch * 8;
            }
            cpasync16(sa, gp);
        }
    };

    const int nch = K >> 5;
    LOADST(0, kbase);
    CP_COMMIT();

    for (int it = 0; it < nch; ++it) {
        if (it + 1 < nch) LOADST((it + 1) & 1, kbase + ((it + 1) << 5));
        CP_COMMIT();
        CP_WAIT1();
        __syncthreads();

        uint32_t stb = sb + (it & 1) * STAGE;
#pragma unroll
        for (int kk = 0; kk < 2; ++kk) {
            uint32_t ab = stb + kk * 32 + (uint32_t)((lane & 15) + wm * 64) * 80 + ((lane >> 4) << 4);
            uint32_t ah[4][4], al[4][4];
#pragma unroll
            for (int mt = 0; mt < 4; ++mt) {
                ldsm4(ah[mt], ab + mt * 16 * 80);
                ldsm4(al[mt], ab + 10240 + mt * 16 * 80);
            }
            uint32_t bb = stb + 20480 + kk * 32 + (uint32_t)((lane & 7) + wn * 32) * 80 + (((lane >> 3) & 1) << 4);
            uint32_t bh[4][2], bl[4][2];
#pragma unroll
            for (int nt = 0; nt < 4; ++nt) {
                ldsm2(bh[nt], bb + nt * 8 * 80);
                ldsm2(bl[nt], bb + 10240 + nt * 8 * 80);
            }
#pragma unroll
            for (int mt = 0; mt < 4; ++mt)
#pragma unroll
                for (int nt = 0; nt < 4; ++nt) {
                    mma16816(c[mt][nt], ah[mt], bh[nt]);
                    mma16816(c[mt][nt], ah[mt], bl[nt]);
                    mma16816(c[mt][nt], al[mt], bh[nt]);
                }
        }
        __syncthreads();
    }

    // epilogue
#pragma unroll
    for (int mt = 0; mt < 4; ++mt)
#pragma unroll
        for (int nt = 0; nt < 4; ++nt) {
            int r  = m0 + wm * 64 + mt * 16 + (lane >> 2);
            int cl = n0 + wn * 32 + nt * 8 + ((lane & 3) << 1);
            float* d = c[mt][nt];
            if (EP == 0) {
                *(float2*)&of[(long long)r * ldo + cl]       = make_float2(d[0], d[1]);
                *(float2*)&of[(long long)(r + 8) * ldo + cl] = make_float2(d[2], d[3]);
            } else {
                float v0 = d[0], v1 = d[1], v2 = d[2], v3 = d[3];
                if (EP == 2) {
                    float b0v = bias[cl], b1v = bias[cl + 1];
                    v0 = gelu_f(v0 + b0v); v1 = gelu_f(v1 + b1v);
                    v2 = gelu_f(v2 + b0v); v3 = gelu_f(v3 + b1v);
                }
                uint32_t h01, l01, h23, l23;
                bsplit2(v0, v1, h01, l01);
                bsplit2(v2, v3, h23, l23);
                *(uint32_t*)&oh[(long long)r * ldo + cl]       = h01;
                *(uint32_t*)&ol[(long long)r * ldo + cl]       = l01;
                *(uint32_t*)&oh[(long long)(r + 8) * ldo + cl] = h23;
                *(uint32_t*)&ol[(long long)(r + 8) * ldo + cl] = l23;
            }
        }
}

// ---------------- elementwise / transforms -----------------------------------
__global__ void convsplit(const float* __restrict__ in, __nv_bfloat16* __restrict__ oh,
                          __nv_bfloat16* __restrict__ ol)
{
    int i = (blockIdx.x * 256 + threadIdx.x) * 4;
    float4 v = *(const float4*)(in + i);
    uint32_t h0, l0, h1, l1;
    bsplit2(v.x, v.y, h0, l0); bsplit2(v.z, v.w, h1, l1);
    *(uint2*)(oh + i) = make_uint2(h0, h1);
    *(uint2*)(ol + i) = make_uint2(l0, l1);
}

template<bool NORM>
__global__ void tsplit(const float* __restrict__ in, __nv_bfloat16* __restrict__ oh,
                       __nv_bfloat16* __restrict__ ol, int R, int C,
                       long long sIn, long long sOut,
                       const float* __restrict__ cm, const float* __restrict__ cs)
{
    __shared__ float tile[32][33];
    const int z = blockIdx.z;
    const int c0 = blockIdx.x * 32, r0 = blockIdx.y * 32;
    const int tx = threadIdx.x, ty = threadIdx.y;
    const float* ip = in + z * sIn;
    float nm = 0.f, ns = 1.f;
    if (NORM) { nm = cm[z * CC + c0 + tx]; ns = 1.f / cs[z * CC + c0 + tx]; }
#pragma unroll
    for (int i = 0; i < 4; ++i) {
        float v = ip[(long long)(r0 + ty + i * 8) * C + c0 + tx];
        if (NORM) v = expf(v - nm) * ns;
        tile[ty + i * 8][tx] = v;
    }
    __syncthreads();
#pragma unroll
    for (int i = 0; i < 4; ++i) {
        int cidx = c0 + ty + i * 8;
        float v = tile[tx][ty + i * 8];
        unsigned short h, l;
        bsplit(v, h, l);
        long long o = z * sOut + (long long)cidx * R + r0 + tx;
        oh[o] = __ushort_as_bfloat16(h);
        ol[o] = __ushort_as_bfloat16(l);
    }
}

__global__ void softmax_p1(const float* __restrict__ Kin, float* __restrict__ pm, float* __restrict__ ps)
{
    const int b = blockIdx.z, sp = blockIdx.y, c0 = blockIdx.x * 32;
    const int tx = threadIdx.x, ty = threadIdx.y;
    const float* kb = Kin + (long long)b * LSEQ * CC + c0 + tx;
    const int n0 = sp * 512;
    float m = -1e30f, s = 0.f;
    for (int l = ty; l < 512; l += 8) {
        float v = kb[(long long)(n0 + l) * CC];
        if (v > m) { s = s * expf(m - v) + 1.0f; m = v; }
        else       { s += expf(v - m); }
    }
    __shared__ float Ms[8][32], Ss[8][32];
    Ms[ty][tx] = m; Ss[ty][tx] = s;
    __syncthreads();
    if (ty == 0) {
#pragma unroll
        for (int r = 1; r < 8; ++r) {
            float m2 = Ms[r][tx], s2 = Ss[r][tx];
            float mm = fmaxf(m, m2);
            s = s * expf(m - mm) + s2 * expf(m2 - mm);
            m = mm;
        }
        pm[(sp * BATCH + b) * CC + c0 + tx] = m;
        ps[(sp * BATCH + b) * CC + c0 + tx] = s;
    }
}
__global__ void softmax_comb(const float* __restrict__ pm, const float* __restrict__ ps,
                             float* __restrict__ cm, float* __restrict__ cs)
{
    const int b = blockIdx.x, cch = threadIdx.x;
    float m = -1e30f, s = 0.f;
#pragma unroll
    for (int sp = 0; sp < 16; ++sp) {
        float m2 = pm[(sp * BATCH + b) * CC + cch], s2 = ps[(sp * BATCH + b) * CC + cch];
        float mm = fmaxf(m, m2);
        s = s * expf(m - mm) + s2 * expf(m2 - mm);
        m = mm;
    }
    cm[b * CC + cch] = m; cs[b * CC + cch] = s;
}

__global__ void reduce_split(const float* __restrict__ part, __nv_bfloat16* __restrict__ oh,
                             __nv_bfloat16* __restrict__ ol)
{
    int i = blockIdx.x * 256 + threadIdx.x;
    int b = i >> 16, w = i & 65535;
    float s = 0.f;
#pragma unroll
    for (int sp = 0; sp < NSPK; ++sp) s += part[(long long)(b * NSPK + sp) * 65536 + w];
    unsigned short h, l;
    bsplit(s, h, l);
    oh[i] = __ushort_as_bfloat16(h);
    ol[i] = __ushort_as_bfloat16(l);
}

// LN (optionally +bias pre, +residual post); OUT: 0 = hi/lo, 1 = f32
template<int OUT, bool PREB, bool RES>
__global__ void ln_k(const float* __restrict__ X, const float* __restrict__ preb,
                     const float* __restrict__ gamma, const float* __restrict__ beta,
                     const float* __restrict__ resid,
                     float* __restrict__ of, __nv_bfloat16* __restrict__ oh, __nv_bfloat16* __restrict__ ol)
{
    const int row = blockIdx.x, t = threadIdx.x;
    const long long base = (long long)row * CC;
    float x = X[base + t];
    if (PREB) x += preb[t];
    __shared__ float red[8];
    float s = x;
#pragma unroll
    for (int o = 16; o; o >>= 1) s += __shfl_xor_sync(0xffffffffu, s, o);
    if ((t & 31) == 0) red[t >> 5] = s;
    __syncthreads();
    float mu = 0.f;
#pragma unroll
    for (int i = 0; i < 8; ++i) mu += red[i];
    mu *= (1.f / 256.f);
    __syncthreads();
    float d = x - mu, q = d * d;
#pragma unroll
    for (int o = 16; o; o >>= 1) q += __shfl_xor_sync(0xffffffffu, q, o);
    if ((t & 31) == 0) red[t >> 5] = q;
    __syncthreads();
    float var = 0.f;
#pragma unroll
    for (int i = 0; i < 8; ++i) var += red[i];
    var *= (1.f / 256.f);
    float y = d * rsqrtf(var + 1e-5f) * gamma[t] + beta[t];
    if (RES) y += resid[base + t];
    if (OUT == 1) of[base + t] = y;
    else {
        unsigned short h, l;
        bsplit(y, h, l);
        oh[base + t] = __ushort_as_bfloat16(h);
        ol[base + t] = __ushort_as_bfloat16(l);
    }
}

// ---------------- launch ------------------------------------------------------
extern "C" void kernel_launch(void* const* d_in, const int* in_sizes, int n_in,
                              void* d_out, int out_size)
{
    const float* src = (const float*)d_in[0];
    const float* tgt = (const float*)d_in[1];
    const float* Wq  = (const float*)d_in[2];
    const float* Wk  = (const float*)d_in[3];
    const float* Wv  = (const float*)d_in[4];
    const float* Wl  = (const float*)d_in[5];
    const float* gamma1 = (const float*)d_in[6];
    const float* beta1  = (const float*)d_in[7];
    const float* W1  = (const float*)d_in[8];
    const float* b1  = (const float*)d_in[9];
    const float* W2  = (const float*)d_in[10];
    const float* b2  = (const float*)d_in[11];
    const float* gamma2 = (const float*)d_in[12];
    const float* beta2  = (const float*)d_in[13];
    float* out = (float*)d_out;

    cudaFuncSetAttribute(gemm_mma<0,false,false>, cudaFuncAttributeMaxDynamicSharedMemorySize, GSMEM);
    cudaFuncSetAttribute(gemm_mma<0,false,true>,  cudaFuncAttributeMaxDynamicSharedMemorySize, GSMEM);
    cudaFuncSetAttribute(gemm_mma<1,false,false>, cudaFuncAttributeMaxDynamicSharedMemorySize, GSMEM);
    cudaFuncSetAttribute(gemm_mma<2,true,false>,  cudaFuncAttributeMaxDynamicSharedMemorySize, GSMEM);

    #define SYM(v, s) cudaGetSymbolAddress((void**)&v, s)
    __nv_bfloat16 *srcH,*srcL,*tgtH,*tgtL,*qTh,*qTl,*kTh,*kTl,*vH,*vL,*atH,*atL,*l1H,*l1L;
    __nv_bfloat16 *hidH,*hidL,*cxH,*cxL,*WqH,*WqL,*WkH,*WkL,*WvH,*WvL,*WlH,*WlL,*W1H,*W1L,*W2H,*W2L;
    float *qf,*kf,*linf,*f2f,*cpart,*pm,*ps,*cm,*cs;
    SYM(srcH,g_srcH); SYM(srcL,g_srcL); SYM(tgtH,g_tgtH); SYM(tgtL,g_tgtL);
    SYM(qf,g_q); SYM(kf,g_k); SYM(linf,g_lin); SYM(f2f,g_f2);
    SYM(qTh,g_qTh); SYM(qTl,g_qTl); SYM(kTh,g_kTh); SYM(kTl,g_kTl);
    SYM(vH,g_vH); SYM(vL,g_vL); SYM(atH,g_atH); SYM(atL,g_atL);
    SYM(l1H,g_l1H); SYM(l1L,g_l1L); SYM(hidH,g_hidH); SYM(hidL,g_hidL);
    SYM(cxH,g_cxH); SYM(cxL,g_cxL); SYM(cpart,g_cpart);
    SYM(WqH,g_WqH); SYM(WqL,g_WqL); SYM(WkH,g_WkH); SYM(WkL,g_WkL);
    SYM(WvH,g_WvH); SYM(WvL,g_WvL); SYM(WlH,g_WlH); SYM(WlL,g_WlL);
    SYM(W1H,g_W1H); SYM(W1L,g_W1L); SYM(W2H,g_W2H); SYM(W2L,g_W2L);
    SYM(pm,g_pm); SYM(ps,g_ps); SYM(cm,g_cm); SYM(cs,g_cs);
    #undef SYM

    const dim3 tb(32, 8);

    // converts + weight transpose-splits (W [K][N] -> WT [N][K])
    convsplit<<<8192, 256>>>(src, srcH, srcL);
    convsplit<<<8192, 256>>>(tgt, tgtH, tgtL);
    tsplit<false><<<dim3(8, 8, 1),   tb>>>(Wq, WqH, WqL, 256, 256, 0, 0, nullptr, nullptr);
    tsplit<false><<<dim3(8, 8, 1),   tb>>>(Wk, WkH, WkL, 256, 256, 0, 0, nullptr, nullptr);
    tsplit<false><<<dim3(8, 8, 1),   tb>>>(Wv, WvH, WvL, 256, 256, 0, 0, nullptr, nullptr);
    tsplit<false><<<dim3(8, 8, 1),   tb>>>(Wl, WlH, WlL, 256, 256, 0, 0, nullptr, nullptr);
    tsplit<false><<<dim3(64, 16, 1), tb>>>(W1, W1H, W1L, 512, 2048, 0, 0, nullptr, nullptr);
    tsplit<false><<<dim3(8, 64, 1),  tb>>>(W2, W2H, W2L, 2048, 256, 0, 0, nullptr, nullptr);

    // q, k (f32), v (hi/lo)
    gemm_mma<0,false,false><<<dim3(2,256,1), 256, GSMEM>>>(srcH, srcL, nullptr, nullptr, 256,
        WqH, WqL, 256, nullptr, qf, nullptr, nullptr, 256, 256, 0, 0, 0, 0);
    gemm_mma<0,false,false><<<dim3(2,256,1), 256, GSMEM>>>(tgtH, tgtL, nullptr, nullptr, 256,
        WkH, WkL, 256, nullptr, kf, nullptr, nullptr, 256, 256, 0, 0, 0, 0);
    gemm_mma<1,false,false><<<dim3(2,256,1), 256, GSMEM>>>(tgtH, tgtL, nullptr, nullptr, 256,
        WvH, WvL, 256, nullptr, nullptr, vH, vL, 256, 256, 0, 0, 0, 0);

    // softmax over tokens; transpose+split k (normalized) and q -> [b][c][n]
    softmax_p1<<<dim3(8, 16, BATCH), tb>>>(kf, pm, ps);
    softmax_comb<<<BATCH, 256>>>(pm, ps, cm, cs);
    tsplit<true><<<dim3(8, 256, BATCH), tb>>>(kf, kTh, kTl, LSEQ, 256,
        (long long)LSEQ*CC, (long long)CC*LSEQ, cm, cs);
    tsplit<false><<<dim3(8, 256, BATCH), tb>>>(qf, qTh, qTl, LSEQ, 256,
        (long long)LSEQ*CC, (long long)CC*LSEQ, nullptr, nullptr);

    // ctx[d][e] = sum_n qT[d][n] * kT[e][n]  (split-K, f32 partials, det. reduce)
    gemm_mma<0,false,true><<<dim3(2, 2, BATCH*NSPK), 256, GSMEM>>>(qTh, qTl, nullptr, nullptr, LSEQ,
        kTh, kTl, LSEQ, nullptr, cpart, nullptr, nullptr, 256,
        LSEQ, (long long)CC*LSEQ, (long long)CC*LSEQ, 65536, LSEQ / NSPK);
    reduce_split<<<1024, 256>>>(cpart, cxH, cxL);

    // attn[n][d] = sum_e v[n][e] * ctx[d][e]
    gemm_mma<1,false,false><<<dim3(2, 64, BATCH), 256, GSMEM>>>(vH, vL, nullptr, nullptr, 256,
        cxH, cxL, 256, nullptr, nullptr, atH, atL, 256,
        256, (long long)LSEQ*CC, 65536, (long long)LSEQ*CC, 0);

    // message = LN(attn @ Wl)
    gemm_mma<0,false,false><<<dim3(2,256,1), 256, GSMEM>>>(atH, atL, nullptr, nullptr, 256,
        WlH, WlL, 256, nullptr, linf, nullptr, nullptr, 256, 256, 0, 0, 0, 0);
    ln_k<0,false,false><<<32768, 256>>>(linf, nullptr, gamma1, beta1, nullptr, nullptr, l1H, l1L);

    // hidden = gelu([src | msg] @ W1 + b1)
    gemm_mma<2,true,false><<<dim3(16,256,1), 256, GSMEM>>>(srcH, srcL, l1H, l1L, 256,
        W1H, W1L, 512, b1, nullptr, hidH, hidL, 2048, 512, 0, 0, 0, 0);

    // out = src + LN(hidden @ W2 + b2)
    gemm_mma<0,false,false><<<dim3(2,256,1), 256, GSMEM>>>(hidH, hidL, nullptr, nullptr, 2048,
        W2H, W2L, 2048, nullptr, f2f, nullptr, nullptr, 256, 2048, 0, 0, 0, 0);
    ln_k<1,true,true><<<32768, 256>>>(f2f, b2, gamma2, beta2, src, out, nullptr, nullptr);
}

// round 5
// speedup vs baseline: 2.3637x; 1.0313x over previous
#include <cuda_runtime.h>
#include <cuda_bf16.h>
#include <cstdint>
#include <math.h>

#define BATCH 4
#define LSEQ  8192
#define CC    256
#define BL    32768
#define HID   2048
#define NSPK  16

// ---------------- PTX helpers -----------------------------------------------
__device__ __forceinline__ uint32_t s2u(const void* p) {
    uint32_t a;
    asm("{ .reg .u64 t; cvta.to.shared.u64 t, %1; cvt.u32.u64 %0, t; }" : "=r"(a) : "l"(p));
    return a;
}
__device__ __forceinline__ void cpasync16(uint32_t s, const void* g) {
    asm volatile("cp.async.cg.shared.global [%0], [%1], 16;" :: "r"(s), "l"(g));
}
#define CP_COMMIT() asm volatile("cp.async.commit_group;" ::: "memory")
#define CP_WAIT1()  asm volatile("cp.async.wait_group 1;" ::: "memory")
__device__ __forceinline__ void ldsm4(uint32_t* r, uint32_t a) {
    asm volatile("ldmatrix.sync.aligned.m8n8.x4.shared.b16 {%0,%1,%2,%3}, [%4];"
        : "=r"(r[0]), "=r"(r[1]), "=r"(r[2]), "=r"(r[3]) : "r"(a));
}
__device__ __forceinline__ void mma16816(float* d, const uint32_t* a, const uint32_t* b) {
    asm volatile(
        "mma.sync.aligned.m16n8k16.row.col.f32.bf16.bf16.f32 "
        "{%0,%1,%2,%3}, {%4,%5,%6,%7}, {%8,%9}, {%0,%1,%2,%3};"
        : "+f"(d[0]), "+f"(d[1]), "+f"(d[2]), "+f"(d[3])
        : "r"(a[0]), "r"(a[1]), "r"(a[2]), "r"(a[3]), "r"(b[0]), "r"(b[1]));
}

// ---------------- scratch ----------------------------------------------------
__device__ __nv_bfloat16 g_srcH[BL*CC], g_srcL[BL*CC], g_tgtH[BL*CC], g_tgtL[BL*CC];
__device__ float         g_q[BL*CC], g_k[BL*CC], g_lin[BL*CC], g_f2[BL*CC];
__device__ __nv_bfloat16 g_qTh[BL*CC], g_qTl[BL*CC], g_kTh[BL*CC], g_kTl[BL*CC];
__device__ __nv_bfloat16 g_vH[BL*CC], g_vL[BL*CC], g_atH[BL*CC], g_atL[BL*CC];
__device__ __nv_bfloat16 g_l1H[BL*CC], g_l1L[BL*CC];
__device__ __nv_bfloat16 g_hidH[(long long)BL*HID], g_hidL[(long long)BL*HID];
__device__ __nv_bfloat16 g_cxH[BATCH*CC*CC], g_cxL[BATCH*CC*CC];
__device__ float         g_cpart[BATCH*NSPK*CC*CC];
__device__ __nv_bfloat16 g_WqH[CC*CC], g_WqL[CC*CC], g_WkH[CC*CC], g_WkL[CC*CC];
__device__ __nv_bfloat16 g_WvH[CC*CC], g_WvL[CC*CC], g_WlH[CC*CC], g_WlL[CC*CC];
__device__ __nv_bfloat16 g_W1H[HID*2*CC], g_W1L[HID*2*CC], g_W2H[CC*HID], g_W2L[CC*HID];
__device__ float g_pm[16*BATCH*CC], g_ps[16*BATCH*CC], g_cm[BATCH*CC], g_cs[BATCH*CC];

// ---------------- small utils -------------------------------------------------
__device__ __forceinline__ void bsplit(float x, unsigned short& h, unsigned short& l) {
    __nv_bfloat16 bh = __float2bfloat16_rn(x);
    __nv_bfloat16 bl = __float2bfloat16_rn(x - __bfloat162float(bh));
    h = __bfloat16_as_ushort(bh); l = __bfloat16_as_ushort(bl);
}
__device__ __forceinline__ void bsplit2(float a, float b, uint32_t& h, uint32_t& l) {
    unsigned short h0, l0, h1, l1;
    bsplit(a, h0, l0); bsplit(b, h1, l1);
    h = (uint32_t)h0 | ((uint32_t)h1 << 16);
    l = (uint32_t)l0 | ((uint32_t)l1 << 16);
}
__device__ __forceinline__ float gelu_f(float x) {
    return 0.5f * x * (1.0f + erff(x * 0.70710678118654752f));
}

// ---------------- mma.sync GEMM ----------------------------------------------
// Tile M=128 N=128 Kchunk=32, 3-stage cp.async, 8 warps (2m x 4n), bf16x3.
// EP: 0 = f32 out, 1 = hi/lo out, 2 = bias+gelu hi/lo out
static constexpr int STAGE = 40960;            // Ah|Al|Bh|Bl, each 128*80B
static constexpr int GSMEM = 3 * STAGE;

template<int EP, bool DUAL, bool SPLITK>
__global__ __launch_bounds__(256)
void gemm_mma(const __nv_bfloat16* __restrict__ Ah, const __nv_bfloat16* __restrict__ Al,
              const __nv_bfloat16* __restrict__ A2h, const __nv_bfloat16* __restrict__ A2l, int lda,
              const __nv_bfloat16* __restrict__ Bh, const __nv_bfloat16* __restrict__ Bl, int ldb,
              const float* __restrict__ bias,
              float* __restrict__ of, __nv_bfloat16* __restrict__ oh, __nv_bfloat16* __restrict__ ol,
              int ldo, int Ktot, long long sA, long long sB, long long sO, int kslen)
{
    extern __shared__ char smem[];
    const uint32_t sb = s2u(smem);
    const int tid = threadIdx.x, lane = tid & 31, wid = tid >> 5;
    const int wm = wid >> 2, wn = wid & 3;
    const int m0 = blockIdx.y * 128, n0 = blockIdx.x * 128, z = blockIdx.z;

    int kbase = 0, K = Ktot;
    long long ooff;
    if (SPLITK) {
        int b = z / NSPK, sp = z - b * NSPK;
        Ah += (long long)b * sA; Al += (long long)b * sA;
        Bh += (long long)b * sB; Bl += (long long)b * sB;
        kbase = sp * kslen; K = kslen;
        ooff = (long long)z * sO;
    } else {
        Ah += (long long)z * sA; Al += (long long)z * sA;
        Bh += (long long)z * sB; Bl += (long long)z * sB;
        ooff = (long long)z * sO;
    }
    if (of) of += ooff;
    if (oh) { oh += ooff; ol += ooff; }

    float c[4][4][4];
#pragma unroll
    for (int i = 0; i < 4; ++i)
#pragma unroll
        for (int j = 0; j < 4; ++j)
#pragma unroll
            for (int q = 0; q < 4; ++q) c[i][j][q] = 0.f;

    auto LOADST = [&](int s, int kc) {
        uint32_t stb = sb + s * STAGE;
#pragma unroll
        for (int i = 0; i < 8; ++i) {
            int g = tid + i * 256;
            int tile = g >> 9, idx = g & 511;
            int row = idx >> 2, ch = idx & 3;
            uint32_t sa = stb + tile * 10240 + row * 80 + ch * 16;
            const __nv_bfloat16* gp;
            if (tile < 2) {
                const __nv_bfloat16* pa; int ka = kc;
                if (DUAL && kc >= 256) { pa = (tile == 0 ? A2h : A2l); ka = kc - 256; }
                else                   { pa = (tile == 0 ? Ah  : Al ); }
                gp = pa + (long long)(m0 + row) * lda + ka + ch * 8;
            } else {
                gp = (tile == 2 ? Bh : Bl) + (long long)(n0 + row) * ldb + kc + ch * 8;
            }
            cpasync16(sa, gp);
        }
    };

    const int nch = K >> 5;
    LOADST(0, kbase);
    CP_COMMIT();
    if (nch > 1) LOADST(1, kbase + 32);
    CP_COMMIT();

    int sidx = 0;                         // stage of current chunk
    for (int it = 0; it < nch; ++it) {
        CP_WAIT1();
        __syncthreads();
        if (it + 2 < nch) {
            int ns = sidx + 2; if (ns >= 3) ns -= 3;
            LOADST(ns, kbase + ((it + 2) << 5));
        }
        CP_COMMIT();

        uint32_t stb = sb + sidx * STAGE;
#pragma unroll
        for (int kk = 0; kk < 2; ++kk) {
            // A fragments: hi + lo
            uint32_t ab = stb + (uint32_t)((lane & 15) + wm * 64) * 80 + ((lane >> 4) << 4) + kk * 32;
            uint32_t ah[4][4], al[4][4];
#pragma unroll
            for (int mt = 0; mt < 4; ++mt) {
                ldsm4(ah[mt], ab + mt * 16 * 80);
                ldsm4(al[mt], ab + 10240 + mt * 16 * 80);
            }
            // B fragments: ldsm4 covers two nt tiles at once
            int brow = (lane & 7) + ((lane >> 4) << 3);     // 0..15
            int bcol = (lane >> 3) & 1;                      // k-half
            uint32_t bb = stb + 20480 + (uint32_t)(wn * 32 + brow) * 80 + kk * 32 + bcol * 16;
            uint32_t bh[4][2], bl[4][2];
#pragma unroll
            for (int p = 0; p < 2; ++p) {
                uint32_t rh[4], rl[4];
                ldsm4(rh, bb + p * 16 * 80);
                ldsm4(rl, bb + 10240 + p * 16 * 80);
                bh[2*p][0] = rh[0]; bh[2*p][1] = rh[1];
                bh[2*p+1][0] = rh[2]; bh[2*p+1][1] = rh[3];
                bl[2*p][0] = rl[0]; bl[2*p][1] = rl[1];
                bl[2*p+1][0] = rl[2]; bl[2*p+1][1] = rl[3];
            }
#pragma unroll
            for (int mt = 0; mt < 4; ++mt)
#pragma unroll
                for (int nt = 0; nt < 4; ++nt) {
                    mma16816(c[mt][nt], ah[mt], bh[nt]);
                    mma16816(c[mt][nt], ah[mt], bl[nt]);
                    mma16816(c[mt][nt], al[mt], bh[nt]);
                }
        }
        if (++sidx == 3) sidx = 0;
    }
    __syncthreads();

    // epilogue
#pragma unroll
    for (int mt = 0; mt < 4; ++mt)
#pragma unroll
        for (int nt = 0; nt < 4; ++nt) {
            int r  = m0 + wm * 64 + mt * 16 + (lane >> 2);
            int cl = n0 + wn * 32 + nt * 8 + ((lane & 3) << 1);
            float* d = c[mt][nt];
            if (EP == 0) {
                *(float2*)&of[(long long)r * ldo + cl]       = make_float2(d[0], d[1]);
                *(float2*)&of[(long long)(r + 8) * ldo + cl] = make_float2(d[2], d[3]);
            } else {
                float v0 = d[0], v1 = d[1], v2 = d[2], v3 = d[3];
                if (EP == 2) {
                    float b0v = bias[cl], b1v = bias[cl + 1];
                    v0 = gelu_f(v0 + b0v); v1 = gelu_f(v1 + b1v);
                    v2 = gelu_f(v2 + b0v); v3 = gelu_f(v3 + b1v);
                }
                uint32_t h01, l01, h23, l23;
                bsplit2(v0, v1, h01, l01);
                bsplit2(v2, v3, h23, l23);
                *(uint32_t*)&oh[(long long)r * ldo + cl]       = h01;
                *(uint32_t*)&ol[(long long)r * ldo + cl]       = l01;
                *(uint32_t*)&oh[(long long)(r + 8) * ldo + cl] = h23;
                *(uint32_t*)&ol[(long long)(r + 8) * ldo + cl] = l23;
            }
        }
}

// ---------------- elementwise / transforms -----------------------------------
__global__ void convsplit(const float* __restrict__ in, __nv_bfloat16* __restrict__ oh,
                          __nv_bfloat16* __restrict__ ol)
{
    int i = (blockIdx.x * 256 + threadIdx.x) * 4;
    float4 v = *(const float4*)(in + i);
    uint32_t h0, l0, h1, l1;
    bsplit2(v.x, v.y, h0, l0); bsplit2(v.z, v.w, h1, l1);
    *(uint2*)(oh + i) = make_uint2(h0, h1);
    *(uint2*)(ol + i) = make_uint2(l0, l1);
}

template<bool NORM>
__global__ void tsplit(const float* __restrict__ in, __nv_bfloat16* __restrict__ oh,
                       __nv_bfloat16* __restrict__ ol, int R, int C,
                       long long sIn, long long sOut,
                       const float* __restrict__ cm, const float* __restrict__ cs)
{
    __shared__ float tile[32][33];
    const int z = blockIdx.z;
    const int c0 = blockIdx.x * 32, r0 = blockIdx.y * 32;
    const int tx = threadIdx.x, ty = threadIdx.y;
    const float* ip = in + z * sIn;
    float nm = 0.f, ns = 1.f;
    if (NORM) { nm = cm[z * CC + c0 + tx]; ns = 1.f / cs[z * CC + c0 + tx]; }
#pragma unroll
    for (int i = 0; i < 4; ++i) {
        float v = ip[(long long)(r0 + ty + i * 8) * C + c0 + tx];
        if (NORM) v = expf(v - nm) * ns;
        tile[ty + i * 8][tx] = v;
    }
    __syncthreads();
#pragma unroll
    for (int i = 0; i < 4; ++i) {
        int cidx = c0 + ty + i * 8;
        float v = tile[tx][ty + i * 8];
        unsigned short h, l;
        bsplit(v, h, l);
        long long o = z * sOut + (long long)cidx * R + r0 + tx;
        oh[o] = __ushort_as_bfloat16(h);
        ol[o] = __ushort_as_bfloat16(l);
    }
}

__global__ void softmax_p1(const float* __restrict__ Kin, float* __restrict__ pm, float* __restrict__ ps)
{
    const int b = blockIdx.z, sp = blockIdx.y, c0 = blockIdx.x * 32;
    const int tx = threadIdx.x, ty = threadIdx.y;
    const float* kb = Kin + (long long)b * LSEQ * CC + c0 + tx;
    const int n0 = sp * 512;
    float m = -1e30f, s = 0.f;
    for (int l = ty; l < 512; l += 8) {
        float v = kb[(long long)(n0 + l) * CC];
        if (v > m) { s = s * expf(m - v) + 1.0f; m = v; }
        else       { s += expf(v - m); }
    }
    __shared__ float Ms[8][32], Ss[8][32];
    Ms[ty][tx] = m; Ss[ty][tx] = s;
    __syncthreads();
    if (ty == 0) {
#pragma unroll
        for (int r = 1; r < 8; ++r) {
            float m2 = Ms[r][tx], s2 = Ss[r][tx];
            float mm = fmaxf(m, m2);
            s = s * expf(m - mm) + s2 * expf(m2 - mm);
            m = mm;
        }
        pm[(sp * BATCH + b) * CC + c0 + tx] = m;
        ps[(sp * BATCH + b) * CC + c0 + tx] = s;
    }
}
__global__ void softmax_comb(const float* __restrict__ pm, const float* __restrict__ ps,
                             float* __restrict__ cm, float* __restrict__ cs)
{
    const int b = blockIdx.x, cch = threadIdx.x;
    float m = -1e30f, s = 0.f;
#pragma unroll
    for (int sp = 0; sp < 16; ++sp) {
        float m2 = pm[(sp * BATCH + b) * CC + cch], s2 = ps[(sp * BATCH + b) * CC + cch];
        float mm = fmaxf(m, m2);
        s = s * expf(m - mm) + s2 * expf(m2 - mm);
        m = mm;
    }
    cm[b * CC + cch] = m; cs[b * CC + cch] = s;
}

__global__ void reduce_split(const float* __restrict__ part, __nv_bfloat16* __restrict__ oh,
                             __nv_bfloat16* __restrict__ ol)
{
    int i = blockIdx.x * 256 + threadIdx.x;
    int b = i >> 16, w = i & 65535;
    float s = 0.f;
#pragma unroll
    for (int sp = 0; sp < NSPK; ++sp) s += part[(long long)(b * NSPK + sp) * 65536 + w];
    unsigned short h, l;
    bsplit(s, h, l);
    oh[i] = __ushort_as_bfloat16(h);
    ol[i] = __ushort_as_bfloat16(l);
}

// LN (optionally +bias pre, +residual post); OUT: 0 = hi/lo, 1 = f32
template<int OUT, bool PREB, bool RES>
__global__ void ln_k(const float* __restrict__ X, const float* __restrict__ preb,
                     const float* __restrict__ gamma, const float* __restrict__ beta,
                     const float* __restrict__ resid,
                     float* __restrict__ of, __nv_bfloat16* __restrict__ oh, __nv_bfloat16* __restrict__ ol)
{
    const int row = blockIdx.x, t = threadIdx.x;
    const long long base = (long long)row * CC;
    float x = X[base + t];
    if (PREB) x += preb[t];
    __shared__ float red[8];
    float s = x;
#pragma unroll
    for (int o = 16; o; o >>= 1) s += __shfl_xor_sync(0xffffffffu, s, o);
    if ((t & 31) == 0) red[t >> 5] = s;
    __syncthreads();
    float mu = 0.f;
#pragma unroll
    for (int i = 0; i < 8; ++i) mu += red[i];
    mu *= (1.f / 256.f);
    __syncthreads();
    float d = x - mu, q = d * d;
#pragma unroll
    for (int o = 16; o; o >>= 1) q += __shfl_xor_sync(0xffffffffu, q, o);
    if ((t & 31) == 0) red[t >> 5] = q;
    __syncthreads();
    float var = 0.f;
#pragma unroll
    for (int i = 0; i < 8; ++i) var += red[i];
    var *= (1.f / 256.f);
    float y = d * rsqrtf(var + 1e-5f) * gamma[t] + beta[t];
    if (RES) y += resid[base + t];
    if (OUT == 1) of[base + t] = y;
    else {
        unsigned short h, l;
        bsplit(y, h, l);
        oh[base + t] = __ushort_as_bfloat16(h);
        ol[base + t] = __ushort_as_bfloat16(l);
    }
}

// ---------------- launch ------------------------------------------------------
extern "C" void kernel_launch(void* const* d_in, const int* in_sizes, int n_in,
                              void* d_out, int out_size)
{
    const float* src = (const float*)d_in[0];
    const float* tgt = (const float*)d_in[1];
    const float* Wq  = (const float*)d_in[2];
    const float* Wk  = (const float*)d_in[3];
    const float* Wv  = (const float*)d_in[4];
    const float* Wl  = (const float*)d_in[5];
    const float* gamma1 = (const float*)d_in[6];
    const float* beta1  = (const float*)d_in[7];
    const float* W1  = (const float*)d_in[8];
    const float* b1  = (const float*)d_in[9];
    const float* W2  = (const float*)d_in[10];
    const float* b2  = (const float*)d_in[11];
    const float* gamma2 = (const float*)d_in[12];
    const float* beta2  = (const float*)d_in[13];
    float* out = (float*)d_out;

    cudaFuncSetAttribute(gemm_mma<0,false,false>, cudaFuncAttributeMaxDynamicSharedMemorySize, GSMEM);
    cudaFuncSetAttribute(gemm_mma<0,false,true>,  cudaFuncAttributeMaxDynamicSharedMemorySize, GSMEM);
    cudaFuncSetAttribute(gemm_mma<1,false,false>, cudaFuncAttributeMaxDynamicSharedMemorySize, GSMEM);
    cudaFuncSetAttribute(gemm_mma<2,true,false>,  cudaFuncAttributeMaxDynamicSharedMemorySize, GSMEM);

    #define SYM(v, s) cudaGetSymbolAddress((void**)&v, s)
    __nv_bfloat16 *srcH,*srcL,*tgtH,*tgtL,*qTh,*qTl,*kTh,*kTl,*vH,*vL,*atH,*atL,*l1H,*l1L;
    __nv_bfloat16 *hidH,*hidL,*cxH,*cxL,*WqH,*WqL,*WkH,*WkL,*WvH,*WvL,*WlH,*WlL,*W1H,*W1L,*W2H,*W2L;
    float *qf,*kf,*linf,*f2f,*cpart,*pm,*ps,*cm,*cs;
    SYM(srcH,g_srcH); SYM(srcL,g_srcL); SYM(tgtH,g_tgtH); SYM(tgtL,g_tgtL);
    SYM(qf,g_q); SYM(kf,g_k); SYM(linf,g_lin); SYM(f2f,g_f2);
    SYM(qTh,g_qTh); SYM(qTl,g_qTl); SYM(kTh,g_kTh); SYM(kTl,g_kTl);
    SYM(vH,g_vH); SYM(vL,g_vL); SYM(atH,g_atH); SYM(atL,g_atL);
    SYM(l1H,g_l1H); SYM(l1L,g_l1L); SYM(hidH,g_hidH); SYM(hidL,g_hidL);
    SYM(cxH,g_cxH); SYM(cxL,g_cxL); SYM(cpart,g_cpart);
    SYM(WqH,g_WqH); SYM(WqL,g_WqL); SYM(WkH,g_WkH); SYM(WkL,g_WkL);
    SYM(WvH,g_WvH); SYM(WvL,g_WvL); SYM(WlH,g_WlH); SYM(WlL,g_WlL);
    SYM(W1H,g_W1H); SYM(W1L,g_W1L); SYM(W2H,g_W2H); SYM(W2L,g_W2L);
    SYM(pm,g_pm); SYM(ps,g_ps); SYM(cm,g_cm); SYM(cs,g_cs);
    #undef SYM

    const dim3 tb(32, 8);

    // converts + weight transpose-splits (W [K][N] -> WT [N][K])
    convsplit<<<8192, 256>>>(src, srcH, srcL);
    convsplit<<<8192, 256>>>(tgt, tgtH, tgtL);
    tsplit<false><<<dim3(8, 8, 1),   tb>>>(Wq, WqH, WqL, 256, 256, 0, 0, nullptr, nullptr);
    tsplit<false><<<dim3(8, 8, 1),   tb>>>(Wk, WkH, WkL, 256, 256, 0, 0, nullptr, nullptr);
    tsplit<false><<<dim3(8, 8, 1),   tb>>>(Wv, WvH, WvL, 256, 256, 0, 0, nullptr, nullptr);
    tsplit<false><<<dim3(8, 8, 1),   tb>>>(Wl, WlH, WlL, 256, 256, 0, 0, nullptr, nullptr);
    tsplit<false><<<dim3(64, 16, 1), tb>>>(W1, W1H, W1L, 512, 2048, 0, 0, nullptr, nullptr);
    tsplit<false><<<dim3(8, 64, 1),  tb>>>(W2, W2H, W2L, 2048, 256, 0, 0, nullptr, nullptr);

    // q, k (f32), v (hi/lo)
    gemm_mma<0,false,false><<<dim3(2,256,1), 256, GSMEM>>>(srcH, srcL, nullptr, nullptr, 256,
        WqH, WqL, 256, nullptr, qf, nullptr, nullptr, 256, 256, 0, 0, 0, 0);
    gemm_mma<0,false,false><<<dim3(2,256,1), 256, GSMEM>>>(tgtH, tgtL, nullptr, nullptr, 256,
        WkH, WkL, 256, nullptr, kf, nullptr, nullptr, 256, 256, 0, 0, 0, 0);
    gemm_mma<1,false,false><<<dim3(2,256,1), 256, GSMEM>>>(tgtH, tgtL, nullptr, nullptr, 256,
        WvH, WvL, 256, nullptr, nullptr, vH, vL, 256, 256, 0, 0, 0, 0);

    // softmax over tokens; transpose+split k (normalized) and q -> [b][c][n]
    softmax_p1<<<dim3(8, 16, BATCH), tb>>>(kf, pm, ps);
    softmax_comb<<<BATCH, 256>>>(pm, ps, cm, cs);
    tsplit<true><<<dim3(8, 256, BATCH), tb>>>(kf, kTh, kTl, LSEQ, 256,
        (long long)LSEQ*CC, (long long)CC*LSEQ, cm, cs);
    tsplit<false><<<dim3(8, 256, BATCH), tb>>>(qf, qTh, qTl, LSEQ, 256,
        (long long)LSEQ*CC, (long long)CC*LSEQ, nullptr, nullptr);

    // ctx[d][e] = sum_n qT[d][n] * kT[e][n]  (split-K, f32 partials, det. reduce)
    gemm_mma<0,false,true><<<dim3(2, 2, BATCH*NSPK), 256, GSMEM>>>(qTh, qTl, nullptr, nullptr, LSEQ,
        kTh, kTl, LSEQ, nullptr, cpart, nullptr, nullptr, 256,
        LSEQ, (long long)CC*LSEQ, (long long)CC*LSEQ, 65536, LSEQ / NSPK);
    reduce_split<<<1024, 256>>>(cpart, cxH, cxL);

    // attn[n][d] = sum_e v[n][e] * ctx[d][e]
    gemm_mma<1,false,false><<<dim3(2, 64, BATCH), 256, GSMEM>>>(vH, vL, nullptr, nullptr, 256,
        cxH, cxL, 256, nullptr, nullptr, atH, atL, 256,
        256, (long long)LSEQ*CC, 65536, (long long)LSEQ*CC, 0);

    // message = LN(attn @ Wl)
    gemm_mma<0,false,false><<<dim3(2,256,1), 256, GSMEM>>>(atH, atL, nullptr, nullptr, 256,
        WlH, WlL, 256, nullptr, linf, nullptr, nullptr, 256, 256, 0, 0, 0, 0);
    ln_k<0,false,false><<<32768, 256>>>(linf, nullptr, gamma1, beta1, nullptr, nullptr, l1H, l1L);

    // hidden = gelu([src | msg] @ W1 + b1)
    gemm_mma<2,true,false><<<dim3(16,256,1), 256, GSMEM>>>(srcH, srcL, l1H, l1L, 256,
        W1H, W1L, 512, b1, nullptr, hidH, hidL, 2048, 512, 0, 0, 0, 0);

    // out = src + LN(hidden @ W2 + b2)
    gemm_mma<0,false,false><<<dim3(2,256,1), 256, GSMEM>>>(hidH, hidL, nullptr, nullptr, 2048,
        W2H, W2L, 2048, nullptr, f2f, nullptr, nullptr, 256, 2048, 0, 0, 0, 0);
    ln_k<1,true,true><<<32768, 256>>>(f2f, b2, gamma2, beta2, src, out, nullptr, nullptr);
}

// round 6
// speedup vs baseline: 2.8588x; 1.2094x over previous
#include <cuda_runtime.h>
#include <cuda_fp16.h>
#include <cstdint>
#include <math.h>

#define BATCH 4
#define LSEQ  8192
#define CC    256
#define BL    32768
#define HID   2048
#define NSPK  16
#define KSCALE 4096.0f

// ---------------- PTX helpers -----------------------------------------------
__device__ __forceinline__ uint32_t s2u(const void* p) {
    uint32_t a;
    asm("{ .reg .u64 t; cvta.to.shared.u64 t, %1; cvt.u32.u64 %0, t; }" : "=r"(a) : "l"(p));
    return a;
}
__device__ __forceinline__ void cpasync16(uint32_t s, const void* g) {
    asm volatile("cp.async.cg.shared.global [%0], [%1], 16;" :: "r"(s), "l"(g));
}
#define CP_COMMIT() asm volatile("cp.async.commit_group;" ::: "memory")
#define CP_WAIT1()  asm volatile("cp.async.wait_group 1;" ::: "memory")
__device__ __forceinline__ void ldsm4(uint32_t* r, uint32_t a) {
    asm volatile("ldmatrix.sync.aligned.m8n8.x4.shared.b16 {%0,%1,%2,%3}, [%4];"
        : "=r"(r[0]), "=r"(r[1]), "=r"(r[2]), "=r"(r[3]) : "r"(a));
}
__device__ __forceinline__ void mma16816(float* d, const uint32_t* a, const uint32_t* b) {
    asm volatile(
        "mma.sync.aligned.m16n8k16.row.col.f32.f16.f16.f32 "
        "{%0,%1,%2,%3}, {%4,%5,%6,%7}, {%8,%9}, {%0,%1,%2,%3};"
        : "+f"(d[0]), "+f"(d[1]), "+f"(d[2]), "+f"(d[3])
        : "r"(a[0]), "r"(a[1]), "r"(a[2]), "r"(a[3]), "r"(b[0]), "r"(b[1]));
}

// ---------------- scratch ----------------------------------------------------
__device__ __half g_srcH[BL*CC], g_srcL[BL*CC], g_tgtH[BL*CC], g_tgtL[BL*CC];
__device__ float  g_q[BL*CC], g_k[BL*CC], g_lin[BL*CC], g_f2[BL*CC];
__device__ __half g_qTh[BL*CC], g_qTl[BL*CC], g_kTh[BL*CC], g_kTl[BL*CC];
__device__ __half g_vH[BL*CC], g_vL[BL*CC], g_atH[BL*CC], g_atL[BL*CC];
__device__ __half g_l1H[BL*CC], g_l1L[BL*CC];
__device__ __half g_hidH[(long long)BL*HID], g_hidL[(long long)BL*HID];
__device__ __half g_cxH[BATCH*CC*CC], g_cxL[BATCH*CC*CC];
__device__ float  g_cpart[BATCH*NSPK*CC*CC];
__device__ __half g_WqH[CC*CC], g_WqL[CC*CC], g_WkH[CC*CC], g_WkL[CC*CC];
__device__ __half g_WvH[CC*CC], g_WvL[CC*CC], g_WlH[CC*CC], g_WlL[CC*CC];
__device__ __half g_W1H[HID*2*CC], g_W1L[HID*2*CC], g_W2H[CC*HID], g_W2L[CC*HID];
__device__ float g_pm[16*BATCH*CC], g_ps[16*BATCH*CC], g_cm[BATCH*CC], g_cs[BATCH*CC];

// ---------------- small utils -------------------------------------------------
__device__ __forceinline__ void hsplit(float x, unsigned short& h, unsigned short& l) {
    __half hh = __float2half_rn(x);
    __half hl = __float2half_rn(x - __half2float(hh));
    h = __half_as_ushort(hh); l = __half_as_ushort(hl);
}
__device__ __forceinline__ void hsplit2(float a, float b, uint32_t& h, uint32_t& l) {
    unsigned short h0, l0, h1, l1;
    hsplit(a, h0, l0); hsplit(b, h1, l1);
    h = (uint32_t)h0 | ((uint32_t)h1 << 16);
    l = (uint32_t)l0 | ((uint32_t)l1 << 16);
}
__device__ __forceinline__ float gelu_f(float x) {
    return 0.5f * x * (1.0f + erff(x * 0.70710678118654752f));
}

// ---------------- mma.sync GEMM ----------------------------------------------
// Tile M=128 N=128 Kchunk=32, 3-stage cp.async, 8 warps (2m x 4n), fp16 split.
// TERMS: 3 = AhBh + AlBh + AhBl (err ~2^-22); 2 = AhBh + AlBh (err = B rounding)
// EP: 0 = f32 out, 1 = hi/lo out, 2 = bias+gelu hi/lo out
static constexpr int STAGE = 40960;            // Ah|Al|Bh|Bl, each 128*80B
static constexpr int GSMEM = 3 * STAGE;

template<int EP, bool DUAL, bool SPLITK, int TERMS>
__global__ __launch_bounds__(256)
void gemm_mma(const __half* __restrict__ Ah, const __half* __restrict__ Al,
              const __half* __restrict__ A2h, const __half* __restrict__ A2l, int lda,
              const __half* __restrict__ Bh, const __half* __restrict__ Bl, int ldb,
              const float* __restrict__ bias,
              float* __restrict__ of, __half* __restrict__ oh, __half* __restrict__ ol,
              int ldo, int Ktot, long long sA, long long sB, long long sO, int kslen)
{
    extern __shared__ char smem[];
    const uint32_t sb = s2u(smem);
    const int tid = threadIdx.x, lane = tid & 31, wid = tid >> 5;
    const int wm = wid >> 2, wn = wid & 3;
    const int m0 = blockIdx.y * 128, n0 = blockIdx.x * 128, z = blockIdx.z;

    int kbase = 0, K = Ktot;
    long long ooff;
    if (SPLITK) {
        int b = z / NSPK, sp = z - b * NSPK;
        Ah += (long long)b * sA; Al += (long long)b * sA;
        Bh += (long long)b * sB; Bl += (long long)b * sB;
        kbase = sp * kslen; K = kslen;
        ooff = (long long)z * sO;
    } else {
        Ah += (long long)z * sA; Al += (long long)z * sA;
        Bh += (long long)z * sB; Bl += (long long)z * sB;
        ooff = (long long)z * sO;
    }
    if (of) of += ooff;
    if (oh) { oh += ooff; ol += ooff; }

    float c[4][4][4];
#pragma unroll
    for (int i = 0; i < 4; ++i)
#pragma unroll
        for (int j = 0; j < 4; ++j)
#pragma unroll
            for (int q = 0; q < 4; ++q) c[i][j][q] = 0.f;

    // loads: 3 tiles always (Ah,Al,Bh) + Bl only if TERMS==3
    auto LOADST = [&](int s, int kc) {
        uint32_t stb = sb + s * STAGE;
        const int NT = (TERMS == 3) ? 8 : 6;      // 512-thread-chunks of 16B
#pragma unroll
        for (int i = 0; i < NT; ++i) {
            int g = tid + i * 256;
            int tile = g >> 9, idx = g & 511;
            int row = idx >> 2, ch = idx & 3;
            uint32_t sa = stb + tile * 10240 + row * 80 + ch * 16;
            const __half* gp;
            if (tile < 2) {
                const __half* pa; int ka = kc;
                if (DUAL && kc >= 256) { pa = (tile == 0 ? A2h : A2l); ka = kc - 256; }
                else                   { pa = (tile == 0 ? Ah  : Al ); }
                gp = pa + (long long)(m0 + row) * lda + ka + ch * 8;
            } else {
                gp = (tile == 2 ? Bh : Bl) + (long long)(n0 + row) * ldb + kc + ch * 8;
            }
            cpasync16(sa, gp);
        }
    };

    const int nch = K >> 5;
    LOADST(0, kbase);
    CP_COMMIT();
    if (nch > 1) LOADST(1, kbase + 32);
    CP_COMMIT();

    int sidx = 0;
    for (int it = 0; it < nch; ++it) {
        CP_WAIT1();
        __syncthreads();
        if (it + 2 < nch) {
            int ns = sidx + 2; if (ns >= 3) ns -= 3;
            LOADST(ns, kbase + ((it + 2) << 5));
        }
        CP_COMMIT();

        uint32_t stb = sb + sidx * STAGE;
#pragma unroll
        for (int kk = 0; kk < 2; ++kk) {
            uint32_t ab = stb + (uint32_t)((lane & 15) + wm * 64) * 80 + ((lane >> 4) << 4) + kk * 32;
            uint32_t ah[4][4], al[4][4];
#pragma unroll
            for (int mt = 0; mt < 4; ++mt) {
                ldsm4(ah[mt], ab + mt * 16 * 80);
                ldsm4(al[mt], ab + 10240 + mt * 16 * 80);
            }
            int brow = (lane & 7) + ((lane >> 4) << 3);
            int bcol = (lane >> 3) & 1;
            uint32_t bb = stb + 20480 + (uint32_t)(wn * 32 + brow) * 80 + kk * 32 + bcol * 16;
            uint32_t bh[4][2], bl[4][2];
#pragma unroll
            for (int p = 0; p < 2; ++p) {
                uint32_t rh[4];
                ldsm4(rh, bb + p * 16 * 80);
                bh[2*p][0] = rh[0]; bh[2*p][1] = rh[1];
                bh[2*p+1][0] = rh[2]; bh[2*p+1][1] = rh[3];
                if (TERMS == 3) {
                    uint32_t rl[4];
                    ldsm4(rl, bb + 10240 + p * 16 * 80);
                    bl[2*p][0] = rl[0]; bl[2*p][1] = rl[1];
                    bl[2*p+1][0] = rl[2]; bl[2*p+1][1] = rl[3];
                }
            }
#pragma unroll
            for (int mt = 0; mt < 4; ++mt)
#pragma unroll
                for (int nt = 0; nt < 4; ++nt) {
                    mma16816(c[mt][nt], ah[mt], bh[nt]);
                    mma16816(c[mt][nt], al[mt], bh[nt]);
                    if (TERMS == 3) mma16816(c[mt][nt], ah[mt], bl[nt]);
                }
        }
        if (++sidx == 3) sidx = 0;
    }
    __syncthreads();

    // epilogue
#pragma unroll
    for (int mt = 0; mt < 4; ++mt)
#pragma unroll
        for (int nt = 0; nt < 4; ++nt) {
            int r  = m0 + wm * 64 + mt * 16 + (lane >> 2);
            int cl = n0 + wn * 32 + nt * 8 + ((lane & 3) << 1);
            float* d = c[mt][nt];
            if (EP == 0) {
                *(float2*)&of[(long long)r * ldo + cl]       = make_float2(d[0], d[1]);
                *(float2*)&of[(long long)(r + 8) * ldo + cl] = make_float2(d[2], d[3]);
            } else {
                float v0 = d[0], v1 = d[1], v2 = d[2], v3 = d[3];
                if (EP == 2) {
                    float b0v = bias[cl], b1v = bias[cl + 1];
                    v0 = gelu_f(v0 + b0v); v1 = gelu_f(v1 + b1v);
                    v2 = gelu_f(v2 + b0v); v3 = gelu_f(v3 + b1v);
                }
                uint32_t h01, l01, h23, l23;
                hsplit2(v0, v1, h01, l01);
                hsplit2(v2, v3, h23, l23);
                *(uint32_t*)&oh[(long long)r * ldo + cl]       = h01;
                *(uint32_t*)&ol[(long long)r * ldo + cl]       = l01;
                *(uint32_t*)&oh[(long long)(r + 8) * ldo + cl] = h23;
                *(uint32_t*)&ol[(long long)(r + 8) * ldo + cl] = l23;
            }
        }
}

// ---------------- elementwise / transforms -----------------------------------
__global__ void convsplit(const float* __restrict__ in, __half* __restrict__ oh,
                          __half* __restrict__ ol)
{
    int i = (blockIdx.x * 256 + threadIdx.x) * 4;
    float4 v = *(const float4*)(in + i);
    uint32_t h0, l0, h1, l1;
    hsplit2(v.x, v.y, h0, l0); hsplit2(v.z, v.w, h1, l1);
    *(uint2*)(oh + i) = make_uint2(h0, h1);
    *(uint2*)(ol + i) = make_uint2(l0, l1);
}

template<bool NORM>
__global__ void tsplit(const float* __restrict__ in, __half* __restrict__ oh,
                       __half* __restrict__ ol, int R, int C,
                       long long sIn, long long sOut,
                       const float* __restrict__ cm, const float* __restrict__ cs)
{
    __shared__ float tile[32][33];
    const int z = blockIdx.z;
    const int c0 = blockIdx.x * 32, r0 = blockIdx.y * 32;
    const int tx = threadIdx.x, ty = threadIdx.y;
    const float* ip = in + z * sIn;
    float nm = 0.f, ns = 1.f;
    if (NORM) { nm = cm[z * CC + c0 + tx]; ns = KSCALE / cs[z * CC + c0 + tx]; }
#pragma unroll
    for (int i = 0; i < 4; ++i) {
        float v = ip[(long long)(r0 + ty + i * 8) * C + c0 + tx];
        if (NORM) v = expf(v - nm) * ns;
        tile[ty + i * 8][tx] = v;
    }
    __syncthreads();
#pragma unroll
    for (int i = 0; i < 4; ++i) {
        int cidx = c0 + ty + i * 8;
        float v = tile[tx][ty + i * 8];
        unsigned short h, l;
        hsplit(v, h, l);
        long long o = z * sOut + (long long)cidx * R + r0 + tx;
        oh[o] = __ushort_as_half(h);
        ol[o] = __ushort_as_half(l);
    }
}

__global__ void softmax_p1(const float* __restrict__ Kin, float* __restrict__ pm, float* __restrict__ ps)
{
    const int b = blockIdx.z, sp = blockIdx.y, c0 = blockIdx.x * 32;
    const int tx = threadIdx.x, ty = threadIdx.y;
    const float* kb = Kin + (long long)b * LSEQ * CC + c0 + tx;
    const int n0 = sp * 512;
    float m = -1e30f, s = 0.f;
    for (int l = ty; l < 512; l += 8) {
        float v = kb[(long long)(n0 + l) * CC];
        if (v > m) { s = s * expf(m - v) + 1.0f; m = v; }
        else       { s += expf(v - m); }
    }
    __shared__ float Ms[8][32], Ss[8][32];
    Ms[ty][tx] = m; Ss[ty][tx] = s;
    __syncthreads();
    if (ty == 0) {
#pragma unroll
        for (int r = 1; r < 8; ++r) {
            float m2 = Ms[r][tx], s2 = Ss[r][tx];
            float mm = fmaxf(m, m2);
            s = s * expf(m - mm) + s2 * expf(m2 - mm);
            m = mm;
        }
        pm[(sp * BATCH + b) * CC + c0 + tx] = m;
        ps[(sp * BATCH + b) * CC + c0 + tx] = s;
    }
}
__global__ void softmax_comb(const float* __restrict__ pm, const float* __restrict__ ps,
                             float* __restrict__ cm, float* __restrict__ cs)
{
    const int b = blockIdx.x, cch = threadIdx.x;
    float m = -1e30f, s = 0.f;
#pragma unroll
    for (int sp = 0; sp < 16; ++sp) {
        float m2 = pm[(sp * BATCH + b) * CC + cch], s2 = ps[(sp * BATCH + b) * CC + cch];
        float mm = fmaxf(m, m2);
        s = s * expf(m - mm) + s2 * expf(m2 - mm);
        m = mm;
    }
    cm[b * CC + cch] = m; cs[b * CC + cch] = s;
}

__global__ void reduce_split(const float* __restrict__ part, __half* __restrict__ oh,
                             __half* __restrict__ ol)
{
    int i = blockIdx.x * 256 + threadIdx.x;
    int b = i >> 16, w = i & 65535;
    float s = 0.f;
#pragma unroll
    for (int sp = 0; sp < NSPK; ++sp) s += part[(long long)(b * NSPK + sp) * 65536 + w];
    s *= (1.0f / KSCALE);
    unsigned short h, l;
    hsplit(s, h, l);
    oh[i] = __ushort_as_half(h);
    ol[i] = __ushort_as_half(l);
}

// LN (optionally +bias pre, +residual post); OUT: 0 = hi/lo, 1 = f32
template<int OUT, bool PREB, bool RES>
__global__ void ln_k(const float* __restrict__ X, const float* __restrict__ preb,
                     const float* __restrict__ gamma, const float* __restrict__ beta,
                     const float* __restrict__ resid,
                     float* __restrict__ of, __half* __restrict__ oh, __half* __restrict__ ol)
{
    const int row = blockIdx.x, t = threadIdx.x;
    const long long base = (long long)row * CC;
    float x = X[base + t];
    if (PREB) x += preb[t];
    __shared__ float red[8];
    float s = x;
#pragma unroll
    for (int o = 16; o; o >>= 1) s += __shfl_xor_sync(0xffffffffu, s, o);
    if ((t & 31) == 0) red[t >> 5] = s;
    __syncthreads();
    float mu = 0.f;
#pragma unroll
    for (int i = 0; i < 8; ++i) mu += red[i];
    mu *= (1.f / 256.f);
    __syncthreads();
    float d = x - mu, q = d * d;
#pragma unroll
    for (int o = 16; o; o >>= 1) q += __shfl_xor_sync(0xffffffffu, q, o);
    if ((t & 31) == 0) red[t >> 5] = q;
    __syncthreads();
    float var = 0.f;
#pragma unroll
    for (int i = 0; i < 8; ++i) var += red[i];
    var *= (1.f / 256.f);
    float y = d * rsqrtf(var + 1e-5f) * gamma[t] + beta[t];
    if (RES) y += resid[base + t];
    if (OUT == 1) of[base + t] = y;
    else {
        unsigned short h, l;
        hsplit(y, h, l);
        oh[base + t] = __ushort_as_half(h);
        ol[base + t] = __ushort_as_half(l);
    }
}

// ---------------- launch ------------------------------------------------------
extern "C" void kernel_launch(void* const* d_in, const int* in_sizes, int n_in,
                              void* d_out, int out_size)
{
    const float* src = (const float*)d_in[0];
    const float* tgt = (const float*)d_in[1];
    const float* Wq  = (const float*)d_in[2];
    const float* Wk  = (const float*)d_in[3];
    const float* Wv  = (const float*)d_in[4];
    const float* Wl  = (const float*)d_in[5];
    const float* gamma1 = (const float*)d_in[6];
    const float* beta1  = (const float*)d_in[7];
    const float* W1  = (const float*)d_in[8];
    const float* b1  = (const float*)d_in[9];
    const float* W2  = (const float*)d_in[10];
    const float* b2  = (const float*)d_in[11];
    const float* gamma2 = (const float*)d_in[12];
    const float* beta2  = (const float*)d_in[13];
    float* out = (float*)d_out;

    cudaFuncSetAttribute(gemm_mma<0,false,false,3>, cudaFuncAttributeMaxDynamicSharedMemorySize, GSMEM);
    cudaFuncSetAttribute(gemm_mma<1,false,false,3>, cudaFuncAttributeMaxDynamicSharedMemorySize, GSMEM);
    cudaFuncSetAttribute(gemm_mma<0,false,true,3>,  cudaFuncAttributeMaxDynamicSharedMemorySize, GSMEM);
    cudaFuncSetAttribute(gemm_mma<2,true,false,2>,  cudaFuncAttributeMaxDynamicSharedMemorySize, GSMEM);
    cudaFuncSetAttribute(gemm_mma<0,false,false,2>, cudaFuncAttributeMaxDynamicSharedMemorySize, GSMEM);

    #define SYM(v, s) cudaGetSymbolAddress((void**)&v, s)
    __half *srcH,*srcL,*tgtH,*tgtL,*qTh,*qTl,*kTh,*kTl,*vH,*vL,*atH,*atL,*l1H,*l1L;
    __half *hidH,*hidL,*cxH,*cxL,*WqH,*WqL,*WkH,*WkL,*WvH,*WvL,*WlH,*WlL,*W1H,*W1L,*W2H,*W2L;
    float *qf,*kf,*linf,*f2f,*cpart,*pm,*ps,*cm,*cs;
    SYM(srcH,g_srcH); SYM(srcL,g_srcL); SYM(tgtH,g_tgtH); SYM(tgtL,g_tgtL);
    SYM(qf,g_q); SYM(kf,g_k); SYM(linf,g_lin); SYM(f2f,g_f2);
    SYM(qTh,g_qTh); SYM(qTl,g_qTl); SYM(kTh,g_kTh); SYM(kTl,g_kTl);
    SYM(vH,g_vH); SYM(vL,g_vL); SYM(atH,g_atH); SYM(atL,g_atL);
    SYM(l1H,g_l1H); SYM(l1L,g_l1L); SYM(hidH,g_hidH); SYM(hidL,g_hidL);
    SYM(cxH,g_cxH); SYM(cxL,g_cxL); SYM(cpart,g_cpart);
    SYM(WqH,g_WqH); SYM(WqL,g_WqL); SYM(WkH,g_WkH); SYM(WkL,g_WkL);
    SYM(WvH,g_WvH); SYM(WvL,g_WvL); SYM(WlH,g_WlH); SYM(WlL,g_WlL);
    SYM(W1H,g_W1H); SYM(W1L,g_W1L); SYM(W2H,g_W2H); SYM(W2L,g_W2L);
    SYM(pm,g_pm); SYM(ps,g_ps); SYM(cm,g_cm); SYM(cs,g_cs);
    #undef SYM

    const dim3 tb(32, 8);

    // converts + weight transpose-splits (W [K][N] -> WT [N][K])
    convsplit<<<8192, 256>>>(src, srcH, srcL);
    convsplit<<<8192, 256>>>(tgt, tgtH, tgtL);
    tsplit<false><<<dim3(8, 8, 1),   tb>>>(Wq, WqH, WqL, 256, 256, 0, 0, nullptr, nullptr);
    tsplit<false><<<dim3(8, 8, 1),   tb>>>(Wk, WkH, WkL, 256, 256, 0, 0, nullptr, nullptr);
    tsplit<false><<<dim3(8, 8, 1),   tb>>>(Wv, WvH, WvL, 256, 256, 0, 0, nullptr, nullptr);
    tsplit<false><<<dim3(8, 8, 1),   tb>>>(Wl, WlH, WlL, 256, 256, 0, 0, nullptr, nullptr);
    tsplit<false><<<dim3(64, 16, 1), tb>>>(W1, W1H, W1L, 512, 2048, 0, 0, nullptr, nullptr);
    tsplit<false><<<dim3(8, 64, 1),  tb>>>(W2, W2H, W2L, 2048, 256, 0, 0, nullptr, nullptr);

    // q, k (f32), v (hi/lo)   [3-term]
    gemm_mma<0,false,false,3><<<dim3(2,256,1), 256, GSMEM>>>(srcH, srcL, nullptr, nullptr, 256,
        WqH, WqL, 256, nullptr, qf, nullptr, nullptr, 256, 256, 0, 0, 0, 0);
    gemm_mma<0,false,false,3><<<dim3(2,256,1), 256, GSMEM>>>(tgtH, tgtL, nullptr, nullptr, 256,
        WkH, WkL, 256, nullptr, kf, nullptr, nullptr, 256, 256, 0, 0, 0, 0);
    gemm_mma<1,false,false,3><<<dim3(2,256,1), 256, GSMEM>>>(tgtH, tgtL, nullptr, nullptr, 256,
        WvH, WvL, 256, nullptr, nullptr, vH, vL, 256, 256, 0, 0, 0, 0);

    // softmax over tokens; transpose+split k (normalized, x4096) and q
    softmax_p1<<<dim3(8, 16, BATCH), tb>>>(kf, pm, ps);
    softmax_comb<<<BATCH, 256>>>(pm, ps, cm, cs);
    tsplit<true><<<dim3(8, 256, BATCH), tb>>>(kf, kTh, kTl, LSEQ, 256,
        (long long)LSEQ*CC, (long long)CC*LSEQ, cm, cs);
    tsplit<false><<<dim3(8, 256, BATCH), tb>>>(qf, qTh, qTl, LSEQ, 256,
        (long long)LSEQ*CC, (long long)CC*LSEQ, nullptr, nullptr);

    // ctx[d][e] = sum_n qT[d][n] * kT[e][n]  (split-K, f32 partials)  [3-term]
    gemm_mma<0,false,true,3><<<dim3(2, 2, BATCH*NSPK), 256, GSMEM>>>(qTh, qTl, nullptr, nullptr, LSEQ,
        kTh, kTl, LSEQ, nullptr, cpart, nullptr, nullptr, 256,
        LSEQ, (long long)CC*LSEQ, (long long)CC*LSEQ, 65536, LSEQ / NSPK);
    reduce_split<<<1024, 256>>>(cpart, cxH, cxL);

    // attn[n][d] = sum_e v[n][e] * ctx[d][e]  [3-term]
    gemm_mma<1,false,false,3><<<dim3(2, 64, BATCH), 256, GSMEM>>>(vH, vL, nullptr, nullptr, 256,
        cxH, cxL, 256, nullptr, nullptr, atH, atL, 256,
        256, (long long)LSEQ*CC, 65536, (long long)LSEQ*CC, 0);

    // message = LN(attn @ Wl)  [3-term]
    gemm_mma<0,false,false,3><<<dim3(2,256,1), 256, GSMEM>>>(atH, atL, nullptr, nullptr, 256,
        WlH, WlL, 256, nullptr, linf, nullptr, nullptr, 256, 256, 0, 0, 0, 0);
    ln_k<0,false,false><<<32768, 256>>>(linf, nullptr, gamma1, beta1, nullptr, nullptr, l1H, l1L);

    // hidden = gelu([src | msg] @ W1 + b1)  [2-term]
    gemm_mma<2,true,false,2><<<dim3(16,256,1), 256, GSMEM>>>(srcH, srcL, l1H, l1L, 256,
        W1H, W1L, 512, b1, nullptr, hidH, hidL, 2048, 512, 0, 0, 0, 0);

    // out = src + LN(hidden @ W2 + b2)  [2-term]
    gemm_mma<0,false,false,2><<<dim3(2,256,1), 256, GSMEM>>>(hidH, hidL, nullptr, nullptr, 2048,
        W2H, W2L, 2048, nullptr, f2f, nullptr, nullptr, 256, 2048, 0, 0, 0, 0);
    ln_k<1,true,true><<<32768, 256>>>(f2f, b2, gamma2, beta2, src, out, nullptr, nullptr);
}

// round 7
// speedup vs baseline: 3.4740x; 1.2152x over previous
#include <cuda_runtime.h>
#include <cuda_fp16.h>
#include <cstdint>
#include <math.h>

#define BATCH 4
#define LSEQ  8192
#define CC    256
#define BL    32768
#define HID   2048
#define NSPK  16
#define KSCALE 4096.0f

// ---------------- PTX helpers -----------------------------------------------
__device__ __forceinline__ uint32_t s2u(const void* p) {
    uint32_t a;
    asm("{ .reg .u64 t; cvta.to.shared.u64 t, %1; cvt.u32.u64 %0, t; }" : "=r"(a) : "l"(p));
    return a;
}
__device__ __forceinline__ void cpasync16(uint32_t s, const void* g) {
    asm volatile("cp.async.cg.shared.global [%0], [%1], 16;" :: "r"(s), "l"(g));
}
#define CP_COMMIT() asm volatile("cp.async.commit_group;" ::: "memory")
#define CP_WAIT1()  asm volatile("cp.async.wait_group 1;" ::: "memory")
__device__ __forceinline__ void ldsm4(uint32_t* r, uint32_t a) {
    asm volatile("ldmatrix.sync.aligned.m8n8.x4.shared.b16 {%0,%1,%2,%3}, [%4];"
        : "=r"(r[0]), "=r"(r[1]), "=r"(r[2]), "=r"(r[3]) : "r"(a));
}
__device__ __forceinline__ void mma16816(float* d, const uint32_t* a, const uint32_t* b) {
    asm volatile(
        "mma.sync.aligned.m16n8k16.row.col.f32.f16.f16.f32 "
        "{%0,%1,%2,%3}, {%4,%5,%6,%7}, {%8,%9}, {%0,%1,%2,%3};"
        : "+f"(d[0]), "+f"(d[1]), "+f"(d[2]), "+f"(d[3])
        : "r"(a[0]), "r"(a[1]), "r"(a[2]), "r"(a[3]), "r"(b[0]), "r"(b[1]));
}

// ---------------- scratch ----------------------------------------------------
__device__ __half g_srcH[BL*CC], g_srcL[BL*CC], g_tgtH[BL*CC], g_tgtL[BL*CC];
__device__ float  g_q[BL*CC], g_k[BL*CC], g_lin[BL*CC], g_f2[BL*CC];
__device__ __half g_qTh[BL*CC], g_qTl[BL*CC], g_kTh[BL*CC], g_kTl[BL*CC];
__device__ __half g_vH[BL*CC], g_vL[BL*CC], g_atH[BL*CC], g_atL[BL*CC];
__device__ __half g_l1H[BL*CC], g_l1L[BL*CC];
__device__ __half g_hidH[(long long)BL*HID], g_hidL[(long long)BL*HID];
__device__ __half g_cxH[BATCH*CC*CC], g_cxL[BATCH*CC*CC];
__device__ float  g_cpart[BATCH*NSPK*CC*CC];
__device__ __half g_WqH[CC*CC], g_WqL[CC*CC], g_WkH[CC*CC], g_WkL[CC*CC];
__device__ __half g_WvH[CC*CC], g_WvL[CC*CC], g_WlH[CC*CC], g_WlL[CC*CC];
__device__ __half g_W1H[HID*2*CC], g_W1L[HID*2*CC], g_W2H[CC*HID], g_W2L[CC*HID];
__device__ float g_pm[16*BATCH*CC], g_ps[16*BATCH*CC], g_cm[BATCH*CC], g_cs[BATCH*CC];

// ---------------- small utils -------------------------------------------------
__device__ __forceinline__ void hsplit(float x, unsigned short& h, unsigned short& l) {
    __half hh = __float2half_rn(x);
    __half hl = __float2half_rn(x - __half2float(hh));
    h = __half_as_ushort(hh); l = __half_as_ushort(hl);
}
__device__ __forceinline__ void hsplit2(float a, float b, uint32_t& h, uint32_t& l) {
    unsigned short h0, l0, h1, l1;
    hsplit(a, h0, l0); hsplit(b, h1, l1);
    h = (uint32_t)h0 | ((uint32_t)h1 << 16);
    l = (uint32_t)l0 | ((uint32_t)l1 << 16);
}
__device__ __forceinline__ float gelu_f(float x) {
    return 0.5f * x * (1.0f + erff(x * 0.70710678118654752f));
}

// ---------------- mma.sync GEMM ----------------------------------------------
// Tile M=128 N=128 Kchunk=32, 3-stage cp.async, 8 warps (2m x 4n), fp16 split.
// 2-term: D = Ah*Bh + Al*Bh  (A exact as hi+lo pair, B rounded to fp16)
// EP: 0 = f32 out, 1 = hi/lo out, 2 = bias+gelu hi/lo out
static constexpr int STAGE = 30720;            // Ah|Al|Bh, each 128*80B
static constexpr int GSMEM = 3 * STAGE;

template<int EP, bool DUAL, bool SPLITK>
__global__ __launch_bounds__(256)
void gemm_mma(const __half* __restrict__ Ah, const __half* __restrict__ Al,
              const __half* __restrict__ A2h, const __half* __restrict__ A2l, int lda,
              const __half* __restrict__ Bh, int ldb,
              const float* __restrict__ bias,
              float* __restrict__ of, __half* __restrict__ oh, __half* __restrict__ ol,
              int ldo, int Ktot, long long sA, long long sB, long long sO, int kslen)
{
    extern __shared__ char smem[];
    const uint32_t sb = s2u(smem);
    const int tid = threadIdx.x, lane = tid & 31, wid = tid >> 5;
    const int wm = wid >> 2, wn = wid & 3;
    const int m0 = blockIdx.y * 128, n0 = blockIdx.x * 128, z = blockIdx.z;

    int kbase = 0, K = Ktot;
    long long ooff;
    if (SPLITK) {
        int b = z / NSPK, sp = z - b * NSPK;
        Ah += (long long)b * sA; Al += (long long)b * sA;
        Bh += (long long)b * sB;
        kbase = sp * kslen; K = kslen;
        ooff = (long long)z * sO;
    } else {
        Ah += (long long)z * sA; Al += (long long)z * sA;
        Bh += (long long)z * sB;
        ooff = (long long)z * sO;
    }
    if (of) of += ooff;
    if (oh) { oh += ooff; ol += ooff; }

    float c[4][4][4];
#pragma unroll
    for (int i = 0; i < 4; ++i)
#pragma unroll
        for (int j = 0; j < 4; ++j)
#pragma unroll
            for (int q = 0; q < 4; ++q) c[i][j][q] = 0.f;

    auto LOADST = [&](int s, int kc) {
        uint32_t stb = sb + s * STAGE;
#pragma unroll
        for (int i = 0; i < 6; ++i) {            // 3 tiles x 512 chunks of 16B
            int g = tid + i * 256;
            int tile = g >> 9, idx = g & 511;
            int row = idx >> 2, ch = idx & 3;
            uint32_t sa = stb + tile * 10240 + row * 80 + ch * 16;
            const __half* gp;
            if (tile < 2) {
                const __half* pa; int ka = kc;
                if (DUAL && kc >= 256) { pa = (tile == 0 ? A2h : A2l); ka = kc - 256; }
                else                   { pa = (tile == 0 ? Ah  : Al ); }
                gp = pa + (long long)(m0 + row) * lda + ka + ch * 8;
            } else {
                gp = Bh + (long long)(n0 + row) * ldb + kc + ch * 8;
            }
            cpasync16(sa, gp);
        }
    };

    const int nch = K >> 5;
    LOADST(0, kbase);
    CP_COMMIT();
    if (nch > 1) LOADST(1, kbase + 32);
    CP_COMMIT();

    int sidx = 0;
    for (int it = 0; it < nch; ++it) {
        CP_WAIT1();
        __syncthreads();
        if (it + 2 < nch) {
            int ns = sidx + 2; if (ns >= 3) ns -= 3;
            LOADST(ns, kbase + ((it + 2) << 5));
        }
        CP_COMMIT();

        uint32_t stb = sb + sidx * STAGE;
#pragma unroll
        for (int kk = 0; kk < 2; ++kk) {
            uint32_t ab = stb + (uint32_t)((lane & 15) + wm * 64) * 80 + ((lane >> 4) << 4) + kk * 32;
            uint32_t ah[4][4], al[4][4];
#pragma unroll
            for (int mt = 0; mt < 4; ++mt) {
                ldsm4(ah[mt], ab + mt * 16 * 80);
                ldsm4(al[mt], ab + 10240 + mt * 16 * 80);
            }
            int brow = (lane & 7) + ((lane >> 4) << 3);
            int bcol = (lane >> 3) & 1;
            uint32_t bb = stb + 20480 + (uint32_t)(wn * 32 + brow) * 80 + kk * 32 + bcol * 16;
            uint32_t bh[4][2];
#pragma unroll
            for (int p = 0; p < 2; ++p) {
                uint32_t rh[4];
                ldsm4(rh, bb + p * 16 * 80);
                bh[2*p][0] = rh[0]; bh[2*p][1] = rh[1];
                bh[2*p+1][0] = rh[2]; bh[2*p+1][1] = rh[3];
            }
#pragma unroll
            for (int mt = 0; mt < 4; ++mt)
#pragma unroll
                for (int nt = 0; nt < 4; ++nt) {
                    mma16816(c[mt][nt], ah[mt], bh[nt]);
                    mma16816(c[mt][nt], al[mt], bh[nt]);
                }
        }
        if (++sidx == 3) sidx = 0;
    }
    __syncthreads();

    // epilogue
#pragma unroll
    for (int mt = 0; mt < 4; ++mt)
#pragma unroll
        for (int nt = 0; nt < 4; ++nt) {
            int r  = m0 + wm * 64 + mt * 16 + (lane >> 2);
            int cl = n0 + wn * 32 + nt * 8 + ((lane & 3) << 1);
            float* d = c[mt][nt];
            if (EP == 0) {
                *(float2*)&of[(long long)r * ldo + cl]       = make_float2(d[0], d[1]);
                *(float2*)&of[(long long)(r + 8) * ldo + cl] = make_float2(d[2], d[3]);
            } else {
                float v0 = d[0], v1 = d[1], v2 = d[2], v3 = d[3];
                if (EP == 2) {
                    float b0v = bias[cl], b1v = bias[cl + 1];
                    v0 = gelu_f(v0 + b0v); v1 = gelu_f(v1 + b1v);
                    v2 = gelu_f(v2 + b0v); v3 = gelu_f(v3 + b1v);
                }
                uint32_t h01, l01, h23, l23;
                hsplit2(v0, v1, h01, l01);
                hsplit2(v2, v3, h23, l23);
                *(uint32_t*)&oh[(long long)r * ldo + cl]       = h01;
                *(uint32_t*)&ol[(long long)r * ldo + cl]       = l01;
                *(uint32_t*)&oh[(long long)(r + 8) * ldo + cl] = h23;
                *(uint32_t*)&ol[(long long)(r + 8) * ldo + cl] = l23;
            }
        }
}

// ---------------- elementwise / transforms -----------------------------------
__global__ void convsplit(const float* __restrict__ in, __half* __restrict__ oh,
                          __half* __restrict__ ol)
{
    int i = (blockIdx.x * 256 + threadIdx.x) * 4;
    float4 v = *(const float4*)(in + i);
    uint32_t h0, l0, h1, l1;
    hsplit2(v.x, v.y, h0, l0); hsplit2(v.z, v.w, h1, l1);
    *(uint2*)(oh + i) = make_uint2(h0, h1);
    *(uint2*)(ol + i) = make_uint2(l0, l1);
}

template<bool NORM>
__global__ void tsplit(const float* __restrict__ in, __half* __restrict__ oh,
                       __half* __restrict__ ol, int R, int C,
                       long long sIn, long long sOut,
                       const float* __restrict__ cm, const float* __restrict__ cs)
{
    __shared__ float tile[32][33];
    const int z = blockIdx.z;
    const int c0 = blockIdx.x * 32, r0 = blockIdx.y * 32;
    const int tx = threadIdx.x, ty = threadIdx.y;
    const float* ip = in + z * sIn;
    float nm = 0.f, ns = 1.f;
    if (NORM) { nm = cm[z * CC + c0 + tx]; ns = KSCALE / cs[z * CC + c0 + tx]; }
#pragma unroll
    for (int i = 0; i < 4; ++i) {
        float v = ip[(long long)(r0 + ty + i * 8) * C + c0 + tx];
        if (NORM) v = expf(v - nm) * ns;
        tile[ty + i * 8][tx] = v;
    }
    __syncthreads();
#pragma unroll
    for (int i = 0; i < 4; ++i) {
        int cidx = c0 + ty + i * 8;
        float v = tile[tx][ty + i * 8];
        unsigned short h, l;
        hsplit(v, h, l);
        long long o = z * sOut + (long long)cidx * R + r0 + tx;
        oh[o] = __ushort_as_half(h);
        ol[o] = __ushort_as_half(l);
    }
}

__global__ void softmax_p1(const float* __restrict__ Kin, float* __restrict__ pm, float* __restrict__ ps)
{
    const int b = blockIdx.z, sp = blockIdx.y, c0 = blockIdx.x * 32;
    const int tx = threadIdx.x, ty = threadIdx.y;
    const float* kb = Kin + (long long)b * LSEQ * CC + c0 + tx;
    const int n0 = sp * 512;
    float m = -1e30f, s = 0.f;
    for (int l = ty; l < 512; l += 8) {
        float v = kb[(long long)(n0 + l) * CC];
        if (v > m) { s = s * expf(m - v) + 1.0f; m = v; }
        else       { s += expf(v - m); }
    }
    __shared__ float Ms[8][32], Ss[8][32];
    Ms[ty][tx] = m; Ss[ty][tx] = s;
    __syncthreads();
    if (ty == 0) {
#pragma unroll
        for (int r = 1; r < 8; ++r) {
            float m2 = Ms[r][tx], s2 = Ss[r][tx];
            float mm = fmaxf(m, m2);
            s = s * expf(m - mm) + s2 * expf(m2 - mm);
            m = mm;
        }
        pm[(sp * BATCH + b) * CC + c0 + tx] = m;
        ps[(sp * BATCH + b) * CC + c0 + tx] = s;
    }
}
__global__ void softmax_comb(const float* __restrict__ pm, const float* __restrict__ ps,
                             float* __restrict__ cm, float* __restrict__ cs)
{
    const int b = blockIdx.x, cch = threadIdx.x;
    float m = -1e30f, s = 0.f;
#pragma unroll
    for (int sp = 0; sp < 16; ++sp) {
        float m2 = pm[(sp * BATCH + b) * CC + cch], s2 = ps[(sp * BATCH + b) * CC + cch];
        float mm = fmaxf(m, m2);
        s = s * expf(m - mm) + s2 * expf(m2 - mm);
        m = mm;
    }
    cm[b * CC + cch] = m; cs[b * CC + cch] = s;
}

__global__ void reduce_split(const float* __restrict__ part, __half* __restrict__ oh,
                             __half* __restrict__ ol)
{
    int i = blockIdx.x * 256 + threadIdx.x;
    int b = i >> 16, w = i & 65535;
    float s = 0.f;
#pragma unroll
    for (int sp = 0; sp < NSPK; ++sp) s += part[(long long)(b * NSPK + sp) * 65536 + w];
    s *= (1.0f / KSCALE);
    unsigned short h, l;
    hsplit(s, h, l);
    oh[i] = __ushort_as_half(h);
    ol[i] = __ushort_as_half(l);
}

// LN (optionally +bias pre, +residual post); OUT: 0 = hi/lo, 1 = f32
template<int OUT, bool PREB, bool RES>
__global__ void ln_k(const float* __restrict__ X, const float* __restrict__ preb,
                     const float* __restrict__ gamma, const float* __restrict__ beta,
                     const float* __restrict__ resid,
                     float* __restrict__ of, __half* __restrict__ oh, __half* __restrict__ ol)
{
    const int row = blockIdx.x, t = threadIdx.x;
    const long long base = (long long)row * CC;
    float x = X[base + t];
    if (PREB) x += preb[t];
    __shared__ float red[8];
    float s = x;
#pragma unroll
    for (int o = 16; o; o >>= 1) s += __shfl_xor_sync(0xffffffffu, s, o);
    if ((t & 31) == 0) red[t >> 5] = s;
    __syncthreads();
    float mu = 0.f;
#pragma unroll
    for (int i = 0; i < 8; ++i) mu += red[i];
    mu *= (1.f / 256.f);
    __syncthreads();
    float d = x - mu, q = d * d;
#pragma unroll
    for (int o = 16; o; o >>= 1) q += __shfl_xor_sync(0xffffffffu, q, o);
    if ((t & 31) == 0) red[t >> 5] = q;
    __syncthreads();
    float var = 0.f;
#pragma unroll
    for (int i = 0; i < 8; ++i) var += red[i];
    var *= (1.f / 256.f);
    float y = d * rsqrtf(var + 1e-5f) * gamma[t] + beta[t];
    if (RES) y += resid[base + t];
    if (OUT == 1) of[base + t] = y;
    else {
        unsigned short h, l;
        hsplit(y, h, l);
        oh[base + t] = __ushort_as_half(h);
        ol[base + t] = __ushort_as_half(l);
    }
}

// ---------------- launch ------------------------------------------------------
extern "C" void kernel_launch(void* const* d_in, const int* in_sizes, int n_in,
                              void* d_out, int out_size)
{
    const float* src = (const float*)d_in[0];
    const float* tgt = (const float*)d_in[1];
    const float* Wq  = (const float*)d_in[2];
    const float* Wk  = (const float*)d_in[3];
    const float* Wv  = (const float*)d_in[4];
    const float* Wl  = (const float*)d_in[5];
    const float* gamma1 = (const float*)d_in[6];
    const float* beta1  = (const float*)d_in[7];
    const float* W1  = (const float*)d_in[8];
    const float* b1  = (const float*)d_in[9];
    const float* W2  = (const float*)d_in[10];
    const float* b2  = (const float*)d_in[11];
    const float* gamma2 = (const float*)d_in[12];
    const float* beta2  = (const float*)d_in[13];
    float* out = (float*)d_out;

    cudaFuncSetAttribute(gemm_mma<0,false,false>, cudaFuncAttributeMaxDynamicSharedMemorySize, GSMEM);
    cudaFuncSetAttribute(gemm_mma<1,false,false>, cudaFuncAttributeMaxDynamicSharedMemorySize, GSMEM);
    cudaFuncSetAttribute(gemm_mma<0,false,true>,  cudaFuncAttributeMaxDynamicSharedMemorySize, GSMEM);
    cudaFuncSetAttribute(gemm_mma<2,true,false>,  cudaFuncAttributeMaxDynamicSharedMemorySize, GSMEM);

    #define SYM(v, s) cudaGetSymbolAddress((void**)&v, s)
    __half *srcH,*srcL,*tgtH,*tgtL,*qTh,*qTl,*kTh,*kTl,*vH,*vL,*atH,*atL,*l1H,*l1L;
    __half *hidH,*hidL,*cxH,*cxL,*WqH,*WqL,*WkH,*WkL,*WvH,*WvL,*WlH,*WlL,*W1H,*W1L,*W2H,*W2L;
    float *qf,*kf,*linf,*f2f,*cpart,*pm,*ps,*cm,*cs;
    SYM(srcH,g_srcH); SYM(srcL,g_srcL); SYM(tgtH,g_tgtH); SYM(tgtL,g_tgtL);
    SYM(qf,g_q); SYM(kf,g_k); SYM(linf,g_lin); SYM(f2f,g_f2);
    SYM(qTh,g_qTh); SYM(qTl,g_qTl); SYM(kTh,g_kTh); SYM(kTl,g_kTl);
    SYM(vH,g_vH); SYM(vL,g_vL); SYM(atH,g_atH); SYM(atL,g_atL);
    SYM(l1H,g_l1H); SYM(l1L,g_l1L); SYM(hidH,g_hidH); SYM(hidL,g_hidL);
    SYM(cxH,g_cxH); SYM(cxL,g_cxL); SYM(cpart,g_cpart);
    SYM(WqH,g_WqH); SYM(WqL,g_WqL); SYM(WkH,g_WkH); SYM(WkL,g_WkL);
    SYM(WvH,g_WvH); SYM(WvL,g_WvL); SYM(WlH,g_WlH); SYM(WlL,g_WlL);
    SYM(W1H,g_W1H); SYM(W1L,g_W1L); SYM(W2H,g_W2H); SYM(W2L,g_W2L);
    SYM(pm,g_pm); SYM(ps,g_ps); SYM(cm,g_cm); SYM(cs,g_cs);
    #undef SYM

    const dim3 tb(32, 8);

    // converts + weight transpose-splits (W [K][N] -> WT [N][K])
    convsplit<<<8192, 256>>>(src, srcH, srcL);
    convsplit<<<8192, 256>>>(tgt, tgtH, tgtL);
    tsplit<false><<<dim3(8, 8, 1),   tb>>>(Wq, WqH, WqL, 256, 256, 0, 0, nullptr, nullptr);
    tsplit<false><<<dim3(8, 8, 1),   tb>>>(Wk, WkH, WkL, 256, 256, 0, 0, nullptr, nullptr);
    tsplit<false><<<dim3(8, 8, 1),   tb>>>(Wv, WvH, WvL, 256, 256, 0, 0, nullptr, nullptr);
    tsplit<false><<<dim3(8, 8, 1),   tb>>>(Wl, WlH, WlL, 256, 256, 0, 0, nullptr, nullptr);
    tsplit<false><<<dim3(64, 16, 1), tb>>>(W1, W1H, W1L, 512, 2048, 0, 0, nullptr, nullptr);
    tsplit<false><<<dim3(8, 64, 1),  tb>>>(W2, W2H, W2L, 2048, 256, 0, 0, nullptr, nullptr);

    // q, k (f32), v (hi/lo)
    gemm_mma<0,false,false><<<dim3(2,256,1), 256, GSMEM>>>(srcH, srcL, nullptr, nullptr, 256,
        WqH, 256, nullptr, qf, nullptr, nullptr, 256, 256, 0, 0, 0, 0);
    gemm_mma<0,false,false><<<dim3(2,256,1), 256, GSMEM>>>(tgtH, tgtL, nullptr, nullptr, 256,
        WkH, 256, nullptr, kf, nullptr, nullptr, 256, 256, 0, 0, 0, 0);
    gemm_mma<1,false,false><<<dim3(2,256,1), 256, GSMEM>>>(tgtH, tgtL, nullptr, nullptr, 256,
        WvH, 256, nullptr, nullptr, vH, vL, 256, 256, 0, 0, 0, 0);

    // softmax over tokens; transpose+split k (normalized, x4096) and q
    softmax_p1<<<dim3(8, 16, BATCH), tb>>>(kf, pm, ps);
    softmax_comb<<<BATCH, 256>>>(pm, ps, cm, cs);
    tsplit<true><<<dim3(8, 256, BATCH), tb>>>(kf, kTh, kTl, LSEQ, 256,
        (long long)LSEQ*CC, (long long)CC*LSEQ, cm, cs);
    tsplit<false><<<dim3(8, 256, BATCH), tb>>>(qf, qTh, qTl, LSEQ, 256,
        (long long)LSEQ*CC, (long long)CC*LSEQ, nullptr, nullptr);

    // ctx[d][e] = sum_n qT[d][n] * kT[e][n]  (split-K, f32 partials)
    gemm_mma<0,false,true><<<dim3(2, 2, BATCH*NSPK), 256, GSMEM>>>(qTh, qTl, nullptr, nullptr, LSEQ,
        kTh, LSEQ, nullptr, cpart, nullptr, nullptr, 256,
        LSEQ, (long long)CC*LSEQ, (long long)CC*LSEQ, 65536, LSEQ / NSPK);
    reduce_split<<<1024, 256>>>(cpart, cxH, cxL);

    // attn[n][d] = sum_e v[n][e] * ctx[d][e]
    gemm_mma<1,false,false><<<dim3(2, 64, BATCH), 256, GSMEM>>>(vH, vL, nullptr, nullptr, 256,
        cxH, 256, nullptr, nullptr, atH, atL, 256,
        256, (long long)LSEQ*CC, 65536, (long long)LSEQ*CC, 0);

    // message = LN(attn @ Wl)
    gemm_mma<0,false,false><<<dim3(2,256,1), 256, GSMEM>>>(atH, atL, nullptr, nullptr, 256,
        WlH, 256, nullptr, linf, nullptr, nullptr, 256, 256, 0, 0, 0, 0);
    ln_k<0,false,false><<<32768, 256>>>(linf, nullptr, gamma1, beta1, nullptr, nullptr, l1H, l1L);

    // hidden = gelu([src | msg] @ W1 + b1)
    gemm_mma<2,true,false><<<dim3(16,256,1), 256, GSMEM>>>(srcH, srcL, l1H, l1L, 256,
        W1H, 512, b1, nullptr, hidH, hidL, 2048, 512, 0, 0, 0, 0);

    // out = src + LN(hidden @ W2 + b2)
    gemm_mma<0,false,false><<<dim3(2,256,1), 256, GSMEM>>>(hidH, hidL, nullptr, nullptr, 2048,
        W2H, 2048, nullptr, f2f, nullptr, nullptr, 256, 2048, 0, 0, 0, 0);
    ln_k<1,true,true><<<32768, 256>>>(f2f, b2, gamma2, beta2, src, out, nullptr, nullptr);
}

// round 9
// speedup vs baseline: 4.7710x; 1.3734x over previous
#include <cuda_runtime.h>
#include <cuda_fp16.h>
#include <cstdint>
#include <math.h>

#define BATCH 4
#define LSEQ  8192
#define CC    256
#define BL    32768
#define HID   2048
#define NSPK  16
#define KSCALE 4096.0f

// ---------------- PTX helpers -----------------------------------------------
__device__ __forceinline__ uint32_t s2u(const void* p) {
    uint32_t a;
    asm("{ .reg .u64 t; cvta.to.shared.u64 t, %1; cvt.u32.u64 %0, t; }" : "=r"(a) : "l"(p));
    return a;
}
__device__ __forceinline__ void cpasync16(uint32_t s, const void* g) {
    asm volatile("cp.async.cg.shared.global [%0], [%1], 16;" :: "r"(s), "l"(g));
}
#define CP_COMMIT() asm volatile("cp.async.commit_group;" ::: "memory")
#define CP_WAIT1()  asm volatile("cp.async.wait_group 1;" ::: "memory")
__device__ __forceinline__ void ldsm4(uint32_t* r, uint32_t a) {
    asm volatile("ldmatrix.sync.aligned.m8n8.x4.shared.b16 {%0,%1,%2,%3}, [%4];"
        : "=r"(r[0]), "=r"(r[1]), "=r"(r[2]), "=r"(r[3]) : "r"(a));
}
__device__ __forceinline__ void mma16816(float* d, const uint32_t* a, const uint32_t* b) {
    asm volatile(
        "mma.sync.aligned.m16n8k16.row.col.f32.f16.f16.f32 "
        "{%0,%1,%2,%3}, {%4,%5,%6,%7}, {%8,%9}, {%0,%1,%2,%3};"
        : "+f"(d[0]), "+f"(d[1]), "+f"(d[2]), "+f"(d[3])
        : "r"(a[0]), "r"(a[1]), "r"(a[2]), "r"(a[3]), "r"(b[0]), "r"(b[1]));
}

// ---------------- scratch ----------------------------------------------------
__device__ __half g_srcH[BL*CC], g_srcL[BL*CC], g_tgtH[BL*CC], g_tgtL[BL*CC];
__device__ float  g_q[BL*CC], g_k[BL*CC], g_lin[BL*CC], g_f2[BL*CC];
__device__ __half g_qTh[BL*CC], g_qTl[BL*CC], g_kTh[BL*CC], g_kTl[BL*CC];
__device__ __half g_vH[BL*CC], g_vL[BL*CC], g_atH[BL*CC], g_atL[BL*CC];
__device__ __half g_l1H[BL*CC];
__device__ __half g_hidH[(long long)BL*HID];
__device__ __half g_cxH[BATCH*CC*CC], g_cxL[BATCH*CC*CC];
__device__ float  g_cpart[BATCH*NSPK*CC*CC];
__device__ __half g_WqH[CC*CC], g_WkH[CC*CC], g_WvH[CC*CC], g_WlH[CC*CC];
__device__ __half g_W1H[HID*2*CC], g_W2H[CC*HID];
__device__ float g_pm[16*BATCH*CC], g_ps[16*BATCH*CC], g_cm[BATCH*CC], g_cs[BATCH*CC];

// ---------------- small utils -------------------------------------------------
__device__ __forceinline__ void hsplit(float x, unsigned short& h, unsigned short& l) {
    __half hh = __float2half_rn(x);
    __half hl = __float2half_rn(x - __half2float(hh));
    h = __half_as_ushort(hh); l = __half_as_ushort(hl);
}
__device__ __forceinline__ void hsplit2(float a, float b, uint32_t& h, uint32_t& l) {
    unsigned short h0, l0, h1, l1;
    hsplit(a, h0, l0); hsplit(b, h1, l1);
    h = (uint32_t)h0 | ((uint32_t)h1 << 16);
    l = (uint32_t)l0 | ((uint32_t)l1 << 16);
}
__device__ __forceinline__ float gelu_f(float x) {
    return 0.5f * x * (1.0f + erff(x * 0.70710678118654752f));
}

// ---------------- mma.sync GEMM ----------------------------------------------
// Tile M=128 N=128 Kchunk=32, 3-stage cp.async, 8 warps (2m x 4n), fp16.
// TERMS=2: D = Ah*Bh + Al*Bh (A exact pair). TERMS=1: D = Ah*Bh (both rounded).
// EP: 0 = f32 out, 1 = hi/lo out, 2 = bias+gelu single-half out
template<int TERMS> struct Cfg {
    static constexpr int STAGE = (TERMS + 1) * 10240;   // A tiles + B tile, 128*80B each
    static constexpr int SMEM  = 3 * STAGE;
};

template<int EP, bool DUAL, bool SPLITK, int TERMS>
__global__ __launch_bounds__(256)
void gemm_mma(const __half* __restrict__ Ah, const __half* __restrict__ Al,
              const __half* __restrict__ A2h, const __half* __restrict__ A2l, int lda,
              const __half* __restrict__ Bh, int ldb,
              const float* __restrict__ bias,
              float* __restrict__ of, __half* __restrict__ oh, __half* __restrict__ ol,
              int ldo, int Ktot, long long sA, long long sB, long long sO, int kslen)
{
    constexpr int STAGE = Cfg<TERMS>::STAGE;
    constexpr int BOFF  = TERMS * 10240;
    extern __shared__ char smem[];
    const uint32_t sb = s2u(smem);
    const int tid = threadIdx.x, lane = tid & 31, wid = tid >> 5;
    const int wm = wid >> 2, wn = wid & 3;
    const int m0 = blockIdx.y * 128, n0 = blockIdx.x * 128, z = blockIdx.z;

    int kbase = 0, K = Ktot;
    long long ooff;
    if (SPLITK) {
        int b = z / NSPK, sp = z - b * NSPK;
        Ah += (long long)b * sA; if (TERMS == 2) Al += (long long)b * sA;
        Bh += (long long)b * sB;
        kbase = sp * kslen; K = kslen;
        ooff = (long long)z * sO;
    } else {
        Ah += (long long)z * sA; if (TERMS == 2) Al += (long long)z * sA;
        Bh += (long long)z * sB;
        ooff = (long long)z * sO;
    }
    if (of) of += ooff;
    if (oh) { oh += ooff; if (ol) ol += ooff; }

    float c[4][4][4];
#pragma unroll
    for (int i = 0; i < 4; ++i)
#pragma unroll
        for (int j = 0; j < 4; ++j)
#pragma unroll
            for (int q = 0; q < 4; ++q) c[i][j][q] = 0.f;

    auto LOADST = [&](int s, int kc) {
        uint32_t stb = sb + s * STAGE;
#pragma unroll
        for (int i = 0; i < (TERMS + 1) * 2; ++i) {
            int g = tid + i * 256;
            int tile = g >> 9, idx = g & 511;
            int row = idx >> 2, ch = idx & 3;
            uint32_t sa = stb + tile * 10240 + row * 80 + ch * 16;
            const __half* gp;
            if (tile < TERMS) {
                const __half* pa; int ka = kc;
                if (DUAL && kc >= 256) { pa = (tile == 0 ? A2h : A2l); ka = kc - 256; }
                else                   { pa = (tile == 0 ? Ah  : Al ); }
                gp = pa + (long long)(m0 + row) * lda + ka + ch * 8;
            } else {
                gp = Bh + (long long)(n0 + row) * ldb + kc + ch * 8;
            }
            cpasync16(sa, gp);
        }
    };

    const int nch = K >> 5;
    LOADST(0, kbase);
    CP_COMMIT();
    if (nch > 1) LOADST(1, kbase + 32);
    CP_COMMIT();

    int sidx = 0;
    for (int it = 0; it < nch; ++it) {
        CP_WAIT1();
        __syncthreads();
        if (it + 2 < nch) {
            int ns = sidx + 2; if (ns >= 3) ns -= 3;
            LOADST(ns, kbase + ((it + 2) << 5));
        }
        CP_COMMIT();

        uint32_t stb = sb + sidx * STAGE;
#pragma unroll
        for (int kk = 0; kk < 2; ++kk) {
            uint32_t ab = stb + (uint32_t)((lane & 15) + wm * 64) * 80 + ((lane >> 4) << 4) + kk * 32;
            uint32_t ah[4][4], al[4][4];
#pragma unroll
            for (int mt = 0; mt < 4; ++mt) {
                ldsm4(ah[mt], ab + mt * 16 * 80);
                if (TERMS == 2) ldsm4(al[mt], ab + 10240 + mt * 16 * 80);
            }
            int brow = (lane & 7) + ((lane >> 4) << 3);
            int bcol = (lane >> 3) & 1;
            uint32_t bb = stb + BOFF + (uint32_t)(wn * 32 + brow) * 80 + kk * 32 + bcol * 16;
            uint32_t bh[4][2];
#pragma unroll
            for (int p = 0; p < 2; ++p) {
                uint32_t rh[4];
                ldsm4(rh, bb + p * 16 * 80);
                bh[2*p][0] = rh[0]; bh[2*p][1] = rh[1];
                bh[2*p+1][0] = rh[2]; bh[2*p+1][1] = rh[3];
            }
#pragma unroll
            for (int mt = 0; mt < 4; ++mt)
#pragma unroll
                for (int nt = 0; nt < 4; ++nt) {
                    mma16816(c[mt][nt], ah[mt], bh[nt]);
                    if (TERMS == 2) mma16816(c[mt][nt], al[mt], bh[nt]);
                }
        }
        if (++sidx == 3) sidx = 0;
    }
    __syncthreads();

    // epilogue
#pragma unroll
    for (int mt = 0; mt < 4; ++mt)
#pragma unroll
        for (int nt = 0; nt < 4; ++nt) {
            int r  = m0 + wm * 64 + mt * 16 + (lane >> 2);
            int cl = n0 + wn * 32 + nt * 8 + ((lane & 3) << 1);
            float* d = c[mt][nt];
            if (EP == 0) {
                *(float2*)&of[(long long)r * ldo + cl]       = make_float2(d[0], d[1]);
                *(float2*)&of[(long long)(r + 8) * ldo + cl] = make_float2(d[2], d[3]);
            } else if (EP == 1) {
                uint32_t h01, l01, h23, l23;
                hsplit2(d[0], d[1], h01, l01);
                hsplit2(d[2], d[3], h23, l23);
                *(uint32_t*)&oh[(long long)r * ldo + cl]       = h01;
                *(uint32_t*)&ol[(long long)r * ldo + cl]       = l01;
                *(uint32_t*)&oh[(long long)(r + 8) * ldo + cl] = h23;
                *(uint32_t*)&ol[(long long)(r + 8) * ldo + cl] = l23;
            } else {               // EP==2: bias+gelu, single half
                float b0v = bias[cl], b1v = bias[cl + 1];
                __half2 p01 = __floats2half2_rn(gelu_f(d[0] + b0v), gelu_f(d[1] + b1v));
                __half2 p23 = __floats2half2_rn(gelu_f(d[2] + b0v), gelu_f(d[3] + b1v));
                *(__half2*)&oh[(long long)r * ldo + cl]       = p01;
                *(__half2*)&oh[(long long)(r + 8) * ldo + cl] = p23;
            }
        }
}

// ---------------- elementwise / transforms -----------------------------------
__global__ void convsplit(const float* __restrict__ in, __half* __restrict__ oh,
                          __half* __restrict__ ol)
{
    int i = (blockIdx.x * 256 + threadIdx.x) * 4;
    float4 v = *(const float4*)(in + i);
    uint32_t h0, l0, h1, l1;
    hsplit2(v.x, v.y, h0, l0); hsplit2(v.z, v.w, h1, l1);
    *(uint2*)(oh + i) = make_uint2(h0, h1);
    *(uint2*)(ol + i) = make_uint2(l0, l1);
}

// single-half weight convert+transpose (no split)
__global__ void tconv(const float* __restrict__ in, __half* __restrict__ oh, int R, int C)
{
    __shared__ float tile[32][33];
    const int c0 = blockIdx.x * 32, r0 = blockIdx.y * 32;
    const int tx = threadIdx.x, ty = threadIdx.y;
#pragma unroll
    for (int i = 0; i < 4; ++i)
        tile[ty + i * 8][tx] = in[(long long)(r0 + ty + i * 8) * C + c0 + tx];
    __syncthreads();
#pragma unroll
    for (int i = 0; i < 4; ++i) {
        int cidx = c0 + ty + i * 8;
        oh[(long long)cidx * R + r0 + tx] = __float2half_rn(tile[tx][ty + i * 8]);
    }
}

template<bool NORM>
__global__ void tsplit(const float* __restrict__ in, __half* __restrict__ oh,
                       __half* __restrict__ ol, int R, int C,
                       long long sIn, long long sOut,
                       const float* __restrict__ cm, const float* __restrict__ cs)
{
    __shared__ float tile[32][33];
    const int z = blockIdx.z;
    const int c0 = blockIdx.x * 32, r0 = blockIdx.y * 32;
    const int tx = threadIdx.x, ty = threadIdx.y;
    const float* ip = in + z * sIn;
    float nm = 0.f, ns = 1.f;
    if (NORM) { nm = cm[z * CC + c0 + tx]; ns = KSCALE / cs[z * CC + c0 + tx]; }
#pragma unroll
    for (int i = 0; i < 4; ++i) {
        float v = ip[(long long)(r0 + ty + i * 8) * C + c0 + tx];
        if (NORM) v = expf(v - nm) * ns;
        tile[ty + i * 8][tx] = v;
    }
    __syncthreads();
#pragma unroll
    for (int i = 0; i < 4; ++i) {
        int cidx = c0 + ty + i * 8;
        float v = tile[tx][ty + i * 8];
        unsigned short h, l;
        hsplit(v, h, l);
        long long o = z * sOut + (long long)cidx * R + r0 + tx;
        oh[o] = __ushort_as_half(h);
        ol[o] = __ushort_as_half(l);
    }
}

__global__ void softmax_p1(const float* __restrict__ Kin, float* __restrict__ pm, float* __restrict__ ps)
{
    const int b = blockIdx.z, sp = blockIdx.y, c0 = blockIdx.x * 32;
    const int tx = threadIdx.x, ty = threadIdx.y;
    const float* kb = Kin + (long long)b * LSEQ * CC + c0 + tx;
    const int n0 = sp * 512;
    float m = -1e30f, s = 0.f;
    for (int l = ty; l < 512; l += 8) {
        float v = kb[(long long)(n0 + l) * CC];
        if (v > m) { s = s * expf(m - v) + 1.0f; m = v; }
        else       { s += expf(v - m); }
    }
    __shared__ float Ms[8][32], Ss[8][32];
    Ms[ty][tx] = m; Ss[ty][tx] = s;
    __syncthreads();
    if (ty == 0) {
#pragma unroll
        for (int r = 1; r < 8; ++r) {
            float m2 = Ms[r][tx], s2 = Ss[r][tx];
            float mm = fmaxf(m, m2);
            s = s * expf(m - mm) + s2 * expf(m2 - mm);
            m = mm;
        }
        pm[(sp * BATCH + b) * CC + c0 + tx] = m;
        ps[(sp * BATCH + b) * CC + c0 + tx] = s;
    }
}
__global__ void softmax_comb(const float* __restrict__ pm, const float* __restrict__ ps,
                             float* __restrict__ cm, float* __restrict__ cs)
{
    const int b = blockIdx.x, cch = threadIdx.x;
    float m = -1e30f, s = 0.f;
#pragma unroll
    for (int sp = 0; sp < 16; ++sp) {
        float m2 = pm[(sp * BATCH + b) * CC + cch], s2 = ps[(sp * BATCH + b) * CC + cch];
        float mm = fmaxf(m, m2);
        s = s * expf(m - mm) + s2 * expf(m2 - mm);
        m = mm;
    }
    cm[b * CC + cch] = m; cs[b * CC + cch] = s;
}

__global__ void reduce_split(const float* __restrict__ part, __half* __restrict__ oh,
                             __half* __restrict__ ol)
{
    int i = blockIdx.x * 256 + threadIdx.x;
    int b = i >> 16, w = i & 65535;
    float s = 0.f;
#pragma unroll
    for (int sp = 0; sp < NSPK; ++sp) s += part[(long long)(b * NSPK + sp) * 65536 + w];
    s *= (1.0f / KSCALE);
    unsigned short h, l;
    hsplit(s, h, l);
    oh[i] = __ushort_as_half(h);
    ol[i] = __ushort_as_half(l);
}

// LN; OUT: 0 = single half, 1 = f32 (+opt pre-bias, +opt residual)
template<int OUT, bool PREB, bool RES>
__global__ void ln_k(const float* __restrict__ X, const float* __restrict__ preb,
                     const float* __restrict__ gamma, const float* __restrict__ beta,
                     const float* __restrict__ resid,
                     float* __restrict__ of, __half* __restrict__ oh)
{
    const int row = blockIdx.x, t = threadIdx.x;
    const long long base = (long long)row * CC;
    float x = X[base + t];
    if (PREB) x += preb[t];
    __shared__ float red[8];
    float s = x;
#pragma unroll
    for (int o = 16; o; o >>= 1) s += __shfl_xor_sync(0xffffffffu, s, o);
    if ((t & 31) == 0) red[t >> 5] = s;
    __syncthreads();
    float mu = 0.f;
#pragma unroll
    for (int i = 0; i < 8; ++i) mu += red[i];
    mu *= (1.f / 256.f);
    __syncthreads();
    float d = x - mu, q = d * d;
#pragma unroll
    for (int o = 16; o; o >>= 1) q += __shfl_xor_sync(0xffffffffu, q, o);
    if ((t & 31) == 0) red[t >> 5] = q;
    __syncthreads();
    float var = 0.f;
#pragma unroll
    for (int i = 0; i < 8; ++i) var += red[i];
    var *= (1.f / 256.f);
    float y = d * rsqrtf(var + 1e-5f) * gamma[t] + beta[t];
    if (RES) y += resid[base + t];
    if (OUT == 1) of[base + t] = y;
    else          oh[base + t] = __float2half_rn(y);
}

// ---------------- launch ------------------------------------------------------
extern "C" void kernel_launch(void* const* d_in, const int* in_sizes, int n_in,
                              void* d_out, int out_size)
{
    const float* src = (const float*)d_in[0];
    const float* tgt = (const float*)d_in[1];
    const float* Wq  = (const float*)d_in[2];
    const float* Wk  = (const float*)d_in[3];
    const float* Wv  = (const float*)d_in[4];
    const float* Wl  = (const float*)d_in[5];
    const float* gamma1 = (const float*)d_in[6];
    const float* beta1  = (const float*)d_in[7];
    const float* W1  = (const float*)d_in[8];
    const float* b1  = (const float*)d_in[9];
    const float* W2  = (const float*)d_in[10];
    const float* b2  = (const float*)d_in[11];
    const float* gamma2 = (const float*)d_in[12];
    const float* beta2  = (const float*)d_in[13];
    float* out = (float*)d_out;

    constexpr int SM2 = Cfg<2>::SMEM, SM1 = Cfg<1>::SMEM;
    cudaFuncSetAttribute(gemm_mma<0,false,false,2>, cudaFuncAttributeMaxDynamicSharedMemorySize, SM2);
    cudaFuncSetAttribute(gemm_mma<1,false,false,2>, cudaFuncAttributeMaxDynamicSharedMemorySize, SM2);
    cudaFuncSetAttribute(gemm_mma<0,false,true,2>,  cudaFuncAttributeMaxDynamicSharedMemorySize, SM2);
    cudaFuncSetAttribute(gemm_mma<2,true,false,1>,  cudaFuncAttributeMaxDynamicSharedMemorySize, SM1);
    cudaFuncSetAttribute(gemm_mma<0,false,false,1>, cudaFuncAttributeMaxDynamicSharedMemorySize, SM1);

    #define SYM(v, s) cudaGetSymbolAddress((void**)&v, s)
    __half *srcH,*srcL,*tgtH,*tgtL,*qTh,*qTl,*kTh,*kTl,*vH,*vL,*atH,*atL,*l1H;
    __half *hidH,*cxH,*cxL,*WqH,*WkH,*WvH,*WlH,*W1H,*W2H;
    float *qf,*kf,*linf,*f2f,*cpart,*pm,*ps,*cm,*cs;
    SYM(srcH,g_srcH); SYM(srcL,g_srcL); SYM(tgtH,g_tgtH); SYM(tgtL,g_tgtL);
    SYM(qf,g_q); SYM(kf,g_k); SYM(linf,g_lin); SYM(f2f,g_f2);
    SYM(qTh,g_qTh); SYM(qTl,g_qTl); SYM(kTh,g_kTh); SYM(kTl,g_kTl);
    SYM(vH,g_vH); SYM(vL,g_vL); SYM(atH,g_atH); SYM(atL,g_atL);
    SYM(l1H,g_l1H); SYM(hidH,g_hidH);
    SYM(cxH,g_cxH); SYM(cxL,g_cxL); SYM(cpart,g_cpart);
    SYM(WqH,g_WqH); SYM(WkH,g_WkH); SYM(WvH,g_WvH); SYM(WlH,g_WlH);
    SYM(W1H,g_W1H); SYM(W2H,g_W2H);
    SYM(pm,g_pm); SYM(ps,g_ps); SYM(cm,g_cm); SYM(cs,g_cs);
    #undef SYM

    const dim3 tb(32, 8);

    // converts + weight transposes (single-half weights)
    convsplit<<<8192, 256>>>(src, srcH, srcL);
    convsplit<<<8192, 256>>>(tgt, tgtH, tgtL);
    tconv<<<dim3(8, 8),   tb>>>(Wq, WqH, 256, 256);
    tconv<<<dim3(8, 8),   tb>>>(Wk, WkH, 256, 256);
    tconv<<<dim3(8, 8),   tb>>>(Wv, WvH, 256, 256);
    tconv<<<dim3(8, 8),   tb>>>(Wl, WlH, 256, 256);
    tconv<<<dim3(64, 16), tb>>>(W1, W1H, 512, 2048);
    tconv<<<dim3(8, 64),  tb>>>(W2, W2H, 2048, 256);

    // q, k (f32), v (hi/lo)   [2-term]
    gemm_mma<0,false,false,2><<<dim3(2,256,1), 256, SM2>>>(srcH, srcL, nullptr, nullptr, 256,
        WqH, 256, nullptr, qf, nullptr, nullptr, 256, 256, 0, 0, 0, 0);
    gemm_mma<0,false,false,2><<<dim3(2,256,1), 256, SM2>>>(tgtH, tgtL, nullptr, nullptr, 256,
        WkH, 256, nullptr, kf, nullptr, nullptr, 256, 256, 0, 0, 0, 0);
    gemm_mma<1,false,false,2><<<dim3(2,256,1), 256, SM2>>>(tgtH, tgtL, nullptr, nullptr, 256,
        WvH, 256, nullptr, nullptr, vH, vL, 256, 256, 0, 0, 0, 0);

    // softmax over tokens; transpose+split k (normalized, x4096) and q
    softmax_p1<<<dim3(8, 16, BATCH), tb>>>(kf, pm, ps);
    softmax_comb<<<BATCH, 256>>>(pm, ps, cm, cs);
    tsplit<true><<<dim3(8, 256, BATCH), tb>>>(kf, kTh, kTl, LSEQ, 256,
        (long long)LSEQ*CC, (long long)CC*LSEQ, cm, cs);
    tsplit<false><<<dim3(8, 256, BATCH), tb>>>(qf, qTh, qTl, LSEQ, 256,
        (long long)LSEQ*CC, (long long)CC*LSEQ, nullptr, nullptr);

    // ctx[d][e] = sum_n qT[d][n] * kT[e][n]  (split-K, f32 partials)  [2-term]
    gemm_mma<0,false,true,2><<<dim3(2, 2, BATCH*NSPK), 256, SM2>>>(qTh, qTl, nullptr, nullptr, LSEQ,
        kTh, LSEQ, nullptr, cpart, nullptr, nullptr, 256,
        LSEQ, (long long)CC*LSEQ, (long long)CC*LSEQ, 65536, LSEQ / NSPK);
    reduce_split<<<1024, 256>>>(cpart, cxH, cxL);

    // attn[n][d] = sum_e v[n][e] * ctx[d][e]   [2-term]
    gemm_mma<1,false,false,2><<<dim3(2, 64, BATCH), 256, SM2>>>(vH, vL, nullptr, nullptr, 256,
        cxH, 256, nullptr, nullptr, atH, atL, 256,
        256, (long long)LSEQ*CC, 65536, (long long)LSEQ*CC, 0);

    // message = LN(attn @ Wl) -> single half  [2-term]
    gemm_mma<0,false,false,2><<<dim3(2,256,1), 256, SM2>>>(atH, atL, nullptr, nullptr, 256,
        WlH, 256, nullptr, linf, nullptr, nullptr, 256, 256, 0, 0, 0, 0);
    ln_k<0,false,false><<<32768, 256>>>(linf, nullptr, gamma1, beta1, nullptr, nullptr, l1H);

    // hidden = gelu([srcH | l1H] @ W1 + b1) -> single half  [1-term]
    gemm_mma<2,true,false,1><<<dim3(16,256,1), 256, SM1>>>(srcH, nullptr, l1H, nullptr, 256,
        W1H, 512, b1, nullptr, hidH, nullptr, 2048, 512, 0, 0, 0, 0);

    // out = src + LN(hidden @ W2 + b2)   [1-term]
    gemm_mma<0,false,false,1><<<dim3(2,256,1), 256, SM1>>>(hidH, nullptr, nullptr, nullptr, 2048,
        W2H, 2048, nullptr, f2f, nullptr, nullptr, 256, 2048, 0, 0, 0, 0);
    ln_k<1,true,true><<<32768, 256>>>(f2f, b2, gamma2, beta2, src, out, nullptr);
}

// round 11
// speedup vs baseline: 5.8932x; 1.2352x over previous
#include <cuda_runtime.h>
#include <cuda_fp16.h>
#include <cstdint>
#include <math.h>

#define BATCH 4
#define LSEQ  8192
#define CC    256
#define BL    32768
#define HID   2048
#define NSPK  16
#define KSCALE 4096.0f

// ---------------- PTX helpers -----------------------------------------------
__device__ __forceinline__ uint32_t s2u(const void* p) {
    uint32_t a;
    asm("{ .reg .u64 t; cvta.to.shared.u64 t, %1; cvt.u32.u64 %0, t; }" : "=r"(a) : "l"(p));
    return a;
}
__device__ __forceinline__ void cpasync16(uint32_t s, const void* g) {
    asm volatile("cp.async.cg.shared.global [%0], [%1], 16;" :: "r"(s), "l"(g));
}
#define CP_COMMIT() asm volatile("cp.async.commit_group;" ::: "memory")
#define CP_WAIT1()  asm volatile("cp.async.wait_group 1;" ::: "memory")
__device__ __forceinline__ void ldsm4(uint32_t* r, uint32_t a) {
    asm volatile("ldmatrix.sync.aligned.m8n8.x4.shared.b16 {%0,%1,%2,%3}, [%4];"
        : "=r"(r[0]), "=r"(r[1]), "=r"(r[2]), "=r"(r[3]) : "r"(a));
}
__device__ __forceinline__ void mma16816(float* d, const uint32_t* a, const uint32_t* b) {
    asm volatile(
        "mma.sync.aligned.m16n8k16.row.col.f32.f16.f16.f32 "
        "{%0,%1,%2,%3}, {%4,%5,%6,%7}, {%8,%9}, {%0,%1,%2,%3};"
        : "+f"(d[0]), "+f"(d[1]), "+f"(d[2]), "+f"(d[3])
        : "r"(a[0]), "r"(a[1]), "r"(a[2]), "r"(a[3]), "r"(b[0]), "r"(b[1]));
}

// ---------------- scratch ----------------------------------------------------
__device__ __half g_srcH[BL*CC], g_tgtH[BL*CC];
__device__ float  g_kTf[BL*CC], g_lin[BL*CC], g_f2[BL*CC];
__device__ __half g_qTh[BL*CC], g_kTh[BL*CC];
__device__ __half g_vH[BL*CC], g_atH[BL*CC], g_l1H[BL*CC];
__device__ __half g_hidH[(long long)BL*HID];
__device__ __half g_cxH[BATCH*CC*CC];
__device__ float  g_cpart[BATCH*NSPK*CC*CC];
__device__ __half g_WqH[CC*CC], g_WkH[CC*CC], g_WvH[CC*CC], g_WlH[CC*CC];
__device__ __half g_W1H[HID*2*CC], g_W2H[CC*HID];

// ---------------- small utils -------------------------------------------------
__device__ __forceinline__ float gelu_f(float x) {
    return 0.5f * x * (1.0f + erff(x * 0.70710678118654752f));
}

// ---------------- mma.sync GEMM (pure fp16, 1-term) ---------------------------
// Tile M=128 N=128 Kchunk=32, 3-stage cp.async, 8 warps (2m x 4n).
// EP: 0 = f32 out, 2 = bias+gelu half out, 3 = half out,
//     4 = TRANSPOSED half out ([b][c][n], ld=LSEQ), 5 = TRANSPOSED f32 out
static constexpr int STAGE = 20480;            // A|B, each 128*80B
static constexpr int GSMEM  = 3 * STAGE;       // 61440
static constexpr int GSMEM5 = 69632;           // EP=5 staging (128*132 f32)

template<int EP, bool DUAL, bool SPLITK>
__global__ __launch_bounds__(256)
void gemm_mma(const __half* __restrict__ Ah, const __half* __restrict__ A2h, int lda,
              const __half* __restrict__ Bh, int ldb,
              const float* __restrict__ bias,
              float* __restrict__ of, __half* __restrict__ oh,
              int ldo, int Ktot, long long sA, long long sB, long long sO, int kslen)
{
    extern __shared__ char smem[];
    const uint32_t sb = s2u(smem);
    const int tid = threadIdx.x, lane = tid & 31, wid = tid >> 5;
    const int wm = wid >> 2, wn = wid & 3;
    const int m0 = blockIdx.y * 128, n0 = blockIdx.x * 128, z = blockIdx.z;

    int kbase = 0, K = Ktot;
    long long ooff;
    if (SPLITK) {
        int b = z / NSPK, sp = z - b * NSPK;
        Ah += (long long)b * sA;
        Bh += (long long)b * sB;
        kbase = sp * kslen; K = kslen;
        ooff = (long long)z * sO;
    } else {
        Ah += (long long)z * sA;
        Bh += (long long)z * sB;
        ooff = (long long)z * sO;
    }
    if (of) of += ooff;
    if (oh) oh += ooff;

    float c[4][4][4];
#pragma unroll
    for (int i = 0; i < 4; ++i)
#pragma unroll
        for (int j = 0; j < 4; ++j)
#pragma unroll
            for (int q = 0; q < 4; ++q) c[i][j][q] = 0.f;

    auto LOADST = [&](int s, int kc) {
        uint32_t stb = sb + s * STAGE;
#pragma unroll
        for (int i = 0; i < 4; ++i) {
            int g = tid + i * 256;
            int tile = g >> 9, idx = g & 511;
            int row = idx >> 2, ch = idx & 3;
            uint32_t sa = stb + tile * 10240 + row * 80 + ch * 16;
            const __half* gp;
            if (tile == 0) {
                const __half* pa; int ka = kc;
                if (DUAL && kc >= 256) { pa = A2h; ka = kc - 256; }
                else                   { pa = Ah; }
                gp = pa + (long long)(m0 + row) * lda + ka + ch * 8;
            } else {
                gp = Bh + (long long)(n0 + row) * ldb + kc + ch * 8;
            }
            cpasync16(sa, gp);
        }
    };

    const int nch = K >> 5;
    LOADST(0, kbase);
    CP_COMMIT();
    if (nch > 1) LOADST(1, kbase + 32);
    CP_COMMIT();

    int sidx = 0;
    for (int it = 0; it < nch; ++it) {
        CP_WAIT1();
        __syncthreads();
        if (it + 2 < nch) {
            int ns = sidx + 2; if (ns >= 3) ns -= 3;
            LOADST(ns, kbase + ((it + 2) << 5));
        }
        CP_COMMIT();

        uint32_t stb = sb + sidx * STAGE;
#pragma unroll
        for (int kk = 0; kk < 2; ++kk) {
            uint32_t ab = stb + (uint32_t)((lane & 15) + wm * 64) * 80 + ((lane >> 4) << 4) + kk * 32;
            uint32_t ah[4][4];
#pragma unroll
            for (int mt = 0; mt < 4; ++mt) ldsm4(ah[mt], ab + mt * 16 * 80);
            int brow = (lane & 7) + ((lane >> 4) << 3);
            int bcol = (lane >> 3) & 1;
            uint32_t bb = stb + 10240 + (uint32_t)(wn * 32 + brow) * 80 + kk * 32 + bcol * 16;
            uint32_t bh[4][2];
#pragma unroll
            for (int p = 0; p < 2; ++p) {
                uint32_t rh[4];
                ldsm4(rh, bb + p * 16 * 80);
                bh[2*p][0] = rh[0]; bh[2*p][1] = rh[1];
                bh[2*p+1][0] = rh[2]; bh[2*p+1][1] = rh[3];
            }
#pragma unroll
            for (int mt = 0; mt < 4; ++mt)
#pragma unroll
                for (int nt = 0; nt < 4; ++nt)
                    mma16816(c[mt][nt], ah[mt], bh[nt]);
        }
        if (++sidx == 3) sidx = 0;
    }
    __syncthreads();

    // ---------------- epilogues ------------------------------------------------
    if (EP == 4) {
        // transposed half out via smem staging: out[b][n0+col][m-local]
        __half* st = (__half*)smem;
        const int LDT = 136;
#pragma unroll
        for (int mt = 0; mt < 4; ++mt)
#pragma unroll
            for (int nt = 0; nt < 4; ++nt) {
                int r  = wm * 64 + mt * 16 + (lane >> 2);
                int cl = wn * 32 + nt * 8 + ((lane & 3) << 1);
                float* d = c[mt][nt];
                st[cl * LDT + r]           = __float2half_rn(d[0]);
                st[(cl + 1) * LDT + r]     = __float2half_rn(d[1]);
                st[cl * LDT + r + 8]       = __float2half_rn(d[2]);
                st[(cl + 1) * LDT + r + 8] = __float2half_rn(d[3]);
            }
        __syncthreads();
        int bz = m0 >> 13, rloc = m0 & 8191;
        __half* dst = oh + (long long)bz * CC * LSEQ + (long long)n0 * LSEQ + rloc;
#pragma unroll
        for (int g = tid; g < 2048; g += 256) {
            int ccl = g >> 4, seg = g & 15;
            uint4 v = *(uint4*)((char*)st + ccl * 272 + seg * 16);
            *(uint4*)(dst + (long long)ccl * LSEQ + seg * 8) = v;
        }
    } else if (EP == 5) {
        // transposed f32 out via smem staging
        float* st = (float*)smem;
        const int LDT = 132;
#pragma unroll
        for (int mt = 0; mt < 4; ++mt)
#pragma unroll
            for (int nt = 0; nt < 4; ++nt) {
                int r  = wm * 64 + mt * 16 + (lane >> 2);
                int cl = wn * 32 + nt * 8 + ((lane & 3) << 1);
                float* d = c[mt][nt];
                st[cl * LDT + r]           = d[0];
                st[(cl + 1) * LDT + r]     = d[1];
                st[cl * LDT + r + 8]       = d[2];
                st[(cl + 1) * LDT + r + 8] = d[3];
            }
        __syncthreads();
        int bz = m0 >> 13, rloc = m0 & 8191;
        float* dst = of + (long long)bz * CC * LSEQ + (long long)n0 * LSEQ + rloc;
#pragma unroll
        for (int g = tid; g < 4096; g += 256) {
            int ccl = g >> 5, seg = g & 31;
            uint4 v = *(uint4*)((char*)st + ccl * 528 + seg * 16);
            *(uint4*)(dst + (long long)ccl * LSEQ + seg * 4) = v;
        }
    } else {
#pragma unroll
        for (int mt = 0; mt < 4; ++mt)
#pragma unroll
            for (int nt = 0; nt < 4; ++nt) {
                int r  = m0 + wm * 64 + mt * 16 + (lane >> 2);
                int cl = n0 + wn * 32 + nt * 8 + ((lane & 3) << 1);
                float* d = c[mt][nt];
                if (EP == 0) {
                    *(float2*)&of[(long long)r * ldo + cl]       = make_float2(d[0], d[1]);
                    *(float2*)&of[(long long)(r + 8) * ldo + cl] = make_float2(d[2], d[3]);
                } else if (EP == 3) {
                    *(__half2*)&oh[(long long)r * ldo + cl]       = __floats2half2_rn(d[0], d[1]);
                    *(__half2*)&oh[(long long)(r + 8) * ldo + cl] = __floats2half2_rn(d[2], d[3]);
                } else {               // EP==2: bias + gelu
                    float b0v = bias[cl], b1v = bias[cl + 1];
                    *(__half2*)&oh[(long long)r * ldo + cl] =
                        __floats2half2_rn(gelu_f(d[0] + b0v), gelu_f(d[1] + b1v));
                    *(__half2*)&oh[(long long)(r + 8) * ldo + cl] =
                        __floats2half2_rn(gelu_f(d[2] + b0v), gelu_f(d[3] + b1v));
                }
            }
    }
}

// ---------------- elementwise / transforms -----------------------------------
__global__ void convh(const float* __restrict__ in, __half* __restrict__ oh)
{
    int i = (blockIdx.x * 256 + threadIdx.x) * 8;
    float4 a = *(const float4*)(in + i), b = *(const float4*)(in + i + 4);
    __half2 h0 = __floats2half2_rn(a.x, a.y), h1 = __floats2half2_rn(a.z, a.w);
    __half2 h2 = __floats2half2_rn(b.x, b.y), h3 = __floats2half2_rn(b.z, b.w);
    *(uint4*)(oh + i) = make_uint4(*(uint32_t*)&h0, *(uint32_t*)&h1,
                                   *(uint32_t*)&h2, *(uint32_t*)&h3);
}

// weight convert+transpose f32 [R?]... in[r][c] (RxC) -> oh[c][r]
__global__ void tconv(const float* __restrict__ in, __half* __restrict__ oh, int R, int C)
{
    __shared__ float tile[32][33];
    const int c0 = blockIdx.x * 32, r0 = blockIdx.y * 32;
    const int tx = threadIdx.x, ty = threadIdx.y;
#pragma unroll
    for (int i = 0; i < 4; ++i)
        tile[ty + i * 8][tx] = in[(long long)(r0 + ty + i * 8) * C + c0 + tx];
    __syncthreads();
#pragma unroll
    for (int i = 0; i < 4; ++i) {
        int cidx = c0 + ty + i * 8;
        oh[(long long)cidx * R + r0 + tx] = __float2half_rn(tile[tx][ty + i * 8]);
    }
}

// fused whole-row softmax over n: kTf[row][0..8191] -> kTh = exp(v-max)/sum * KSCALE
__global__ void softmax_row(const float* __restrict__ kTf, __half* __restrict__ kTh)
{
    __shared__ float buf[LSEQ];
    __shared__ float red[8];
    const long long base = (long long)blockIdx.x * LSEQ;
    const int t = threadIdx.x;
    float m = -1e30f;
#pragma unroll
    for (int i = 0; i < 8; ++i) {
        int idx = (i * 256 + t) * 4;
        float4 v = *(const float4*)(kTf + base + idx);
        *(float4*)(buf + idx) = v;
        m = fmaxf(m, fmaxf(fmaxf(v.x, v.y), fmaxf(v.z, v.w)));
    }
#pragma unroll
    for (int o = 16; o; o >>= 1) m = fmaxf(m, __shfl_xor_sync(0xffffffffu, m, o));
    if ((t & 31) == 0) red[t >> 5] = m;
    __syncthreads();
    float M = red[0];
#pragma unroll
    for (int i = 1; i < 8; ++i) M = fmaxf(M, red[i]);
    __syncthreads();
    float s = 0.f;
#pragma unroll
    for (int i = 0; i < 8; ++i) {
        int idx = (i * 256 + t) * 4;
        float4 v = *(float4*)(buf + idx);
        v.x = expf(v.x - M); v.y = expf(v.y - M);
        v.z = expf(v.z - M); v.w = expf(v.w - M);
        *(float4*)(buf + idx) = v;
        s += v.x + v.y + v.z + v.w;
    }
#pragma unroll
    for (int o = 16; o; o >>= 1) s += __shfl_xor_sync(0xffffffffu, s, o);
    if ((t & 31) == 0) red[t >> 5] = s;
    __syncthreads();
    float S = 0.f;
#pragma unroll
    for (int i = 0; i < 8; ++i) S += red[i];
    float sc = KSCALE / S;
#pragma unroll
    for (int i = 0; i < 8; ++i) {
        int idx = (i * 256 + t) * 4;
        float4 v = *(float4*)(buf + idx);
        __half2 a = __floats2half2_rn(v.x * sc, v.y * sc);
        __half2 b = __floats2half2_rn(v.z * sc, v.w * sc);
        *(uint2*)(kTh + base + idx) = make_uint2(*(uint32_t*)&a, *(uint32_t*)&b);
    }
}

__global__ void reduce_half(const float* __restrict__ part, __half* __restrict__ oh)
{
    int i = blockIdx.x * 256 + threadIdx.x;
    int b = i >> 16, w = i & 65535;
    float s = 0.f;
#pragma unroll
    for (int sp = 0; sp < NSPK; ++sp) s += part[(long long)(b * NSPK + sp) * 65536 + w];
    oh[i] = __float2half_rn(s * (1.0f / KSCALE));
}

// LN; OUT: 0 = single half, 1 = f32 (+opt pre-bias, +opt residual)
template<int OUT, bool PREB, bool RES>
__global__ void ln_k(const float* __restrict__ X, const float* __restrict__ preb,
                     const float* __restrict__ gamma, const float* __restrict__ beta,
                     const float* __restrict__ resid,
                     float* __restrict__ of, __half* __restrict__ oh)
{
    const int row = blockIdx.x, t = threadIdx.x;
    const long long base = (long long)row * CC;
    float x = X[base + t];
    if (PREB) x += preb[t];
    __shared__ float red[8];
    float s = x;
#pragma unroll
    for (int o = 16; o; o >>= 1) s += __shfl_xor_sync(0xffffffffu, s, o);
    if ((t & 31) == 0) red[t >> 5] = s;
    __syncthreads();
    float mu = 0.f;
#pragma unroll
    for (int i = 0; i < 8; ++i) mu += red[i];
    mu *= (1.f / 256.f);
    __syncthreads();
    float d = x - mu, q = d * d;
#pragma unroll
    for (int o = 16; o; o >>= 1) q += __shfl_xor_sync(0xffffffffu, q, o);
    if ((t & 31) == 0) red[t >> 5] = q;
    __syncthreads();
    float var = 0.f;
#pragma unroll
    for (int i = 0; i < 8; ++i) var += red[i];
    var *= (1.f / 256.f);
    float y = d * rsqrtf(var + 1e-5f) * gamma[t] + beta[t];
    if (RES) y += resid[base + t];
    if (OUT == 1) of[base + t] = y;
    else          oh[base + t] = __float2half_rn(y);
}

// ---------------- launch ------------------------------------------------------
extern "C" void kernel_launch(void* const* d_in, const int* in_sizes, int n_in,
                              void* d_out, int out_size)
{
    const float* src = (const float*)d_in[0];
    const float* tgt = (const float*)d_in[1];
    const float* Wq  = (const float*)d_in[2];
    const float* Wk  = (const float*)d_in[3];
    const float* Wv  = (const float*)d_in[4];
    const float* Wl  = (const float*)d_in[5];
    const float* gamma1 = (const float*)d_in[6];
    const float* beta1  = (const float*)d_in[7];
    const float* W1  = (const float*)d_in[8];
    const float* b1  = (const float*)d_in[9];
    const float* W2  = (const float*)d_in[10];
    const float* b2  = (const float*)d_in[11];
    const float* gamma2 = (const float*)d_in[12];
    const float* beta2  = (const float*)d_in[13];
    float* out = (float*)d_out;

    cudaFuncSetAttribute(gemm_mma<4,false,false>, cudaFuncAttributeMaxDynamicSharedMemorySize, GSMEM);
    cudaFuncSetAttribute(gemm_mma<5,false,false>, cudaFuncAttributeMaxDynamicSharedMemorySize, GSMEM5);
    cudaFuncSetAttribute(gemm_mma<3,false,false>, cudaFuncAttributeMaxDynamicSharedMemorySize, GSMEM);
    cudaFuncSetAttribute(gemm_mma<0,false,true>,  cudaFuncAttributeMaxDynamicSharedMemorySize, GSMEM);
    cudaFuncSetAttribute(gemm_mma<0,false,false>, cudaFuncAttributeMaxDynamicSharedMemorySize, GSMEM);
    cudaFuncSetAttribute(gemm_mma<2,true,false>,  cudaFuncAttributeMaxDynamicSharedMemorySize, GSMEM);

    #define SYM(v, s) cudaGetSymbolAddress((void**)&v, s)
    __half *srcH,*tgtH,*qTh,*kTh,*vH,*atH,*l1H,*hidH,*cxH,*WqH,*WkH,*WvH,*WlH,*W1H,*W2H;
    float *kTf,*linf,*f2f,*cpart;
    SYM(srcH,g_srcH); SYM(tgtH,g_tgtH);
    SYM(kTf,g_kTf); SYM(linf,g_lin); SYM(f2f,g_f2);
    SYM(qTh,g_qTh); SYM(kTh,g_kTh);
    SYM(vH,g_vH); SYM(atH,g_atH); SYM(l1H,g_l1H); SYM(hidH,g_hidH);
    SYM(cxH,g_cxH); SYM(cpart,g_cpart);
    SYM(WqH,g_WqH); SYM(WkH,g_WkH); SYM(WvH,g_WvH); SYM(WlH,g_WlH);
    SYM(W1H,g_W1H); SYM(W2H,g_W2H);
    #undef SYM

    const dim3 tb(32, 8);

    // input + weight converts
    convh<<<4096, 256>>>(src, srcH);
    convh<<<4096, 256>>>(tgt, tgtH);
    tconv<<<dim3(8, 8),   tb>>>(Wq, WqH, 256, 256);
    tconv<<<dim3(8, 8),   tb>>>(Wk, WkH, 256, 256);
    tconv<<<dim3(8, 8),   tb>>>(Wv, WvH, 256, 256);
    tconv<<<dim3(8, 8),   tb>>>(Wl, WlH, 256, 256);
    tconv<<<dim3(64, 16), tb>>>(W1, W1H, 512, 2048);
    tconv<<<dim3(8, 64),  tb>>>(W2, W2H, 2048, 256);

    // q -> qT (half, transposed epilogue), k -> kT (f32, transposed), v -> vH
    gemm_mma<4,false,false><<<dim3(2,256,1), 256, GSMEM>>>(srcH, nullptr, 256,
        WqH, 256, nullptr, nullptr, qTh, 0, 256, 0, 0, 0, 0);
    gemm_mma<5,false,false><<<dim3(2,256,1), 256, GSMEM5>>>(tgtH, nullptr, 256,
        WkH, 256, nullptr, kTf, nullptr, 0, 256, 0, 0, 0, 0);
    gemm_mma<3,false,false><<<dim3(2,256,1), 256, GSMEM>>>(tgtH, nullptr, 256,
        WvH, 256, nullptr, nullptr, vH, 256, 256, 0, 0, 0, 0);

    // fused row softmax on kT (scaled x4096) -> kTh
    softmax_row<<<BATCH * CC, 256>>>(kTf, kTh);

    // ctx[d][e] = sum_n qT[d][n] * kTh[e][n]  (split-K, f32 partials)
    gemm_mma<0,false,true><<<dim3(2, 2, BATCH*NSPK), 256, GSMEM>>>(qTh, nullptr, LSEQ,
        kTh, LSEQ, nullptr, cpart, nullptr, 256,
        LSEQ, (long long)CC*LSEQ, (long long)CC*LSEQ, 65536, LSEQ / NSPK);
    reduce_half<<<1024, 256>>>(cpart, cxH);

    // attn[n][d] = sum_e v[n][e] * ctx[d][e]
    gemm_mma<3,false,false><<<dim3(2, 64, BATCH), 256, GSMEM>>>(vH, nullptr, 256,
        cxH, 256, nullptr, nullptr, atH, 256,
        256, (long long)LSEQ*CC, 65536, (long long)LSEQ*CC, 0);

    // message = LN(attn @ Wl) -> half
    gemm_mma<0,false,false><<<dim3(2,256,1), 256, GSMEM>>>(atH, nullptr, 256,
        WlH, 256, nullptr, linf, nullptr, 256, 256, 0, 0, 0, 0);
    ln_k<0,false,false><<<32768, 256>>>(linf, nullptr, gamma1, beta1, nullptr, nullptr, l1H);

    // hidden = gelu([srcH | l1H] @ W1 + b1) -> half
    gemm_mma<2,true,false><<<dim3(16,256,1), 256, GSMEM>>>(srcH, l1H, 256,
        W1H, 512, b1, nullptr, hidH, 2048, 512, 0, 0, 0, 0);

    // out = src + LN(hidden @ W2 + b2)
    gemm_mma<0,false,false><<<dim3(2,256,1), 256, GSMEM>>>(hidH, nullptr, 2048,
        W2H, 2048, nullptr, f2f, nullptr, 256, 2048, 0, 0, 0, 0);
    ln_k<1,true,true><<<32768, 256>>>(f2f, b2, gamma2, beta2, src, out, nullptr);
}

// round 12
// speedup vs baseline: 6.2786x; 1.0654x over previous
#include <cuda_runtime.h>
#include <cuda_fp16.h>
#include <cstdint>
#include <math.h>

#define BATCH 4
#define LSEQ  8192
#define CC    256
#define BL    32768
#define HID   2048
#define NSPK  16
#define KSCALE 4096.0f

// ---------------- PTX helpers -----------------------------------------------
__device__ __forceinline__ uint32_t s2u(const void* p) {
    uint32_t a;
    asm("{ .reg .u64 t; cvta.to.shared.u64 t, %1; cvt.u32.u64 %0, t; }" : "=r"(a) : "l"(p));
    return a;
}
__device__ __forceinline__ void cpasync16(uint32_t s, const void* g) {
    asm volatile("cp.async.cg.shared.global [%0], [%1], 16;" :: "r"(s), "l"(g));
}
#define CP_COMMIT() asm volatile("cp.async.commit_group;" ::: "memory")
#define CP_WAIT1()  asm volatile("cp.async.wait_group 1;" ::: "memory")
__device__ __forceinline__ void ldsm4(uint32_t* r, uint32_t a) {
    asm volatile("ldmatrix.sync.aligned.m8n8.x4.shared.b16 {%0,%1,%2,%3}, [%4];"
        : "=r"(r[0]), "=r"(r[1]), "=r"(r[2]), "=r"(r[3]) : "r"(a));
}
__device__ __forceinline__ void mma16816(float* d, const uint32_t* a, const uint32_t* b) {
    asm volatile(
        "mma.sync.aligned.m16n8k16.row.col.f32.f16.f16.f32 "
        "{%0,%1,%2,%3}, {%4,%5,%6,%7}, {%8,%9}, {%0,%1,%2,%3};"
        : "+f"(d[0]), "+f"(d[1]), "+f"(d[2]), "+f"(d[3])
        : "r"(a[0]), "r"(a[1]), "r"(a[2]), "r"(a[3]), "r"(b[0]), "r"(b[1]));
}

// ---------------- scratch ----------------------------------------------------
__device__ __half g_srcH[BL*CC], g_tgtH[BL*CC];
__device__ float  g_kTf[BL*CC];
__device__ __half g_qTh[BL*CC], g_kTh[BL*CC];
__device__ __half g_vH[BL*CC], g_l1H[BL*CC];
__device__ __half g_hidH[(long long)BL*HID];
__device__ __half g_cxTh[BATCH*CC*CC], g_m2T[BATCH*CC*CC];
__device__ float  g_cpart[BATCH*NSPK*CC*CC];
__device__ __half g_WqH[CC*CC], g_WkH[CC*CC], g_WvH[CC*CC], g_WlH[CC*CC];
__device__ __half g_W1H[HID*2*CC], g_W2H[CC*HID];

// ---------------- small utils -------------------------------------------------
__device__ __forceinline__ float gelu_f(float x) {
    return 0.5f * x * (1.0f + erff(x * 0.70710678118654752f));
}

// ---------------- mma.sync GEMM (pure fp16, 1-term) ---------------------------
// CFG 0: tile 128x128 (MT=4,NT=4).  CFG 1: tile 64x256 (MT=2,NT=8) — full row,
// enables fused LayerNorm epilogues.
// EP: 0 = f32 out, 2 = bias+gelu half out, 3 = half out,
//     4 = transposed half out ([b][c][n], ld=LSEQ), 5 = transposed f32 out,
//     6 = bias+LN+residual f32 out (CFG1), 7 = LN half out (CFG1)
static constexpr int SM_C0  = 3 * 20480;   // 61440
static constexpr int SM_C0T = 69632;       // CFG0 EP5 staging (128*132 f32)
static constexpr int SM_C1  = 3 * 25600;   // 76800

template<int EP, bool DUAL, bool SPLITK, int CFG>
__global__ __launch_bounds__(256)
void gemm_mma(const __half* __restrict__ Ah, const __half* __restrict__ A2h, int lda,
              const __half* __restrict__ Bh, int ldb,
              const float* __restrict__ bias, const float* __restrict__ gamma,
              const float* __restrict__ beta, const float* __restrict__ resid,
              float* __restrict__ of, __half* __restrict__ oh,
              int ldo, int Ktot, long long sA, long long sB, long long sO, int kslen)
{
    constexpr int AROWS = CFG ? 64 : 128;
    constexpr int BROWS = CFG ? 256 : 128;
    constexpr int NTILE = CFG ? 256 : 128;
    constexpr int MT = CFG ? 2 : 4;
    constexpr int NT = CFG ? 8 : 4;
    constexpr int STAGE = (AROWS + BROWS) * 80;
    constexpr int BOFF = AROWS * 80;
    constexpr int NITER = (AROWS + BROWS) * 4 / 256;

    extern __shared__ char smem[];
    const uint32_t sb = s2u(smem);
    const int tid = threadIdx.x, lane = tid & 31, wid = tid >> 5;
    const int wm = wid >> 2, wn = wid & 3;
    const int m0 = blockIdx.y * AROWS, n0 = blockIdx.x * NTILE, z = blockIdx.z;

    int kbase = 0, K = Ktot;
    long long ooff;
    if (SPLITK) {
        int b = z / NSPK, sp = z - b * NSPK;
        Ah += (long long)b * sA;
        Bh += (long long)b * sB;
        kbase = sp * kslen; K = kslen;
        ooff = (long long)z * sO;
    } else {
        Ah += (long long)z * sA;
        Bh += (long long)z * sB;
        ooff = (long long)z * sO;
    }
    if (of) of += ooff;
    if (oh) oh += ooff;
    const float* residz = resid ? resid + ooff : nullptr;

    float c[MT][NT][4];
#pragma unroll
    for (int i = 0; i < MT; ++i)
#pragma unroll
        for (int j = 0; j < NT; ++j)
#pragma unroll
            for (int q = 0; q < 4; ++q) c[i][j][q] = 0.f;

    auto LOADST = [&](int s, int kc) {
        uint32_t stb = sb + s * STAGE;
#pragma unroll
        for (int i = 0; i < NITER; ++i) {
            int g = tid + i * 256;
            int rl = g >> 2, ch = g & 3;
            const __half* gp;
            uint32_t sa;
            if (rl < AROWS) {
                const __half* pa; int ka = kc;
                if (DUAL && kc >= 256) { pa = A2h; ka = kc - 256; }
                else                   { pa = Ah; }
                gp = pa + (long long)(m0 + rl) * lda + ka + ch * 8;
                sa = stb + rl * 80 + ch * 16;
            } else {
                int br = rl - AROWS;
                gp = Bh + (long long)(n0 + br) * ldb + kc + ch * 8;
                sa = stb + BOFF + br * 80 + ch * 16;
            }
            cpasync16(sa, gp);
        }
    };

    const int nch = K >> 5;
    LOADST(0, kbase);
    CP_COMMIT();
    if (nch > 1) LOADST(1, kbase + 32);
    CP_COMMIT();

    int sidx = 0;
    for (int it = 0; it < nch; ++it) {
        CP_WAIT1();
        __syncthreads();
        if (it + 2 < nch) {
            int ns = sidx + 2; if (ns >= 3) ns -= 3;
            LOADST(ns, kbase + ((it + 2) << 5));
        }
        CP_COMMIT();

        uint32_t stb = sb + sidx * STAGE;
#pragma unroll
        for (int kk = 0; kk < 2; ++kk) {
            uint32_t ab = stb + (uint32_t)((lane & 15) + wm * (AROWS / 2)) * 80
                        + ((lane >> 4) << 4) + kk * 32;
            uint32_t ah[MT][4];
#pragma unroll
            for (int mt = 0; mt < MT; ++mt) ldsm4(ah[mt], ab + mt * 16 * 80);
            int brow = (lane & 7) + ((lane >> 4) << 3);
            int bcol = (lane >> 3) & 1;
            uint32_t bb = stb + BOFF + (uint32_t)(wn * (NTILE / 4) + brow) * 80
                        + kk * 32 + bcol * 16;
            uint32_t bh[NT][2];
#pragma unroll
            for (int p = 0; p < NT / 2; ++p) {
                uint32_t rh[4];
                ldsm4(rh, bb + p * 16 * 80);
                bh[2*p][0] = rh[0]; bh[2*p][1] = rh[1];
                bh[2*p+1][0] = rh[2]; bh[2*p+1][1] = rh[3];
            }
#pragma unroll
            for (int mt = 0; mt < MT; ++mt)
#pragma unroll
                for (int nt = 0; nt < NT; ++nt)
                    mma16816(c[mt][nt], ah[mt], bh[nt]);
        }
        if (++sidx == 3) sidx = 0;
    }
    __syncthreads();

    // ---------------- epilogues ------------------------------------------------
    if (EP == 6 || EP == 7) {
        // fused LayerNorm over full 256-col rows (CFG1 only)
        float* psum = (float*)smem;          // [4][64]
        float* psq  = psum + 256;
        if (EP == 6) {
#pragma unroll
            for (int mt = 0; mt < MT; ++mt)
#pragma unroll
                for (int nt = 0; nt < NT; ++nt) {
                    int cl = wn * 64 + nt * 8 + ((lane & 3) << 1);
                    float b0 = bias[cl], b1 = bias[cl + 1];
                    c[mt][nt][0] += b0; c[mt][nt][1] += b1;
                    c[mt][nt][2] += b0; c[mt][nt][3] += b1;
                }
        }
#pragma unroll
        for (int mt = 0; mt < MT; ++mt) {
            float s1 = 0, q1 = 0, s2 = 0, q2 = 0;
#pragma unroll
            for (int nt = 0; nt < NT; ++nt) {
                float* d = c[mt][nt];
                s1 += d[0] + d[1]; q1 += d[0]*d[0] + d[1]*d[1];
                s2 += d[2] + d[3]; q2 += d[2]*d[2] + d[3]*d[3];
            }
#pragma unroll
            for (int o = 1; o < 4; o <<= 1) {
                s1 += __shfl_xor_sync(0xffffffffu, s1, o);
                q1 += __shfl_xor_sync(0xffffffffu, q1, o);
                s2 += __shfl_xor_sync(0xffffffffu, s2, o);
                q2 += __shfl_xor_sync(0xffffffffu, q2, o);
            }
            if ((lane & 3) == 0) {
                int r1 = wm * 32 + mt * 16 + (lane >> 2);
                psum[wn * 64 + r1] = s1;     psq[wn * 64 + r1] = q1;
                psum[wn * 64 + r1 + 8] = s2; psq[wn * 64 + r1 + 8] = q2;
            }
        }
        __syncthreads();
        float mu_[MT][2], rs_[MT][2];
#pragma unroll
        for (int mt = 0; mt < MT; ++mt) {
            int rb = wm * 32 + mt * 16 + (lane >> 2);
#pragma unroll
            for (int h = 0; h < 2; ++h) {
                int r = rb + h * 8;
                float S = psum[r] + psum[64 + r] + psum[128 + r] + psum[192 + r];
                float Q = psq[r]  + psq[64 + r]  + psq[128 + r]  + psq[192 + r];
                float mu = S * (1.f / 256.f);
                float var = Q * (1.f / 256.f) - mu * mu;
                mu_[mt][h] = mu; rs_[mt][h] = rsqrtf(var + 1e-5f);
            }
        }
#pragma unroll
        for (int mt = 0; mt < MT; ++mt)
#pragma unroll
            for (int nt = 0; nt < NT; ++nt) {
                int r  = m0 + wm * 32 + mt * 16 + (lane >> 2);
                int cl = wn * 64 + nt * 8 + ((lane & 3) << 1);
                float g0 = gamma[cl], g1 = gamma[cl + 1];
                float e0 = beta[cl],  e1 = beta[cl + 1];
                float* d = c[mt][nt];
                float y0 = (d[0] - mu_[mt][0]) * rs_[mt][0] * g0 + e0;
                float y1 = (d[1] - mu_[mt][0]) * rs_[mt][0] * g1 + e1;
                float y2 = (d[2] - mu_[mt][1]) * rs_[mt][1] * g0 + e0;
                float y3 = (d[3] - mu_[mt][1]) * rs_[mt][1] * g1 + e1;
                if (EP == 7) {
                    *(__half2*)&oh[(long long)r * 256 + cl]       = __floats2half2_rn(y0, y1);
                    *(__half2*)&oh[(long long)(r + 8) * 256 + cl] = __floats2half2_rn(y2, y3);
                } else {
                    y0 += residz[(long long)r * 256 + cl];
                    y1 += residz[(long long)r * 256 + cl + 1];
                    y2 += residz[(long long)(r + 8) * 256 + cl];
                    y3 += residz[(long long)(r + 8) * 256 + cl + 1];
                    *(float2*)&of[(long long)r * 256 + cl]       = make_float2(y0, y1);
                    *(float2*)&of[(long long)(r + 8) * 256 + cl] = make_float2(y2, y3);
                }
            }
    } else if (EP == 4) {
        __half* st = (__half*)smem;
        const int LDT = 136;
#pragma unroll
        for (int mt = 0; mt < MT; ++mt)
#pragma unroll
            for (int nt = 0; nt < NT; ++nt) {
                int r  = wm * 64 + mt * 16 + (lane >> 2);
                int cl = wn * 32 + nt * 8 + ((lane & 3) << 1);
                float* d = c[mt][nt];
                st[cl * LDT + r]           = __float2half_rn(d[0]);
                st[(cl + 1) * LDT + r]     = __float2half_rn(d[1]);
                st[cl * LDT + r + 8]       = __float2half_rn(d[2]);
                st[(cl + 1) * LDT + r + 8] = __float2half_rn(d[3]);
            }
        __syncthreads();
        int bz = m0 >> 13, rloc = m0 & 8191;
        __half* dst = oh + (long long)bz * CC * LSEQ + (long long)n0 * LSEQ + rloc;
#pragma unroll
        for (int g = tid; g < 2048; g += 256) {
            int ccl = g >> 4, seg = g & 15;
            uint4 v = *(uint4*)((char*)st + ccl * 272 + seg * 16);
            *(uint4*)(dst + (long long)ccl * LSEQ + seg * 8) = v;
        }
    } else if (EP == 5) {
        float* st = (float*)smem;
        const int LDT = 132;
#pragma unroll
        for (int mt = 0; mt < MT; ++mt)
#pragma unroll
            for (int nt = 0; nt < NT; ++nt) {
                int r  = wm * 64 + mt * 16 + (lane >> 2);
                int cl = wn * 32 + nt * 8 + ((lane & 3) << 1);
                float* d = c[mt][nt];
                st[cl * LDT + r]           = d[0];
                st[(cl + 1) * LDT + r]     = d[1];
                st[cl * LDT + r + 8]       = d[2];
                st[(cl + 1) * LDT + r + 8] = d[3];
            }
        __syncthreads();
        int bz = m0 >> 13, rloc = m0 & 8191;
        float* dst = of + (long long)bz * CC * LSEQ + (long long)n0 * LSEQ + rloc;
#pragma unroll
        for (int g = tid; g < 4096; g += 256) {
            int ccl = g >> 5, seg = g & 31;
            uint4 v = *(uint4*)((char*)st + ccl * 528 + seg * 16);
            *(uint4*)(dst + (long long)ccl * LSEQ + seg * 4) = v;
        }
    } else {
#pragma unroll
        for (int mt = 0; mt < MT; ++mt)
#pragma unroll
            for (int nt = 0; nt < NT; ++nt) {
                int r  = m0 + wm * (AROWS / 2) + mt * 16 + (lane >> 2);
                int cl = n0 + wn * (NTILE / 4) + nt * 8 + ((lane & 3) << 1);
                float* d = c[mt][nt];
                if (EP == 0) {
                    *(float2*)&of[(long long)r * ldo + cl]       = make_float2(d[0], d[1]);
                    *(float2*)&of[(long long)(r + 8) * ldo + cl] = make_float2(d[2], d[3]);
                } else if (EP == 3) {
                    *(__half2*)&oh[(long long)r * ldo + cl]       = __floats2half2_rn(d[0], d[1]);
                    *(__half2*)&oh[(long long)(r + 8) * ldo + cl] = __floats2half2_rn(d[2], d[3]);
                } else {               // EP==2: bias + gelu
                    float b0v = bias[cl], b1v = bias[cl + 1];
                    *(__half2*)&oh[(long long)r * ldo + cl] =
                        __floats2half2_rn(gelu_f(d[0] + b0v), gelu_f(d[1] + b1v));
                    *(__half2*)&oh[(long long)(r + 8) * ldo + cl] =
                        __floats2half2_rn(gelu_f(d[2] + b0v), gelu_f(d[3] + b1v));
                }
            }
    }
}

// ---------------- elementwise / transforms -----------------------------------
__global__ void convh(const float* __restrict__ in, __half* __restrict__ oh)
{
    int i = (blockIdx.x * 256 + threadIdx.x) * 8;
    float4 a = *(const float4*)(in + i), b = *(const float4*)(in + i + 4);
    __half2 h0 = __floats2half2_rn(a.x, a.y), h1 = __floats2half2_rn(a.z, a.w);
    __half2 h2 = __floats2half2_rn(b.x, b.y), h3 = __floats2half2_rn(b.z, b.w);
    *(uint4*)(oh + i) = make_uint4(*(uint32_t*)&h0, *(uint32_t*)&h1,
                                   *(uint32_t*)&h2, *(uint32_t*)&h3);
}

__global__ void tconv(const float* __restrict__ in, __half* __restrict__ oh, int R, int C)
{
    __shared__ float tile[32][33];
    const int c0 = blockIdx.x * 32, r0 = blockIdx.y * 32;
    const int tx = threadIdx.x, ty = threadIdx.y;
#pragma unroll
    for (int i = 0; i < 4; ++i)
        tile[ty + i * 8][tx] = in[(long long)(r0 + ty + i * 8) * C + c0 + tx];
    __syncthreads();
#pragma unroll
    for (int i = 0; i < 4; ++i) {
        int cidx = c0 + ty + i * 8;
        oh[(long long)cidx * R + r0 + tx] = __float2half_rn(tile[tx][ty + i * 8]);
    }
}

// fused whole-row softmax over n: kTf[row] -> kTh = exp(v-max)/sum * KSCALE
__global__ void softmax_row(const float* __restrict__ kTf, __half* __restrict__ kTh)
{
    __shared__ float buf[LSEQ];
    __shared__ float red[8];
    const long long base = (long long)blockIdx.x * LSEQ;
    const int t = threadIdx.x;
    float m = -1e30f;
#pragma unroll
    for (int i = 0; i < 8; ++i) {
        int idx = (i * 256 + t) * 4;
        float4 v = *(const float4*)(kTf + base + idx);
        *(float4*)(buf + idx) = v;
        m = fmaxf(m, fmaxf(fmaxf(v.x, v.y), fmaxf(v.z, v.w)));
    }
#pragma unroll
    for (int o = 16; o; o >>= 1) m = fmaxf(m, __shfl_xor_sync(0xffffffffu, m, o));
    if ((t & 31) == 0) red[t >> 5] = m;
    __syncthreads();
    float M = red[0];
#pragma unroll
    for (int i = 1; i < 8; ++i) M = fmaxf(M, red[i]);
    __syncthreads();
    float s = 0.f;
#pragma unroll
    for (int i = 0; i < 8; ++i) {
        int idx = (i * 256 + t) * 4;
        float4 v = *(float4*)(buf + idx);
        v.x = expf(v.x - M); v.y = expf(v.y - M);
        v.z = expf(v.z - M); v.w = expf(v.w - M);
        *(float4*)(buf + idx) = v;
        s += v.x + v.y + v.z + v.w;
    }
#pragma unroll
    for (int o = 16; o; o >>= 1) s += __shfl_xor_sync(0xffffffffu, s, o);
    if ((t & 31) == 0) red[t >> 5] = s;
    __syncthreads();
    float S = 0.f;
#pragma unroll
    for (int i = 0; i < 8; ++i) S += red[i];
    float sc = KSCALE / S;
#pragma unroll
    for (int i = 0; i < 8; ++i) {
        int idx = (i * 256 + t) * 4;
        float4 v = *(float4*)(buf + idx);
        __half2 a = __floats2half2_rn(v.x * sc, v.y * sc);
        __half2 b = __floats2half2_rn(v.z * sc, v.w * sc);
        *(uint2*)(kTh + base + idx) = make_uint2(*(uint32_t*)&a, *(uint32_t*)&b);
    }
}

// split-K reduce + transpose: cpart[b][sp][d][e] -> cxTh[b][e][d] (half, /KSCALE)
__global__ void reduce_tr(const float* __restrict__ part, __half* __restrict__ oh)
{
    __shared__ float t[32][33];
    const int b = blockIdx.z;
    const int e0 = blockIdx.x * 32, d0 = blockIdx.y * 32;
    const int tx = threadIdx.x, ty = threadIdx.y;
#pragma unroll
    for (int i = 0; i < 4; ++i) {
        int d = d0 + ty + i * 8;
        float s = 0.f;
#pragma unroll
        for (int sp = 0; sp < NSPK; ++sp)
            s += part[(long long)(b * NSPK + sp) * 65536 + d * 256 + e0 + tx];
        t[ty + i * 8][tx] = s;
    }
    __syncthreads();
#pragma unroll
    for (int i = 0; i < 4; ++i) {
        int e = e0 + ty + i * 8;
        oh[(long long)b * 65536 + e * 256 + d0 + tx] =
            __float2half_rn(t[tx][ty + i * 8] * (1.0f / KSCALE));
    }
}

// ---------------- launch ------------------------------------------------------
extern "C" void kernel_launch(void* const* d_in, const int* in_sizes, int n_in,
                              void* d_out, int out_size)
{
    const float* src = (const float*)d_in[0];
    const float* tgt = (const float*)d_in[1];
    const float* Wq  = (const float*)d_in[2];
    const float* Wk  = (const float*)d_in[3];
    const float* Wv  = (const float*)d_in[4];
    const float* Wl  = (const float*)d_in[5];
    const float* gamma1 = (const float*)d_in[6];
    const float* beta1  = (const float*)d_in[7];
    const float* W1  = (const float*)d_in[8];
    const float* b1  = (const float*)d_in[9];
    const float* W2  = (const float*)d_in[10];
    const float* b2  = (const float*)d_in[11];
    const float* gamma2 = (const float*)d_in[12];
    const float* beta2  = (const float*)d_in[13];
    float* out = (float*)d_out;

    cudaFuncSetAttribute(gemm_mma<4,false,false,0>, cudaFuncAttributeMaxDynamicSharedMemorySize, SM_C0);
    cudaFuncSetAttribute(gemm_mma<5,false,false,0>, cudaFuncAttributeMaxDynamicSharedMemorySize, SM_C0T);
    cudaFuncSetAttribute(gemm_mma<3,false,false,0>, cudaFuncAttributeMaxDynamicSharedMemorySize, SM_C0);
    cudaFuncSetAttribute(gemm_mma<0,false,true,0>,  cudaFuncAttributeMaxDynamicSharedMemorySize, SM_C0);
    cudaFuncSetAttribute(gemm_mma<2,true,false,0>,  cudaFuncAttributeMaxDynamicSharedMemorySize, SM_C0);
    cudaFuncSetAttribute(gemm_mma<7,false,false,1>, cudaFuncAttributeMaxDynamicSharedMemorySize, SM_C1);
    cudaFuncSetAttribute(gemm_mma<6,false,false,1>, cudaFuncAttributeMaxDynamicSharedMemorySize, SM_C1);

    #define SYM(v, s) cudaGetSymbolAddress((void**)&v, s)
    __half *srcH,*tgtH,*qTh,*kTh,*vH,*l1H,*hidH,*cxTh,*m2T,*WqH,*WkH,*WvH,*WlH,*W1H,*W2H;
    float *kTf,*cpart;
    SYM(srcH,g_srcH); SYM(tgtH,g_tgtH);
    SYM(kTf,g_kTf);
    SYM(qTh,g_qTh); SYM(kTh,g_kTh);
    SYM(vH,g_vH); SYM(l1H,g_l1H); SYM(hidH,g_hidH);
    SYM(cxTh,g_cxTh); SYM(m2T,g_m2T); SYM(cpart,g_cpart);
    SYM(WqH,g_WqH); SYM(WkH,g_WkH); SYM(WvH,g_WvH); SYM(WlH,g_WlH);
    SYM(W1H,g_W1H); SYM(W2H,g_W2H);
    #undef SYM

    const dim3 tb(32, 8);

    // input + weight converts
    convh<<<4096, 256>>>(src, srcH);
    convh<<<4096, 256>>>(tgt, tgtH);
    tconv<<<dim3(8, 8),   tb>>>(Wq, WqH, 256, 256);
    tconv<<<dim3(8, 8),   tb>>>(Wk, WkH, 256, 256);
    tconv<<<dim3(8, 8),   tb>>>(Wv, WvH, 256, 256);
    tconv<<<dim3(8, 8),   tb>>>(Wl, WlH, 256, 256);
    tconv<<<dim3(64, 16), tb>>>(W1, W1H, 512, 2048);
    tconv<<<dim3(8, 64),  tb>>>(W2, W2H, 2048, 256);

    // q -> qT (half transposed), k -> kT (f32 transposed), v -> vH
    gemm_mma<4,false,false,0><<<dim3(2,256,1), 256, SM_C0>>>(srcH, nullptr, 256,
        WqH, 256, nullptr, nullptr, nullptr, nullptr, nullptr, qTh, 0, 256, 0, 0, 0, 0);
    gemm_mma<5,false,false,0><<<dim3(2,256,1), 256, SM_C0T>>>(tgtH, nullptr, 256,
        WkH, 256, nullptr, nullptr, nullptr, nullptr, kTf, nullptr, 0, 256, 0, 0, 0, 0);
    gemm_mma<3,false,false,0><<<dim3(2,256,1), 256, SM_C0>>>(tgtH, nullptr, 256,
        WvH, 256, nullptr, nullptr, nullptr, nullptr, nullptr, vH, 256, 256, 0, 0, 0, 0);

    // fused row softmax on kT (scaled x4096) -> kTh
    softmax_row<<<BATCH * CC, 256>>>(kTf, kTh);

    // ctx[d][e] = sum_n qT[d][n] * kTh[e][n]  (split-K, f32 partials)
    gemm_mma<0,false,true,0><<<dim3(2, 2, BATCH*NSPK), 256, SM_C0>>>(qTh, nullptr, LSEQ,
        kTh, LSEQ, nullptr, nullptr, nullptr, nullptr, cpart, nullptr, 256,
        LSEQ, (long long)CC*LSEQ, (long long)CC*LSEQ, 65536, LSEQ / NSPK);
    reduce_tr<<<dim3(8, 8, BATCH), tb>>>(cpart, cxTh);

    // M2T[j][e] = sum_d Wl[d][j] * ctx[d][e]   (tiny per-batch GEMM)
    gemm_mma<3,false,false,0><<<dim3(2, 2, BATCH), 256, SM_C0>>>(WlH, nullptr, 256,
        cxTh, 256, nullptr, nullptr, nullptr, nullptr, nullptr, m2T, 256,
        256, 0, 65536, 65536, 0);

    // message = LN(v @ M2T) -> half   (attn GEMM folded away; LN fused)
    gemm_mma<7,false,false,1><<<dim3(1, 128, BATCH), 256, SM_C1>>>(vH, nullptr, 256,
        m2T, 256, nullptr, gamma1, beta1, nullptr, nullptr, l1H, 256,
        256, (long long)LSEQ*CC, 65536, (long long)LSEQ*CC, 0);

    // hidden = gelu([srcH | l1H] @ W1 + b1) -> half
    gemm_mma<2,true,false,0><<<dim3(16,256,1), 256, SM_C0>>>(srcH, l1H, 256,
        W1H, 512, b1, nullptr, nullptr, nullptr, nullptr, hidH, 2048, 512, 0, 0, 0, 0);

    // out = src + LN(hidden @ W2 + b2)   (bias+LN+residual fused)
    gemm_mma<6,false,false,1><<<dim3(1,512,1), 256, SM_C1>>>(hidH, nullptr, 2048,
        W2H, 2048, b2, gamma2, beta2, src, out, nullptr, 256, 2048, 0, 0, 0, 0);
}

// round 13
// speedup vs baseline: 6.3890x; 1.0176x over previous
#include <cuda_runtime.h>
#include <cuda_fp16.h>
#include <cstdint>
#include <math.h>

#define BATCH 4
#define LSEQ  8192
#define CC    256
#define BL    32768
#define HID   2048
#define NSPK  16
#define KSCALE 4096.0f

// ---------------- PTX helpers -----------------------------------------------
__device__ __forceinline__ uint32_t s2u(const void* p) {
    uint32_t a;
    asm("{ .reg .u64 t; cvta.to.shared.u64 t, %1; cvt.u32.u64 %0, t; }" : "=r"(a) : "l"(p));
    return a;
}
__device__ __forceinline__ void cpasync16(uint32_t s, const void* g) {
    asm volatile("cp.async.cg.shared.global [%0], [%1], 16;" :: "r"(s), "l"(g));
}
#define CP_COMMIT() asm volatile("cp.async.commit_group;" ::: "memory")
#define CP_WAIT1()  asm volatile("cp.async.wait_group 1;" ::: "memory")
__device__ __forceinline__ void ldsm4(uint32_t* r, uint32_t a) {
    asm volatile("ldmatrix.sync.aligned.m8n8.x4.shared.b16 {%0,%1,%2,%3}, [%4];"
        : "=r"(r[0]), "=r"(r[1]), "=r"(r[2]), "=r"(r[3]) : "r"(a));
}
__device__ __forceinline__ void mma16816(float* d, const uint32_t* a, const uint32_t* b) {
    asm volatile(
        "mma.sync.aligned.m16n8k16.row.col.f32.f16.f16.f32 "
        "{%0,%1,%2,%3}, {%4,%5,%6,%7}, {%8,%9}, {%0,%1,%2,%3};"
        : "+f"(d[0]), "+f"(d[1]), "+f"(d[2]), "+f"(d[3])
        : "r"(a[0]), "r"(a[1]), "r"(a[2]), "r"(a[3]), "r"(b[0]), "r"(b[1]));
}

// ---------------- scratch ----------------------------------------------------
__device__ __half g_srcH[BL*CC], g_tgtH[BL*CC];
__device__ float  g_kTf[BL*CC];
__device__ __half g_qTh[BL*CC], g_kTh[BL*CC];
__device__ __half g_vH[BL*CC], g_l1H[BL*CC];
__device__ __half g_hidH[(long long)BL*HID];
__device__ __half g_cxTh[BATCH*CC*CC], g_m2T[BATCH*CC*CC];
__device__ float  g_cpart[BATCH*NSPK*CC*CC];
__device__ __half g_WqH[CC*CC], g_WkH[CC*CC], g_WvH[CC*CC], g_WlH[CC*CC];
__device__ __half g_W1H[HID*2*CC], g_W2H[CC*HID];

// ---------------- small utils -------------------------------------------------
__device__ __forceinline__ float gelu_f(float x) {
    return 0.5f * x * (1.0f + erff(x * 0.70710678118654752f));
}

// ---------------- mma.sync GEMM (pure fp16, 1-term) ---------------------------
// CFG 0: tile 128x128 (MT=4,NT=4).  CFG 1: tile 64x256 (MT=2,NT=8) — full row,
// enables fused LayerNorm epilogues.
// EP: 0 = f32 out, 2 = bias+gelu half out, 3 = half out,
//     4 = transposed half out ([b][c][n], ld=LSEQ), 5 = transposed f32 out,
//     6 = bias+LN+residual f32 out (CFG1), 7 = LN half out (CFG1)
static constexpr int SM_C0  = 3 * 20480;   // 61440
static constexpr int SM_C0T = 69632;       // CFG0 EP5 staging (128*132 f32)
static constexpr int SM_C1  = 3 * 25600;   // 76800

template<int EP, bool DUAL, bool SPLITK, int CFG>
__global__ __launch_bounds__(256)
void gemm_mma(const __half* __restrict__ Ah, const __half* __restrict__ A2h, int lda,
              const __half* __restrict__ Bh, int ldb,
              const float* __restrict__ bias, const float* __restrict__ gamma,
              const float* __restrict__ beta, const float* __restrict__ resid,
              float* __restrict__ of, __half* __restrict__ oh,
              int ldo, int Ktot, long long sA, long long sB, long long sO, int kslen)
{
    constexpr int AROWS = CFG ? 64 : 128;
    constexpr int BROWS = CFG ? 256 : 128;
    constexpr int NTILE = CFG ? 256 : 128;
    constexpr int MT = CFG ? 2 : 4;
    constexpr int NT = CFG ? 8 : 4;
    constexpr int STAGE = (AROWS + BROWS) * 80;
    constexpr int BOFF = AROWS * 80;
    constexpr int NITER = (AROWS + BROWS) * 4 / 256;

    extern __shared__ char smem[];
    const uint32_t sb = s2u(smem);
    const int tid = threadIdx.x, lane = tid & 31, wid = tid >> 5;
    const int wm = wid >> 2, wn = wid & 3;
    const int m0 = blockIdx.y * AROWS, n0 = blockIdx.x * NTILE, z = blockIdx.z;

    int kbase = 0, K = Ktot;
    long long ooff;
    if (SPLITK) {
        int b = z / NSPK, sp = z - b * NSPK;
        Ah += (long long)b * sA;
        Bh += (long long)b * sB;
        kbase = sp * kslen; K = kslen;
        ooff = (long long)z * sO;
    } else {
        Ah += (long long)z * sA;
        Bh += (long long)z * sB;
        ooff = (long long)z * sO;
    }
    if (of) of += ooff;
    if (oh) oh += ooff;
    const float* residz = resid ? resid + ooff : nullptr;

    float c[MT][NT][4];
#pragma unroll
    for (int i = 0; i < MT; ++i)
#pragma unroll
        for (int j = 0; j < NT; ++j)
#pragma unroll
            for (int q = 0; q < 4; ++q) c[i][j][q] = 0.f;

    auto LOADST = [&](int s, int kc) {
        uint32_t stb = sb + s * STAGE;
#pragma unroll
        for (int i = 0; i < NITER; ++i) {
            int g = tid + i * 256;
            int rl = g >> 2, ch = g & 3;
            const __half* gp;
            uint32_t sa;
            if (rl < AROWS) {
                const __half* pa; int ka = kc;
                if (DUAL && kc >= 256) { pa = A2h; ka = kc - 256; }
                else                   { pa = Ah; }
                gp = pa + (long long)(m0 + rl) * lda + ka + ch * 8;
                sa = stb + rl * 80 + ch * 16;
            } else {
                int br = rl - AROWS;
                gp = Bh + (long long)(n0 + br) * ldb + kc + ch * 8;
                sa = stb + BOFF + br * 80 + ch * 16;
            }
            cpasync16(sa, gp);
        }
    };

    const int nch = K >> 5;
    LOADST(0, kbase);
    CP_COMMIT();
    if (nch > 1) LOADST(1, kbase + 32);
    CP_COMMIT();

    int sidx = 0;
    for (int it = 0; it < nch; ++it) {
        CP_WAIT1();
        __syncthreads();
        if (it + 2 < nch) {
            int ns = sidx + 2; if (ns >= 3) ns -= 3;
            LOADST(ns, kbase + ((it + 2) << 5));
        }
        CP_COMMIT();

        uint32_t stb = sb + sidx * STAGE;
#pragma unroll
        for (int kk = 0; kk < 2; ++kk) {
            uint32_t ab = stb + (uint32_t)((lane & 15) + wm * (AROWS / 2)) * 80
                        + ((lane >> 4) << 4) + kk * 32;
            uint32_t ah[MT][4];
#pragma unroll
            for (int mt = 0; mt < MT; ++mt) ldsm4(ah[mt], ab + mt * 16 * 80);
            int brow = (lane & 7) + ((lane >> 4) << 3);
            int bcol = (lane >> 3) & 1;
            uint32_t bb = stb + BOFF + (uint32_t)(wn * (NTILE / 4) + brow) * 80
                        + kk * 32 + bcol * 16;
            uint32_t bh[NT][2];
#pragma unroll
            for (int p = 0; p < NT / 2; ++p) {
                uint32_t rh[4];
                ldsm4(rh, bb + p * 16 * 80);
                bh[2*p][0] = rh[0]; bh[2*p][1] = rh[1];
                bh[2*p+1][0] = rh[2]; bh[2*p+1][1] = rh[3];
            }
#pragma unroll
            for (int mt = 0; mt < MT; ++mt)
#pragma unroll
                for (int nt = 0; nt < NT; ++nt)
                    mma16816(c[mt][nt], ah[mt], bh[nt]);
        }
        if (++sidx == 3) sidx = 0;
    }
    __syncthreads();

    // ---------------- epilogues ------------------------------------------------
    if (EP == 6 || EP == 7) {
        // fused LayerNorm over full 256-col rows (CFG1 only)
        float* psum = (float*)smem;          // [4][64]
        float* psq  = psum + 256;
        if (EP == 6) {
#pragma unroll
            for (int mt = 0; mt < MT; ++mt)
#pragma unroll
                for (int nt = 0; nt < NT; ++nt) {
                    int cl = wn * 64 + nt * 8 + ((lane & 3) << 1);
                    float b0 = bias[cl], b1 = bias[cl + 1];
                    c[mt][nt][0] += b0; c[mt][nt][1] += b1;
                    c[mt][nt][2] += b0; c[mt][nt][3] += b1;
                }
        }
#pragma unroll
        for (int mt = 0; mt < MT; ++mt) {
            float s1 = 0, q1 = 0, s2 = 0, q2 = 0;
#pragma unroll
            for (int nt = 0; nt < NT; ++nt) {
                float* d = c[mt][nt];
                s1 += d[0] + d[1]; q1 += d[0]*d[0] + d[1]*d[1];
                s2 += d[2] + d[3]; q2 += d[2]*d[2] + d[3]*d[3];
            }
#pragma unroll
            for (int o = 1; o < 4; o <<= 1) {
                s1 += __shfl_xor_sync(0xffffffffu, s1, o);
                q1 += __shfl_xor_sync(0xffffffffu, q1, o);
                s2 += __shfl_xor_sync(0xffffffffu, s2, o);
                q2 += __shfl_xor_sync(0xffffffffu, q2, o);
            }
            if ((lane & 3) == 0) {
                int r1 = wm * 32 + mt * 16 + (lane >> 2);
                psum[wn * 64 + r1] = s1;     psq[wn * 64 + r1] = q1;
                psum[wn * 64 + r1 + 8] = s2; psq[wn * 64 + r1 + 8] = q2;
            }
        }
        __syncthreads();
        float mu_[MT][2], rs_[MT][2];
#pragma unroll
        for (int mt = 0; mt < MT; ++mt) {
            int rb = wm * 32 + mt * 16 + (lane >> 2);
#pragma unroll
            for (int h = 0; h < 2; ++h) {
                int r = rb + h * 8;
                float S = psum[r] + psum[64 + r] + psum[128 + r] + psum[192 + r];
                float Q = psq[r]  + psq[64 + r]  + psq[128 + r]  + psq[192 + r];
                float mu = S * (1.f / 256.f);
                float var = Q * (1.f / 256.f) - mu * mu;
                mu_[mt][h] = mu; rs_[mt][h] = rsqrtf(var + 1e-5f);
            }
        }
#pragma unroll
        for (int mt = 0; mt < MT; ++mt)
#pragma unroll
            for (int nt = 0; nt < NT; ++nt) {
                int r  = m0 + wm * 32 + mt * 16 + (lane >> 2);
                int cl = wn * 64 + nt * 8 + ((lane & 3) << 1);
                float g0 = gamma[cl], g1 = gamma[cl + 1];
                float e0 = beta[cl],  e1 = beta[cl + 1];
                float* d = c[mt][nt];
                float y0 = (d[0] - mu_[mt][0]) * rs_[mt][0] * g0 + e0;
                float y1 = (d[1] - mu_[mt][0]) * rs_[mt][0] * g1 + e1;
                float y2 = (d[2] - mu_[mt][1]) * rs_[mt][1] * g0 + e0;
                float y3 = (d[3] - mu_[mt][1]) * rs_[mt][1] * g1 + e1;
                if (EP == 7) {
                    *(__half2*)&oh[(long long)r * 256 + cl]       = __floats2half2_rn(y0, y1);
                    *(__half2*)&oh[(long long)(r + 8) * 256 + cl] = __floats2half2_rn(y2, y3);
                } else {
                    y0 += residz[(long long)r * 256 + cl];
                    y1 += residz[(long long)r * 256 + cl + 1];
                    y2 += residz[(long long)(r + 8) * 256 + cl];
                    y3 += residz[(long long)(r + 8) * 256 + cl + 1];
                    *(float2*)&of[(long long)r * 256 + cl]       = make_float2(y0, y1);
                    *(float2*)&of[(long long)(r + 8) * 256 + cl] = make_float2(y2, y3);
                }
            }
    } else if (EP == 4) {
        __half* st = (__half*)smem;
        const int LDT = 136;
#pragma unroll
        for (int mt = 0; mt < MT; ++mt)
#pragma unroll
            for (int nt = 0; nt < NT; ++nt) {
                int r  = wm * 64 + mt * 16 + (lane >> 2);
                int cl = wn * 32 + nt * 8 + ((lane & 3) << 1);
                float* d = c[mt][nt];
                st[cl * LDT + r]           = __float2half_rn(d[0]);
                st[(cl + 1) * LDT + r]     = __float2half_rn(d[1]);
                st[cl * LDT + r + 8]       = __float2half_rn(d[2]);
                st[(cl + 1) * LDT + r + 8] = __float2half_rn(d[3]);
            }
        __syncthreads();
        int bz = m0 >> 13, rloc = m0 & 8191;
        __half* dst = oh + (long long)bz * CC * LSEQ + (long long)n0 * LSEQ + rloc;
#pragma unroll
        for (int g = tid; g < 2048; g += 256) {
            int ccl = g >> 4, seg = g & 15;
            uint4 v = *(uint4*)((char*)st + ccl * 272 + seg * 16);
            *(uint4*)(dst + (long long)ccl * LSEQ + seg * 8) = v;
        }
    } else if (EP == 5) {
        float* st = (float*)smem;
        const int LDT = 132;
#pragma unroll
        for (int mt = 0; mt < MT; ++mt)
#pragma unroll
            for (int nt = 0; nt < NT; ++nt) {
                int r  = wm * 64 + mt * 16 + (lane >> 2);
                int cl = wn * 32 + nt * 8 + ((lane & 3) << 1);
                float* d = c[mt][nt];
                st[cl * LDT + r]           = d[0];
                st[(cl + 1) * LDT + r]     = d[1];
                st[cl * LDT + r + 8]       = d[2];
                st[(cl + 1) * LDT + r + 8] = d[3];
            }
        __syncthreads();
        int bz = m0 >> 13, rloc = m0 & 8191;
        float* dst = of + (long long)bz * CC * LSEQ + (long long)n0 * LSEQ + rloc;
#pragma unroll
        for (int g = tid; g < 4096; g += 256) {
            int ccl = g >> 5, seg = g & 31;
            uint4 v = *(uint4*)((char*)st + ccl * 528 + seg * 16);
            *(uint4*)(dst + (long long)ccl * LSEQ + seg * 4) = v;
        }
    } else {
#pragma unroll
        for (int mt = 0; mt < MT; ++mt)
#pragma unroll
            for (int nt = 0; nt < NT; ++nt) {
                int r  = m0 + wm * (AROWS / 2) + mt * 16 + (lane >> 2);
                int cl = n0 + wn * (NTILE / 4) + nt * 8 + ((lane & 3) << 1);
                float* d = c[mt][nt];
                if (EP == 0) {
                    *(float2*)&of[(long long)r * ldo + cl]       = make_float2(d[0], d[1]);
                    *(float2*)&of[(long long)(r + 8) * ldo + cl] = make_float2(d[2], d[3]);
                } else if (EP == 3) {
                    *(__half2*)&oh[(long long)r * ldo + cl]       = __floats2half2_rn(d[0], d[1]);
                    *(__half2*)&oh[(long long)(r + 8) * ldo + cl] = __floats2half2_rn(d[2], d[3]);
                } else {               // EP==2: bias + gelu
                    float b0v = bias[cl], b1v = bias[cl + 1];
                    *(__half2*)&oh[(long long)r * ldo + cl] =
                        __floats2half2_rn(gelu_f(d[0] + b0v), gelu_f(d[1] + b1v));
                    *(__half2*)&oh[(long long)(r + 8) * ldo + cl] =
                        __floats2half2_rn(gelu_f(d[2] + b0v), gelu_f(d[3] + b1v));
                }
            }
    }
}

// ---------------- fused converts ----------------------------------------------
// both source tensors in one launch
__global__ void convh2(const float* __restrict__ a, __half* __restrict__ oa,
                       const float* __restrict__ b, __half* __restrict__ ob)
{
    int bid = blockIdx.x;
    const float* in; __half* oh;
    if (bid < 4096) { in = a; oh = oa; }
    else            { in = b; oh = ob; bid -= 4096; }
    int i = (bid * 256 + threadIdx.x) * 8;
    float4 x = *(const float4*)(in + i), y = *(const float4*)(in + i + 4);
    __half2 h0 = __floats2half2_rn(x.x, x.y), h1 = __floats2half2_rn(x.z, x.w);
    __half2 h2 = __floats2half2_rn(y.x, y.y), h3 = __floats2half2_rn(y.z, y.w);
    *(uint4*)(oh + i) = make_uint4(*(uint32_t*)&h0, *(uint32_t*)&h1,
                                   *(uint32_t*)&h2, *(uint32_t*)&h3);
}

// all 6 weight transpose+converts in one launch (block-range dispatch)
__global__ void tconv_all(const float* __restrict__ Wq, __half* __restrict__ WqH,
                          const float* __restrict__ Wk, __half* __restrict__ WkH,
                          const float* __restrict__ Wv, __half* __restrict__ WvH,
                          const float* __restrict__ Wl, __half* __restrict__ WlH,
                          const float* __restrict__ W1, __half* __restrict__ W1H,
                          const float* __restrict__ W2, __half* __restrict__ W2H)
{
    __shared__ float tile[32][33];
    int bid = blockIdx.x;
    const float* in; __half* oh; int R, C, bx, by;
    if (bid < 256) {
        int w = bid >> 6, l = bid & 63;
        in = (w == 0) ? Wq : (w == 1) ? Wk : (w == 2) ? Wv : Wl;
        oh = (w == 0) ? WqH : (w == 1) ? WkH : (w == 2) ? WvH : WlH;
        R = 256; C = 256; bx = l & 7; by = l >> 3;
    } else if (bid < 1280) {
        int l = bid - 256;
        in = W1; oh = W1H; R = 512; C = 2048; bx = l & 63; by = l >> 6;
    } else {
        int l = bid - 1280;
        in = W2; oh = W2H; R = 2048; C = 256; bx = l & 7; by = l >> 3;
    }
    const int c0 = bx * 32, r0 = by * 32;
    const int tx = threadIdx.x, ty = threadIdx.y;
#pragma unroll
    for (int i = 0; i < 4; ++i)
        tile[ty + i * 8][tx] = in[(long long)(r0 + ty + i * 8) * C + c0 + tx];
    __syncthreads();
#pragma unroll
    for (int i = 0; i < 4; ++i) {
        int cidx = c0 + ty + i * 8;
        oh[(long long)cidx * R + r0 + tx] = __float2half_rn(tile[tx][ty + i * 8]);
    }
}

// fused whole-row softmax over n: kTf[row] -> kTh = exp(v-max)/sum * KSCALE
__global__ void softmax_row(const float* __restrict__ kTf, __half* __restrict__ kTh)
{
    __shared__ float buf[LSEQ];
    __shared__ float red[8];
    const long long base = (long long)blockIdx.x * LSEQ;
    const int t = threadIdx.x;
    float m = -1e30f;
#pragma unroll
    for (int i = 0; i < 8; ++i) {
        int idx = (i * 256 + t) * 4;
        float4 v = *(const float4*)(kTf + base + idx);
        *(float4*)(buf + idx) = v;
        m = fmaxf(m, fmaxf(fmaxf(v.x, v.y), fmaxf(v.z, v.w)));
    }
#pragma unroll
    for (int o = 16; o; o >>= 1) m = fmaxf(m, __shfl_xor_sync(0xffffffffu, m, o));
    if ((t & 31) == 0) red[t >> 5] = m;
    __syncthreads();
    float M = red[0];
#pragma unroll
    for (int i = 1; i < 8; ++i) M = fmaxf(M, red[i]);
    __syncthreads();
    float s = 0.f;
#pragma unroll
    for (int i = 0; i < 8; ++i) {
        int idx = (i * 256 + t) * 4;
        float4 v = *(float4*)(buf + idx);
        v.x = expf(v.x - M); v.y = expf(v.y - M);
        v.z = expf(v.z - M); v.w = expf(v.w - M);
        *(float4*)(buf + idx) = v;
        s += v.x + v.y + v.z + v.w;
    }
#pragma unroll
    for (int o = 16; o; o >>= 1) s += __shfl_xor_sync(0xffffffffu, s, o);
    if ((t & 31) == 0) red[t >> 5] = s;
    __syncthreads();
    float S = 0.f;
#pragma unroll
    for (int i = 0; i < 8; ++i) S += red[i];
    float sc = KSCALE / S;
#pragma unroll
    for (int i = 0; i < 8; ++i) {
        int idx = (i * 256 + t) * 4;
        float4 v = *(float4*)(buf + idx);
        __half2 a = __floats2half2_rn(v.x * sc, v.y * sc);
        __half2 b = __floats2half2_rn(v.z * sc, v.w * sc);
        *(uint2*)(kTh + base + idx) = make_uint2(*(uint32_t*)&a, *(uint32_t*)&b);
    }
}

// split-K reduce + transpose: cpart[b][sp][d][e] -> cxTh[b][e][d] (half, /KSCALE)
__global__ void reduce_tr(const float* __restrict__ part, __half* __restrict__ oh)
{
    __shared__ float t[32][33];
    const int b = blockIdx.z;
    const int e0 = blockIdx.x * 32, d0 = blockIdx.y * 32;
    const int tx = threadIdx.x, ty = threadIdx.y;
#pragma unroll
    for (int i = 0; i < 4; ++i) {
        int d = d0 + ty + i * 8;
        float s = 0.f;
#pragma unroll
        for (int sp = 0; sp < NSPK; ++sp)
            s += part[(long long)(b * NSPK + sp) * 65536 + d * 256 + e0 + tx];
        t[ty + i * 8][tx] = s;
    }
    __syncthreads();
#pragma unroll
    for (int i = 0; i < 4; ++i) {
        int e = e0 + ty + i * 8;
        oh[(long long)b * 65536 + e * 256 + d0 + tx] =
            __float2half_rn(t[tx][ty + i * 8] * (1.0f / KSCALE));
    }
}

// ---------------- launch ------------------------------------------------------
extern "C" void kernel_launch(void* const* d_in, const int* in_sizes, int n_in,
                              void* d_out, int out_size)
{
    const float* src = (const float*)d_in[0];
    const float* tgt = (const float*)d_in[1];
    const float* Wq  = (const float*)d_in[2];
    const float* Wk  = (const float*)d_in[3];
    const float* Wv  = (const float*)d_in[4];
    const float* Wl  = (const float*)d_in[5];
    const float* gamma1 = (const float*)d_in[6];
    const float* beta1  = (const float*)d_in[7];
    const float* W1  = (const float*)d_in[8];
    const float* b1  = (const float*)d_in[9];
    const float* W2  = (const float*)d_in[10];
    const float* b2  = (const float*)d_in[11];
    const float* gamma2 = (const float*)d_in[12];
    const float* beta2  = (const float*)d_in[13];
    float* out = (float*)d_out;

    cudaFuncSetAttribute(gemm_mma<4,false,false,0>, cudaFuncAttributeMaxDynamicSharedMemorySize, SM_C0);
    cudaFuncSetAttribute(gemm_mma<5,false,false,0>, cudaFuncAttributeMaxDynamicSharedMemorySize, SM_C0T);
    cudaFuncSetAttribute(gemm_mma<3,false,false,0>, cudaFuncAttributeMaxDynamicSharedMemorySize, SM_C0);
    cudaFuncSetAttribute(gemm_mma<0,false,true,0>,  cudaFuncAttributeMaxDynamicSharedMemorySize, SM_C0);
    cudaFuncSetAttribute(gemm_mma<2,true,false,0>,  cudaFuncAttributeMaxDynamicSharedMemorySize, SM_C0);
    cudaFuncSetAttribute(gemm_mma<7,false,false,1>, cudaFuncAttributeMaxDynamicSharedMemorySize, SM_C1);
    cudaFuncSetAttribute(gemm_mma<6,false,false,1>, cudaFuncAttributeMaxDynamicSharedMemorySize, SM_C1);

    #define SYM(v, s) cudaGetSymbolAddress((void**)&v, s)
    __half *srcH,*tgtH,*qTh,*kTh,*vH,*l1H,*hidH,*cxTh,*m2T,*WqH,*WkH,*WvH,*WlH,*W1H,*W2H;
    float *kTf,*cpart;
    SYM(srcH,g_srcH); SYM(tgtH,g_tgtH);
    SYM(kTf,g_kTf);
    SYM(qTh,g_qTh); SYM(kTh,g_kTh);
    SYM(vH,g_vH); SYM(l1H,g_l1H); SYM(hidH,g_hidH);
    SYM(cxTh,g_cxTh); SYM(m2T,g_m2T); SYM(cpart,g_cpart);
    SYM(WqH,g_WqH); SYM(WkH,g_WkH); SYM(WvH,g_WvH); SYM(WlH,g_WlH);
    SYM(W1H,g_W1H); SYM(W2H,g_W2H);
    #undef SYM

    const dim3 tb(32, 8);

    // fused input + weight converts (2 launches instead of 8)
    convh2<<<8192, 256>>>(src, srcH, tgt, tgtH);
    tconv_all<<<1792, tb>>>(Wq, WqH, Wk, WkH, Wv, WvH, Wl, WlH, W1, W1H, W2, W2H);

    // q -> qT (half transposed), k -> kT (f32 transposed), v -> vH
    gemm_mma<4,false,false,0><<<dim3(2,256,1), 256, SM_C0>>>(srcH, nullptr, 256,
        WqH, 256, nullptr, nullptr, nullptr, nullptr, nullptr, qTh, 0, 256, 0, 0, 0, 0);
    gemm_mma<5,false,false,0><<<dim3(2,256,1), 256, SM_C0T>>>(tgtH, nullptr, 256,
        WkH, 256, nullptr, nullptr, nullptr, nullptr, kTf, nullptr, 0, 256, 0, 0, 0, 0);
    gemm_mma<3,false,false,0><<<dim3(2,256,1), 256, SM_C0>>>(tgtH, nullptr, 256,
        WvH, 256, nullptr, nullptr, nullptr, nullptr, nullptr, vH, 256, 256, 0, 0, 0, 0);

    // fused row softmax on kT (scaled x4096) -> kTh
    softmax_row<<<BATCH * CC, 256>>>(kTf, kTh);

    // ctx[d][e] = sum_n qT[d][n] * kTh[e][n]  (split-K, f32 partials)
    gemm_mma<0,false,true,0><<<dim3(2, 2, BATCH*NSPK), 256, SM_C0>>>(qTh, nullptr, LSEQ,
        kTh, LSEQ, nullptr, nullptr, nullptr, nullptr, cpart, nullptr, 256,
        LSEQ, (long long)CC*LSEQ, (long long)CC*LSEQ, 65536, LSEQ / NSPK);
    reduce_tr<<<dim3(8, 8, BATCH), tb>>>(cpart, cxTh);

    // M2T[j][e] = sum_d Wl[d][j] * ctx[d][e]   (tiny per-batch GEMM)
    gemm_mma<3,false,false,0><<<dim3(2, 2, BATCH), 256, SM_C0>>>(WlH, nullptr, 256,
        cxTh, 256, nullptr, nullptr, nullptr, nullptr, nullptr, m2T, 256,
        256, 0, 65536, 65536, 0);

    // message = LN(v @ M2T) -> half   (attn GEMM folded away; LN fused)
    gemm_mma<7,false,false,1><<<dim3(1, 128, BATCH), 256, SM_C1>>>(vH, nullptr, 256,
        m2T, 256, nullptr, gamma1, beta1, nullptr, nullptr, l1H, 256,
        256, (long long)LSEQ*CC, 65536, (long long)LSEQ*CC, 0);

    // hidden = gelu([srcH | l1H] @ W1 + b1) -> half
    gemm_mma<2,true,false,0><<<dim3(16,256,1), 256, SM_C0>>>(srcH, l1H, 256,
        W1H, 512, b1, nullptr, nullptr, nullptr, nullptr, hidH, 2048, 512, 0, 0, 0, 0);

    // out = src + LN(hidden @ W2 + b2)   (bias+LN+residual fused)
    gemm_mma<6,false,false,1><<<dim3(1,512,1), 256, SM_C1>>>(hidH, nullptr, 2048,
        W2H, 2048, b2, gamma2, beta2, src, out, nullptr, 256, 2048, 0, 0, 0, 0);
}

// round 14
// speedup vs baseline: 6.8945x; 1.0791x over previous
#include <cuda_runtime.h>
#include <cuda_fp16.h>
#include <cstdint>
#include <math.h>

#define BATCH 4
#define LSEQ  8192
#define CC    256
#define BL    32768
#define HID   2048
#define NSPK  16
#define KSCALE 4096.0f

// ---------------- PTX helpers -----------------------------------------------
__device__ __forceinline__ uint32_t s2u(const void* p) {
    uint32_t a;
    asm("{ .reg .u64 t; cvta.to.shared.u64 t, %1; cvt.u32.u64 %0, t; }" : "=r"(a) : "l"(p));
    return a;
}
__device__ __forceinline__ void cpasync16(uint32_t s, const void* g) {
    asm volatile("cp.async.cg.shared.global [%0], [%1], 16;" :: "r"(s), "l"(g));
}
#define CP_COMMIT() asm volatile("cp.async.commit_group;" ::: "memory")
#define CP_WAIT1()  asm volatile("cp.async.wait_group 1;" ::: "memory")
__device__ __forceinline__ void ldsm4(uint32_t* r, uint32_t a) {
    asm volatile("ldmatrix.sync.aligned.m8n8.x4.shared.b16 {%0,%1,%2,%3}, [%4];"
        : "=r"(r[0]), "=r"(r[1]), "=r"(r[2]), "=r"(r[3]) : "r"(a));
}
__device__ __forceinline__ void mma16816(float* d, const uint32_t* a, const uint32_t* b) {
    asm volatile(
        "mma.sync.aligned.m16n8k16.row.col.f32.f16.f16.f32 "
        "{%0,%1,%2,%3}, {%4,%5,%6,%7}, {%8,%9}, {%0,%1,%2,%3};"
        : "+f"(d[0]), "+f"(d[1]), "+f"(d[2]), "+f"(d[3])
        : "r"(a[0]), "r"(a[1]), "r"(a[2]), "r"(a[3]), "r"(b[0]), "r"(b[1]));
}

// ---------------- scratch ----------------------------------------------------
__device__ __half g_srcH[BL*CC], g_tgtH[BL*CC];
__device__ float  g_kTf[BL*CC];
__device__ __half g_qTh[BL*CC], g_kTh[BL*CC];
__device__ __half g_vH[BL*CC], g_l1H[BL*CC];
__device__ __half g_hidH[(long long)BL*HID];
__device__ __half g_cxTh[BATCH*CC*CC], g_m2T[BATCH*CC*CC];
__device__ float  g_cpart[BATCH*NSPK*CC*CC];
__device__ __half g_WqH[CC*CC], g_WkvH[2*CC*CC], g_WlH[CC*CC];
__device__ __half g_W1H[HID*2*CC], g_W2H[CC*HID];

// ---------------- small utils -------------------------------------------------
__device__ __forceinline__ float gelu_f(float x) {
    return 0.5f * x * (1.0f + erff(x * 0.70710678118654752f));
}

// ---------------- mma.sync GEMM (pure fp16, 1-term) ---------------------------
// CFG 0: tile 128x128 (MT=4,NT=4).  CFG 1: tile 64x256 (MT=2,NT=8).
// KCH: K-chunk (32 or 64). Row stride = 2*KCH+16 bytes (conflict-free phases).
// EP: 0 = f32 out, 2 = bias+gelu half out, 3 = half out,
//     4 = transposed half out ([b][c][n], ld=LSEQ), 5 = transposed f32 out,
//     6 = bias+LN+residual f32 out (CFG1), 7 = LN half out (CFG1),
//     8 = fused kv: n<256 -> transposed f32 (kT), n>=256 -> half (v)
static constexpr int SM_C0K = 3 * 36864;   // CFG0 KCH=64: 110592
static constexpr int SM_C1  = 3 * 25600;   // CFG1 KCH=32: 76800

template<int EP, bool DUAL, bool SPLITK, int CFG, int KCH>
__global__ __launch_bounds__(256)
void gemm_mma(const __half* __restrict__ Ah, const __half* __restrict__ A2h, int lda,
              const __half* __restrict__ Bh, int ldb,
              const float* __restrict__ bias, const float* __restrict__ gamma,
              const float* __restrict__ beta, const float* __restrict__ resid,
              float* __restrict__ of, __half* __restrict__ oh,
              int ldo, int Ktot, long long sA, long long sB, long long sO, int kslen)
{
    constexpr int AROWS = CFG ? 64 : 128;
    constexpr int BROWS = CFG ? 256 : (EP == 8 ? 128 : 128);
    constexpr int NTILE = CFG ? 256 : 128;
    constexpr int MT = CFG ? 2 : 4;
    constexpr int NT = CFG ? 8 : 4;
    constexpr int ROWB = 2 * KCH + 16;
    constexpr int STAGE = (AROWS + BROWS) * ROWB;
    constexpr int BOFF = AROWS * ROWB;
    constexpr int CPR = KCH / 8;                       // 16B chunks per row
    constexpr int NITER = (AROWS + BROWS) * CPR / 256;
    constexpr int KKN = KCH / 16;

    extern __shared__ char smem[];
    const uint32_t sb = s2u(smem);
    const int tid = threadIdx.x, lane = tid & 31, wid = tid >> 5;
    const int wm = wid >> 2, wn = wid & 3;
    const int m0 = blockIdx.y * AROWS, n0 = blockIdx.x * NTILE, z = blockIdx.z;

    int kbase = 0, K = Ktot;
    long long ooff;
    if (SPLITK) {
        int b = z / NSPK, sp = z - b * NSPK;
        Ah += (long long)b * sA;
        Bh += (long long)b * sB;
        kbase = sp * kslen; K = kslen;
        ooff = (long long)z * sO;
    } else {
        Ah += (long long)z * sA;
        Bh += (long long)z * sB;
        ooff = (long long)z * sO;
    }
    if (of) of += ooff;
    if (oh) oh += ooff;
    const float* residz = resid ? resid + ooff : nullptr;

    float c[MT][NT][4];
#pragma unroll
    for (int i = 0; i < MT; ++i)
#pragma unroll
        for (int j = 0; j < NT; ++j)
#pragma unroll
            for (int q = 0; q < 4; ++q) c[i][j][q] = 0.f;

    auto LOADST = [&](int s, int kc) {
        uint32_t stb = sb + s * STAGE;
#pragma unroll
        for (int i = 0; i < NITER; ++i) {
            int g = tid + i * 256;
            int rl = g / CPR, ch = g % CPR;
            const __half* gp;
            uint32_t sa;
            if (rl < AROWS) {
                const __half* pa; int ka = kc;
                if (DUAL && kc >= 256) { pa = A2h; ka = kc - 256; }
                else                   { pa = Ah; }
                gp = pa + (long long)(m0 + rl) * lda + ka + ch * 8;
                sa = stb + rl * ROWB + ch * 16;
            } else {
                int br = rl - AROWS;
                gp = Bh + (long long)(n0 + br) * ldb + kc + ch * 8;
                sa = stb + BOFF + br * ROWB + ch * 16;
            }
            cpasync16(sa, gp);
        }
    };

    const int nch = K / KCH;
    LOADST(0, kbase);
    CP_COMMIT();
    if (nch > 1) LOADST(1, kbase + KCH);
    CP_COMMIT();

    int sidx = 0;
    for (int it = 0; it < nch; ++it) {
        CP_WAIT1();
        __syncthreads();
        if (it + 2 < nch) {
            int ns = sidx + 2; if (ns >= 3) ns -= 3;
            LOADST(ns, kbase + (it + 2) * KCH);
        }
        CP_COMMIT();

        uint32_t stb = sb + sidx * STAGE;
#pragma unroll
        for (int kk = 0; kk < KKN; ++kk) {
            uint32_t ab = stb + (uint32_t)((lane & 15) + wm * (AROWS / 2)) * ROWB
                        + ((lane >> 4) << 4) + kk * 32;
            uint32_t ah[MT][4];
#pragma unroll
            for (int mt = 0; mt < MT; ++mt) ldsm4(ah[mt], ab + mt * 16 * ROWB);
            int brow = (lane & 7) + ((lane >> 4) << 3);
            int bcol = (lane >> 3) & 1;
            uint32_t bb = stb + BOFF + (uint32_t)(wn * (NTILE / 4) + brow) * ROWB
                        + kk * 32 + bcol * 16;
            uint32_t bh[NT][2];
#pragma unroll
            for (int p = 0; p < NT / 2; ++p) {
                uint32_t rh[4];
                ldsm4(rh, bb + p * 16 * ROWB);
                bh[2*p][0] = rh[0]; bh[2*p][1] = rh[1];
                bh[2*p+1][0] = rh[2]; bh[2*p+1][1] = rh[3];
            }
#pragma unroll
            for (int mt = 0; mt < MT; ++mt)
#pragma unroll
                for (int nt = 0; nt < NT; ++nt)
                    mma16816(c[mt][nt], ah[mt], bh[nt]);
        }
        if (++sidx == 3) sidx = 0;
    }
    __syncthreads();

    // ---------------- epilogues ------------------------------------------------
    if (EP == 6 || EP == 7) {
        float* psum = (float*)smem;          // [4][64]
        float* psq  = psum + 256;
        if (EP == 6) {
#pragma unroll
            for (int mt = 0; mt < MT; ++mt)
#pragma unroll
                for (int nt = 0; nt < NT; ++nt) {
                    int cl = wn * 64 + nt * 8 + ((lane & 3) << 1);
                    float b0 = bias[cl], b1 = bias[cl + 1];
                    c[mt][nt][0] += b0; c[mt][nt][1] += b1;
                    c[mt][nt][2] += b0; c[mt][nt][3] += b1;
                }
        }
#pragma unroll
        for (int mt = 0; mt < MT; ++mt) {
            float s1 = 0, q1 = 0, s2 = 0, q2 = 0;
#pragma unroll
            for (int nt = 0; nt < NT; ++nt) {
                float* d = c[mt][nt];
                s1 += d[0] + d[1]; q1 += d[0]*d[0] + d[1]*d[1];
                s2 += d[2] + d[3]; q2 += d[2]*d[2] + d[3]*d[3];
            }
#pragma unroll
            for (int o = 1; o < 4; o <<= 1) {
                s1 += __shfl_xor_sync(0xffffffffu, s1, o);
                q1 += __shfl_xor_sync(0xffffffffu, q1, o);
                s2 += __shfl_xor_sync(0xffffffffu, s2, o);
                q2 += __shfl_xor_sync(0xffffffffu, q2, o);
            }
            if ((lane & 3) == 0) {
                int r1 = wm * 32 + mt * 16 + (lane >> 2);
                psum[wn * 64 + r1] = s1;     psq[wn * 64 + r1] = q1;
                psum[wn * 64 + r1 + 8] = s2; psq[wn * 64 + r1 + 8] = q2;
            }
        }
        __syncthreads();
        float mu_[MT][2], rs_[MT][2];
#pragma unroll
        for (int mt = 0; mt < MT; ++mt) {
            int rb = wm * 32 + mt * 16 + (lane >> 2);
#pragma unroll
            for (int h = 0; h < 2; ++h) {
                int r = rb + h * 8;
                float S = psum[r] + psum[64 + r] + psum[128 + r] + psum[192 + r];
                float Q = psq[r]  + psq[64 + r]  + psq[128 + r]  + psq[192 + r];
                float mu = S * (1.f / 256.f);
                float var = Q * (1.f / 256.f) - mu * mu;
                mu_[mt][h] = mu; rs_[mt][h] = rsqrtf(var + 1e-5f);
            }
        }
#pragma unroll
        for (int mt = 0; mt < MT; ++mt)
#pragma unroll
            for (int nt = 0; nt < NT; ++nt) {
                int r  = m0 + wm * 32 + mt * 16 + (lane >> 2);
                int cl = wn * 64 + nt * 8 + ((lane & 3) << 1);
                float g0 = gamma[cl], g1 = gamma[cl + 1];
                float e0 = beta[cl],  e1 = beta[cl + 1];
                float* d = c[mt][nt];
                float y0 = (d[0] - mu_[mt][0]) * rs_[mt][0] * g0 + e0;
                float y1 = (d[1] - mu_[mt][0]) * rs_[mt][0] * g1 + e1;
                float y2 = (d[2] - mu_[mt][1]) * rs_[mt][1] * g0 + e0;
                float y3 = (d[3] - mu_[mt][1]) * rs_[mt][1] * g1 + e1;
                if (EP == 7) {
                    *(__half2*)&oh[(long long)r * 256 + cl]       = __floats2half2_rn(y0, y1);
                    *(__half2*)&oh[(long long)(r + 8) * 256 + cl] = __floats2half2_rn(y2, y3);
                } else {
                    y0 += residz[(long long)r * 256 + cl];
                    y1 += residz[(long long)r * 256 + cl + 1];
                    y2 += residz[(long long)(r + 8) * 256 + cl];
                    y3 += residz[(long long)(r + 8) * 256 + cl + 1];
                    *(float2*)&of[(long long)r * 256 + cl]       = make_float2(y0, y1);
                    *(float2*)&of[(long long)(r + 8) * 256 + cl] = make_float2(y2, y3);
                }
            }
    } else if (EP == 4 || (EP == 8 && n0 < 256)) {
        if (EP == 4) {
            __half* st = (__half*)smem;
            const int LDT = 136;
#pragma unroll
            for (int mt = 0; mt < MT; ++mt)
#pragma unroll
                for (int nt = 0; nt < NT; ++nt) {
                    int r  = wm * 64 + mt * 16 + (lane >> 2);
                    int cl = wn * 32 + nt * 8 + ((lane & 3) << 1);
                    float* d = c[mt][nt];
                    st[cl * LDT + r]           = __float2half_rn(d[0]);
                    st[(cl + 1) * LDT + r]     = __float2half_rn(d[1]);
                    st[cl * LDT + r + 8]       = __float2half_rn(d[2]);
                    st[(cl + 1) * LDT + r + 8] = __float2half_rn(d[3]);
                }
            __syncthreads();
            int bz = m0 >> 13, rloc = m0 & 8191;
            __half* dst = oh + (long long)bz * CC * LSEQ + (long long)n0 * LSEQ + rloc;
#pragma unroll
            for (int g = tid; g < 2048; g += 256) {
                int ccl = g >> 4, seg = g & 15;
                uint4 v = *(uint4*)((char*)st + ccl * 272 + seg * 16);
                *(uint4*)(dst + (long long)ccl * LSEQ + seg * 8) = v;
            }
        } else {
            // EP8 kT half: transposed f32 out
            float* st = (float*)smem;
            const int LDT = 132;
#pragma unroll
            for (int mt = 0; mt < MT; ++mt)
#pragma unroll
                for (int nt = 0; nt < NT; ++nt) {
                    int r  = wm * 64 + mt * 16 + (lane >> 2);
                    int cl = wn * 32 + nt * 8 + ((lane & 3) << 1);
                    float* d = c[mt][nt];
                    st[cl * LDT + r]           = d[0];
                    st[(cl + 1) * LDT + r]     = d[1];
                    st[cl * LDT + r + 8]       = d[2];
                    st[(cl + 1) * LDT + r + 8] = d[3];
                }
            __syncthreads();
            int bz = m0 >> 13, rloc = m0 & 8191;
            float* dst = of + (long long)bz * CC * LSEQ + (long long)n0 * LSEQ + rloc;
#pragma unroll
            for (int g = tid; g < 4096; g += 256) {
                int ccl = g >> 5, seg = g & 31;
                uint4 v = *(uint4*)((char*)st + ccl * 528 + seg * 16);
                *(uint4*)(dst + (long long)ccl * LSEQ + seg * 4) = v;
            }
        }
    } else if (EP == 5) {
        float* st = (float*)smem;
        const int LDT = 132;
#pragma unroll
        for (int mt = 0; mt < MT; ++mt)
#pragma unroll
            for (int nt = 0; nt < NT; ++nt) {
                int r  = wm * 64 + mt * 16 + (lane >> 2);
                int cl = wn * 32 + nt * 8 + ((lane & 3) << 1);
                float* d = c[mt][nt];
                st[cl * LDT + r]           = d[0];
                st[(cl + 1) * LDT + r]     = d[1];
                st[cl * LDT + r + 8]       = d[2];
                st[(cl + 1) * LDT + r + 8] = d[3];
            }
        __syncthreads();
        int bz = m0 >> 13, rloc = m0 & 8191;
        float* dst = of + (long long)bz * CC * LSEQ + (long long)n0 * LSEQ + rloc;
#pragma unroll
        for (int g = tid; g < 4096; g += 256) {
            int ccl = g >> 5, seg = g & 31;
            uint4 v = *(uint4*)((char*)st + ccl * 528 + seg * 16);
            *(uint4*)(dst + (long long)ccl * LSEQ + seg * 4) = v;
        }
    } else {
#pragma unroll
        for (int mt = 0; mt < MT; ++mt)
#pragma unroll
            for (int nt = 0; nt < NT; ++nt) {
                int r  = m0 + wm * (AROWS / 2) + mt * 16 + (lane >> 2);
                int cl = n0 + wn * (NTILE / 4) + nt * 8 + ((lane & 3) << 1);
                float* d = c[mt][nt];
                if (EP == 0) {
                    *(float2*)&of[(long long)r * ldo + cl]       = make_float2(d[0], d[1]);
                    *(float2*)&of[(long long)(r + 8) * ldo + cl] = make_float2(d[2], d[3]);
                } else if (EP == 3 || EP == 8) {
                    int cv = (EP == 8) ? cl - 256 : cl;
                    *(__half2*)&oh[(long long)r * ldo + cv]       = __floats2half2_rn(d[0], d[1]);
                    *(__half2*)&oh[(long long)(r + 8) * ldo + cv] = __floats2half2_rn(d[2], d[3]);
                } else {               // EP==2: bias + gelu
                    float b0v = bias[cl], b1v = bias[cl + 1];
                    *(__half2*)&oh[(long long)r * ldo + cl] =
                        __floats2half2_rn(gelu_f(d[0] + b0v), gelu_f(d[1] + b1v));
                    *(__half2*)&oh[(long long)(r + 8) * ldo + cl] =
                        __floats2half2_rn(gelu_f(d[2] + b0v), gelu_f(d[3] + b1v));
                }
            }
    }
}

// ---------------- fused converts ----------------------------------------------
__global__ void convh2(const float* __restrict__ a, __half* __restrict__ oa,
                       const float* __restrict__ b, __half* __restrict__ ob)
{
    int bid = blockIdx.x;
    const float* in; __half* oh;
    if (bid < 4096) { in = a; oh = oa; }
    else            { in = b; oh = ob; bid -= 4096; }
    int i = (bid * 256 + threadIdx.x) * 8;
    float4 x = *(const float4*)(in + i), y = *(const float4*)(in + i + 4);
    __half2 h0 = __floats2half2_rn(x.x, x.y), h1 = __floats2half2_rn(x.z, x.w);
    __half2 h2 = __floats2half2_rn(y.x, y.y), h3 = __floats2half2_rn(y.z, y.w);
    *(uint4*)(oh + i) = make_uint4(*(uint32_t*)&h0, *(uint32_t*)&h1,
                                   *(uint32_t*)&h2, *(uint32_t*)&h3);
}

// all weight transpose+converts in one launch (block-range dispatch)
__global__ void tconv_all(const float* __restrict__ Wq, __half* __restrict__ WqH,
                          const float* __restrict__ Wk, __half* __restrict__ WkH,
                          const float* __restrict__ Wv, __half* __restrict__ WvH,
                          const float* __restrict__ Wl, __half* __restrict__ WlH,
                          const float* __restrict__ W1, __half* __restrict__ W1H,
                          const float* __restrict__ W2, __half* __restrict__ W2H)
{
    __shared__ float tile[32][33];
    int bid = blockIdx.x;
    const float* in; __half* oh; int R, C, bx, by;
    if (bid < 256) {
        int w = bid >> 6, l = bid & 63;
        in = (w == 0) ? Wq : (w == 1) ? Wk : (w == 2) ? Wv : Wl;
        oh = (w == 0) ? WqH : (w == 1) ? WkH : (w == 2) ? WvH : WlH;
        R = 256; C = 256; bx = l & 7; by = l >> 3;
    } else if (bid < 1280) {
        int l = bid - 256;
        in = W1; oh = W1H; R = 512; C = 2048; bx = l & 63; by = l >> 6;
    } else {
        int l = bid - 1280;
        in = W2; oh = W2H; R = 2048; C = 256; bx = l & 7; by = l >> 3;
    }
    const int c0 = bx * 32, r0 = by * 32;
    const int tx = threadIdx.x, ty = threadIdx.y;
#pragma unroll
    for (int i = 0; i < 4; ++i)
        tile[ty + i * 8][tx] = in[(long long)(r0 + ty + i * 8) * C + c0 + tx];
    __syncthreads();
#pragma unroll
    for (int i = 0; i < 4; ++i) {
        int cidx = c0 + ty + i * 8;
        oh[(long long)cidx * R + r0 + tx] = __float2half_rn(tile[tx][ty + i * 8]);
    }
}

// fused whole-row softmax over n: kTf[row] -> kTh = exp(v-max)/sum * KSCALE
__global__ void softmax_row(const float* __restrict__ kTf, __half* __restrict__ kTh)
{
    __shared__ float buf[LSEQ];
    __shared__ float red[8];
    const long long base = (long long)blockIdx.x * LSEQ;
    const int t = threadIdx.x;
    float m = -1e30f;
#pragma unroll
    for (int i = 0; i < 8; ++i) {
        int idx = (i * 256 + t) * 4;
        float4 v = *(const float4*)(kTf + base + idx);
        *(float4*)(buf + idx) = v;
        m = fmaxf(m, fmaxf(fmaxf(v.x, v.y), fmaxf(v.z, v.w)));
    }
#pragma unroll
    for (int o = 16; o; o >>= 1) m = fmaxf(m, __shfl_xor_sync(0xffffffffu, m, o));
    if ((t & 31) == 0) red[t >> 5] = m;
    __syncthreads();
    float M = red[0];
#pragma unroll
    for (int i = 1; i < 8; ++i) M = fmaxf(M, red[i]);
    __syncthreads();
    float s = 0.f;
#pragma unroll
    for (int i = 0; i < 8; ++i) {
        int idx = (i * 256 + t) * 4;
        float4 v = *(float4*)(buf + idx);
        v.x = expf(v.x - M); v.y = expf(v.y - M);
        v.z = expf(v.z - M); v.w = expf(v.w - M);
        *(float4*)(buf + idx) = v;
        s += v.x + v.y + v.z + v.w;
    }
#pragma unroll
    for (int o = 16; o; o >>= 1) s += __shfl_xor_sync(0xffffffffu, s, o);
    if ((t & 31) == 0) red[t >> 5] = s;
    __syncthreads();
    float S = 0.f;
#pragma unroll
    for (int i = 0; i < 8; ++i) S += red[i];
    float sc = KSCALE / S;
#pragma unroll
    for (int i = 0; i < 8; ++i) {
        int idx = (i * 256 + t) * 4;
        float4 v = *(float4*)(buf + idx);
        __half2 a = __floats2half2_rn(v.x * sc, v.y * sc);
        __half2 b = __floats2half2_rn(v.z * sc, v.w * sc);
        *(uint2*)(kTh + base + idx) = make_uint2(*(uint32_t*)&a, *(uint32_t*)&b);
    }
}

// split-K reduce + transpose: cpart[b][sp][d][e] -> cxTh[b][e][d] (half, /KSCALE)
__global__ void reduce_tr(const float* __restrict__ part, __half* __restrict__ oh)
{
    __shared__ float t[32][33];
    const int b = blockIdx.z;
    const int e0 = blockIdx.x * 32, d0 = blockIdx.y * 32;
    const int tx = threadIdx.x, ty = threadIdx.y;
#pragma unroll
    for (int i = 0; i < 4; ++i) {
        int d = d0 + ty + i * 8;
        float s = 0.f;
#pragma unroll
        for (int sp = 0; sp < NSPK; ++sp)
            s += part[(long long)(b * NSPK + sp) * 65536 + d * 256 + e0 + tx];
        t[ty + i * 8][tx] = s;
    }
    __syncthreads();
#pragma unroll
    for (int i = 0; i < 4; ++i) {
        int e = e0 + ty + i * 8;
        oh[(long long)b * 65536 + e * 256 + d0 + tx] =
            __float2half_rn(t[tx][ty + i * 8] * (1.0f / KSCALE));
    }
}

// ---------------- launch ------------------------------------------------------
extern "C" void kernel_launch(void* const* d_in, const int* in_sizes, int n_in,
                              void* d_out, int out_size)
{
    const float* src = (const float*)d_in[0];
    const float* tgt = (const float*)d_in[1];
    const float* Wq  = (const float*)d_in[2];
    const float* Wk  = (const float*)d_in[3];
    const float* Wv  = (const float*)d_in[4];
    const float* Wl  = (const float*)d_in[5];
    const float* gamma1 = (const float*)d_in[6];
    const float* beta1  = (const float*)d_in[7];
    const float* W1  = (const float*)d_in[8];
    const float* b1  = (const float*)d_in[9];
    const float* W2  = (const float*)d_in[10];
    const float* b2  = (const float*)d_in[11];
    const float* gamma2 = (const float*)d_in[12];
    const float* beta2  = (const float*)d_in[13];
    float* out = (float*)d_out;

    cudaFuncSetAttribute(gemm_mma<4,false,false,0,64>, cudaFuncAttributeMaxDynamicSharedMemorySize, SM_C0K);
    cudaFuncSetAttribute(gemm_mma<8,false,false,0,64>, cudaFuncAttributeMaxDynamicSharedMemorySize, SM_C0K);
    cudaFuncSetAttribute(gemm_mma<3,false,false,0,64>, cudaFuncAttributeMaxDynamicSharedMemorySize, SM_C0K);
    cudaFuncSetAttribute(gemm_mma<0,false,true,0,64>,  cudaFuncAttributeMaxDynamicSharedMemorySize, SM_C0K);
    cudaFuncSetAttribute(gemm_mma<2,true,false,0,64>,  cudaFuncAttributeMaxDynamicSharedMemorySize, SM_C0K);
    cudaFuncSetAttribute(gemm_mma<7,false,false,1,32>, cudaFuncAttributeMaxDynamicSharedMemorySize, SM_C1);
    cudaFuncSetAttribute(gemm_mma<6,false,false,1,32>, cudaFuncAttributeMaxDynamicSharedMemorySize, SM_C1);

    #define SYM(v, s) cudaGetSymbolAddress((void**)&v, s)
    __half *srcH,*tgtH,*qTh,*kTh,*vH,*l1H,*hidH,*cxTh,*m2T,*WqH,*WkvH,*WlH,*W1H,*W2H;
    float *kTf,*cpart;
    SYM(srcH,g_srcH); SYM(tgtH,g_tgtH);
    SYM(kTf,g_kTf);
    SYM(qTh,g_qTh); SYM(kTh,g_kTh);
    SYM(vH,g_vH); SYM(l1H,g_l1H); SYM(hidH,g_hidH);
    SYM(cxTh,g_cxTh); SYM(m2T,g_m2T); SYM(cpart,g_cpart);
    SYM(WqH,g_WqH); SYM(WkvH,g_WkvH); SYM(WlH,g_WlH);
    SYM(W1H,g_W1H); SYM(W2H,g_W2H);
    #undef SYM
    __half* WkH = WkvH;                 // rows 0..255 of W_kv
    __half* WvH = WkvH + 256 * 256;     // rows 256..511

    const dim3 tb(32, 8);

    // fused input + weight converts
    convh2<<<8192, 256>>>(src, srcH, tgt, tgtH);
    tconv_all<<<1792, tb>>>(Wq, WqH, Wk, WkH, Wv, WvH, Wl, WlH, W1, W1H, W2, W2H);

    // q -> qT (half transposed)
    gemm_mma<4,false,false,0,64><<<dim3(2,256,1), 256, SM_C0K>>>(srcH, nullptr, 256,
        WqH, 256, nullptr, nullptr, nullptr, nullptr, nullptr, qTh, 0, 256, 0, 0, 0, 0);
    // fused k+v: n<256 -> kTf (f32 transposed), n>=256 -> vH (half row-major)
    gemm_mma<8,false,false,0,64><<<dim3(4,256,1), 256, SM_C0K>>>(tgtH, nullptr, 256,
        WkvH, 256, nullptr, nullptr, nullptr, nullptr, kTf, vH, 256, 256, 0, 0, 0, 0);

    // fused row softmax on kT (scaled x4096) -> kTh
    softmax_row<<<BATCH * CC, 256>>>(kTf, kTh);

    // ctx[d][e] = sum_n qT[d][n] * kTh[e][n]  (split-K, f32 partials)
    gemm_mma<0,false,true,0,64><<<dim3(2, 2, BATCH*NSPK), 256, SM_C0K>>>(qTh, nullptr, LSEQ,
        kTh, LSEQ, nullptr, nullptr, nullptr, nullptr, cpart, nullptr, 256,
        LSEQ, (long long)CC*LSEQ, (long long)CC*LSEQ, 65536, LSEQ / NSPK);
    reduce_tr<<<dim3(8, 8, BATCH), tb>>>(cpart, cxTh);

    // M2T[j][e] = sum_d Wl[d][j] * ctx[d][e]
    gemm_mma<3,false,false,0,64><<<dim3(2, 2, BATCH), 256, SM_C0K>>>(WlH, nullptr, 256,
        cxTh, 256, nullptr, nullptr, nullptr, nullptr, nullptr, m2T, 256,
        256, 0, 65536, 65536, 0);

    // message = LN(v @ M2T) -> half
    gemm_mma<7,false,false,1,32><<<dim3(1, 128, BATCH), 256, SM_C1>>>(vH, nullptr, 256,
        m2T, 256, nullptr, gamma1, beta1, nullptr, nullptr, l1H, 256,
        256, (long long)LSEQ*CC, 65536, (long long)LSEQ*CC, 0);

    // hidden = gelu([srcH | l1H] @ W1 + b1) -> half
    gemm_mma<2,true,false,0,64><<<dim3(16,256,1), 256, SM_C0K>>>(srcH, l1H, 256,
        W1H, 512, b1, nullptr, nullptr, nullptr, nullptr, hidH, 2048, 512, 0, 0, 0, 0);

    // out = src + LN(hidden @ W2 + b2)
    gemm_mma<6,false,false,1,32><<<dim3(1,512,1), 256, SM_C1>>>(hidH, nullptr, 2048,
        W2H, 2048, b2, gamma2, beta2, src, out, nullptr, 256, 2048, 0, 0, 0, 0);
}